// round 1
// baseline (speedup 1.0000x reference)
#include <cuda_runtime.h>

// Problem constants
#define Bb 16
#define Cc 256
#define Ss 64
#define Hh 8
#define Dd 32   // DH = DV = DW = 32

// ---------------------------------------------------------------------------
// Scratch (device globals; allocation in kernel_launch is forbidden)
// ---------------------------------------------------------------------------
__device__ float g_pool[4][Cc * Bb * Ss];            // A^T layout [c][b*64+s]; 0=qh 1=kh 2=qw 3=kw
__device__ float g_qk[4][Bb * Hh * Ss * Dd];         // [b][head][s][d]
__device__ float g_attn[2][Bb * Hh * Ss * Ss];       // 0=attn_h 1=attn_w
__device__ float g_vconv[(size_t)Bb * Cc * Ss * Ss]; // [b][c][h][w]  (= per-b A^T [K=c][M=hw])
__device__ float g_v[(size_t)Bb * Hh * Ss * Ss * Dd];  // [b][head][h][w*32+dv]
__device__ float g_r[(size_t)Bb * Hh * Ss * Ss * Dd];  // [b][head][h][w*32+dv]
__device__ float g_r2[(size_t)Bb * Hh * Ss * Ss * Dd]; // [b][head][dv][h][w']  (= per-b A^T [K][M])

// ---------------------------------------------------------------------------
// Kernel 1: depthwise 3x3 conv (pad 1) + axis-mean pooling for 4 branches.
// Block = (c, b), 256 threads. Writes pooled outputs in transposed [c][b*64+s]
// layout so the q/k linears can use the shared A^T GEMM.
// ---------------------------------------------------------------------------
__global__ void __launch_bounds__(256) conv_pool_kernel(
    const float* __restrict__ x,
    const float* __restrict__ wqh, const float* __restrict__ bqh,
    const float* __restrict__ wkh, const float* __restrict__ bkh,
    const float* __restrict__ wqw, const float* __restrict__ bqw,
    const float* __restrict__ wkw, const float* __restrict__ bkw)
{
    const int c = blockIdx.x;
    const int b = blockIdx.y;
    __shared__ float xs[66][66];
    __shared__ float rowq[64], rowk[64], colq[64], colk[64];
    const int tid = threadIdx.x;

    for (int i = tid; i < 66 * 66; i += 256) (&xs[0][0])[i] = 0.f;
    if (tid < 64) { rowq[tid] = 0.f; rowk[tid] = 0.f; colq[tid] = 0.f; colk[tid] = 0.f; }
    __syncthreads();

    const float* xp = x + ((size_t)b * Cc + c) * 4096;
    for (int i = tid; i < 4096; i += 256) xs[(i >> 6) + 1][(i & 63) + 1] = xp[i];

    float w0[9], w1[9], w2[9], w3[9];
#pragma unroll
    for (int i = 0; i < 9; i++) {
        w0[i] = wqh[c * 9 + i];
        w1[i] = wkh[c * 9 + i];
        w2[i] = wqw[c * 9 + i];
        w3[i] = wkw[c * 9 + i];
    }
    __syncthreads();

    const int wcol = tid & 63;
    const int hgrp = tid >> 6;  // 0..3 ; all 32 lanes of a warp share h
    float cq = 0.f, ck = 0.f;

    for (int k = 0; k < 16; k++) {
        const int h = hgrp * 16 + k;
        float s0 = 0.f, s1 = 0.f, s2 = 0.f, s3 = 0.f;
#pragma unroll
        for (int dy = 0; dy < 3; dy++)
#pragma unroll
            for (int dx = 0; dx < 3; dx++) {
                const float v = xs[h + dy][wcol + dx];
                const int wi = dy * 3 + dx;
                s0 += w0[wi] * v; s1 += w1[wi] * v;
                s2 += w2[wi] * v; s3 += w3[wi] * v;
            }
        // row sums (qh, kh): warp-reduce then one atomic per warp
#pragma unroll
        for (int off = 16; off; off >>= 1) {
            s0 += __shfl_down_sync(0xffffffffu, s0, off);
            s1 += __shfl_down_sync(0xffffffffu, s1, off);
        }
        if ((tid & 31) == 0) { atomicAdd(&rowq[h], s0); atomicAdd(&rowk[h], s1); }
        // column sums (qw, kw): thread owns a fixed wcol, accumulate in regs
        cq += s2; ck += s3;
    }
    atomicAdd(&colq[wcol], cq);
    atomicAdd(&colk[wcol], ck);
    __syncthreads();

    if (tid < 64) {
        const float inv = 1.f / 64.f;
        const int mi = b * 64 + tid;
        g_pool[0][c * 1024 + mi] = rowq[tid] * inv + bqh[c];
        g_pool[1][c * 1024 + mi] = rowk[tid] * inv + bkh[c];
        g_pool[2][c * 1024 + mi] = colq[tid] * inv + bqw[c];
        g_pool[3][c * 1024 + mi] = colk[tid] * inv + bkw[c];
    }
}

// ---------------------------------------------------------------------------
// Kernel 2: depthwise 3x3 conv (pad 1) for the V branch, full grid output.
// Natural [b][c][h][w] layout == per-batch A^T for the V GEMM.
// ---------------------------------------------------------------------------
__global__ void __launch_bounds__(256) conv_v_kernel(
    const float* __restrict__ x,
    const float* __restrict__ wv, const float* __restrict__ bv)
{
    const int c = blockIdx.x;
    const int b = blockIdx.y;
    __shared__ float xs[66][66];
    const int tid = threadIdx.x;

    for (int i = tid; i < 66 * 66; i += 256) (&xs[0][0])[i] = 0.f;
    __syncthreads();

    const float* xp = x + ((size_t)b * Cc + c) * 4096;
    for (int i = tid; i < 4096; i += 256) xs[(i >> 6) + 1][(i & 63) + 1] = xp[i];

    float w[9];
#pragma unroll
    for (int i = 0; i < 9; i++) w[i] = wv[c * 9 + i];
    const float bias = bv[c];
    __syncthreads();

    float* op = g_vconv + ((size_t)b * Cc + c) * 4096;
    const int wcol = tid & 63;
    const int hgrp = tid >> 6;
    for (int k = 0; k < 16; k++) {
        const int h = hgrp * 16 + k;
        float s = bias;
#pragma unroll
        for (int dy = 0; dy < 3; dy++)
#pragma unroll
            for (int dx = 0; dx < 3; dx++)
                s += w[dy * 3 + dx] * xs[h + dy][wcol + dx];
        op[h * 64 + wcol] = s;
    }
}

// ---------------------------------------------------------------------------
// Shared tiled GEMM:  C = A^T-stored(A) @ W^T + bias
//   A : [K][M] row-major (per batch), W : [N][K] row-major, K = 256, N = 256
//   BM=BN=64, BK=16, 256 threads, 4x4 microtile.
// MODE 0: q/k linears   (M=1024; out -> g_qk[which] as [b][head][s][d])
// MODE 1: V linear      (M=4096, z=batch; out -> g_v as [b][head][h][w*32+dv])
// MODE 2: output linear (M=4096, z=batch; out -> d_out flat [b][hw*256 + c],
//                        matching the reference's raw .view to (B,C,64,64))
// ---------------------------------------------------------------------------
template <int MODE>
__global__ void __launch_bounds__(256) gemm_kernel(
    const float* __restrict__ W, const float* __restrict__ bias,
    float* __restrict__ outp, int which)
{
    constexpr int K = 256;
    constexpr int M = (MODE == 0) ? 1024 : 4096;

    const float* A;
    float* C;
    if (MODE == 0)      { A = g_pool[which];                              C = g_qk[which]; }
    else if (MODE == 1) { A = g_vconv + (size_t)blockIdx.z * (K * M);     C = g_v; }
    else                { A = g_r2   + (size_t)blockIdx.z * (K * M);      C = outp; }

    __shared__ float As[16][64];
    __shared__ float Bs[16][68];

    const int tid = threadIdx.x;
    const int m0 = blockIdx.x * 64;
    const int n0 = blockIdx.y * 64;
    const int tm = (tid >> 4) * 4;
    const int tn = (tid & 15) * 4;

    const int lr = tid >> 6;        // A-load row group (0..3)
    const int lc = tid & 63;
    const int wn = tid >> 2;        // W-load n (0..63)
    const int wk = (tid & 3) * 4;   // W-load k (0,4,8,12)

    float acc[4][4] = {};

    for (int k0 = 0; k0 < K; k0 += 16) {
#pragma unroll
        for (int i = 0; i < 4; i++)
            As[lr + i * 4][lc] = A[(size_t)(k0 + lr + i * 4) * M + m0 + lc];
        const float4 w4 = *reinterpret_cast<const float4*>(&W[(size_t)(n0 + wn) * K + k0 + wk]);
        Bs[wk + 0][wn] = w4.x; Bs[wk + 1][wn] = w4.y;
        Bs[wk + 2][wn] = w4.z; Bs[wk + 3][wn] = w4.w;
        __syncthreads();
#pragma unroll
        for (int kk = 0; kk < 16; kk++) {
            const float4 a4 = *reinterpret_cast<const float4*>(&As[kk][tm]);
            const float4 b4 = *reinterpret_cast<const float4*>(&Bs[kk][tn]);
            const float av[4] = {a4.x, a4.y, a4.z, a4.w};
            const float bv[4] = {b4.x, b4.y, b4.z, b4.w};
#pragma unroll
            for (int i = 0; i < 4; i++)
#pragma unroll
                for (int j = 0; j < 4; j++)
                    acc[i][j] += av[i] * bv[j];
        }
        __syncthreads();
    }

#pragma unroll
    for (int i = 0; i < 4; i++) {
        const int mg = m0 + tm + i;
#pragma unroll
        for (int j = 0; j < 4; j++) {
            const int ng = n0 + tn + j;
            const float v = acc[i][j] + bias[ng];
            size_t idx;
            if (MODE == 0)
                idx = (size_t)(mg >> 6) * 16384 + (size_t)(ng >> 5) * 2048
                    + (size_t)(mg & 63) * 32 + (ng & 31);
            else if (MODE == 1)
                idx = (size_t)blockIdx.z * 1048576 + (size_t)(ng >> 5) * 131072
                    + (size_t)mg * 32 + (ng & 31);
            else
                idx = (size_t)blockIdx.z * 1048576 + (size_t)mg * 256 + ng;
            C[idx] = v;
        }
    }
}

// ---------------------------------------------------------------------------
// Kernel 4: attention scores + softmax for both axes.
// Block = (bh, axis), 64 threads; thread i owns score row i.
// ---------------------------------------------------------------------------
__global__ void __launch_bounds__(64) attn_kernel(
    const float* __restrict__ Bh, const float* __restrict__ Bw)
{
    const int bh = blockIdx.x;          // b*H + head
    const int head = bh & 7;
    const int axis = blockIdx.y;        // 0 = height, 1 = width
    const float scale = 0.17677669529663687f;  // 32^-0.5

    const float* q = g_qk[axis == 0 ? 0 : 2];
    const float* k = g_qk[axis == 0 ? 1 : 3];
    const float* Bm = (axis == 0) ? Bh : Bw;
    float* o = g_attn[axis];

    __shared__ float ks[64][32];
    const int tid = threadIdx.x;
    for (int i = tid; i < 2048; i += 64) (&ks[0][0])[i] = k[(size_t)bh * 2048 + i];
    __syncthreads();

    float qr[32];
#pragma unroll
    for (int d = 0; d < 32; d++) qr[d] = q[(size_t)bh * 2048 + tid * 32 + d];

    float s[64];
    float mx = -1e30f;
#pragma unroll
    for (int j = 0; j < 64; j++) {
        float acc = 0.f;
#pragma unroll
        for (int d = 0; d < 32; d++) acc += qr[d] * ks[j][d];
        acc = acc * scale + Bm[head * 4096 + tid * 64 + j];
        s[j] = acc;
        mx = fmaxf(mx, acc);
    }
    float sum = 0.f;
#pragma unroll
    for (int j = 0; j < 64; j++) { s[j] = __expf(s[j] - mx); sum += s[j]; }
    const float r = 1.f / sum;
#pragma unroll
    for (int j = 0; j < 64; j++) o[(size_t)bh * 4096 + tid * 64 + j] = s[j] * r;
}

// ---------------------------------------------------------------------------
// Kernel 6: r = attn_h @ v  per (b,head):  [64,64] x [64,2048]
// Thread owns one output column (n = w*32+dv) with 64-row accumulator.
// ---------------------------------------------------------------------------
__global__ void __launch_bounds__(256) axialh_kernel()
{
    const int bh = blockIdx.y;
    const int n = blockIdx.x * 256 + threadIdx.x;
    __shared__ float At[64][68];        // At[j][i] = attn_h[i][j]
    const int tid = threadIdx.x;
    const float* ap = g_attn[0] + (size_t)bh * 4096;
    for (int idx = tid; idx < 4096; idx += 256)
        At[idx & 63][idx >> 6] = ap[idx];
    __syncthreads();

    float acc[64];
#pragma unroll
    for (int i = 0; i < 64; i++) acc[i] = 0.f;

    const float* Vp = g_v + (size_t)bh * 131072 + n;
    for (int j = 0; j < 64; j++) {
        const float v = Vp[(size_t)j * 2048];
#pragma unroll
        for (int i = 0; i < 64; i += 4) {
            const float4 a = *reinterpret_cast<const float4*>(&At[j][i]);
            acc[i + 0] += a.x * v; acc[i + 1] += a.y * v;
            acc[i + 2] += a.z * v; acc[i + 3] += a.w * v;
        }
    }
    float* Rp = g_r + (size_t)bh * 131072 + n;
#pragma unroll
    for (int i = 0; i < 64; i++) Rp[(size_t)i * 2048] = acc[i];
}

// ---------------------------------------------------------------------------
// Kernel 7: r2 = (r viewed [h*dv, w]) @ attn_w  per (b,head).
// Block = 2 h-slices, 128 threads; each thread: 8 dv x 4 w' microtile.
// Output written directly in A^T layout [b][head][dv][h][w'] for the final GEMM.
// ---------------------------------------------------------------------------
__global__ void __launch_bounds__(128) axialw_kernel()
{
    const int bh = blockIdx.y;
    const int h0 = blockIdx.x * 2;
    __shared__ float rs[2 * 2048];      // [hloc][w][dv]
    __shared__ float aw[64][64];        // aw[w][w']
    const int tid = threadIdx.x;

    {
        const float4* Rp4 = reinterpret_cast<const float4*>(
            g_r + (size_t)bh * 131072 + (size_t)h0 * 2048);
        float4* rs4 = reinterpret_cast<float4*>(rs);
        for (int i = tid; i < 1024; i += 128) rs4[i] = Rp4[i];
        const float4* Ap4 = reinterpret_cast<const float4*>(g_attn[1] + (size_t)bh * 4096);
        float4* aw4 = reinterpret_cast<float4*>(&aw[0][0]);
        for (int i = tid; i < 1024; i += 128) aw4[i] = Ap4[i];
    }
    __syncthreads();

    const int hloc = tid >> 6;
    const int l = tid & 63;
    const int wp0 = (l & 15) * 4;
    const int dv0 = (l >> 4) * 8;
    const float* rsp = rs + hloc * 2048 + dv0;

    float acc[8][4];
#pragma unroll
    for (int d = 0; d < 8; d++)
#pragma unroll
        for (int p = 0; p < 4; p++) acc[d][p] = 0.f;

    for (int w = 0; w < 64; w++) {
        const float4 a = *reinterpret_cast<const float4*>(&aw[w][wp0]);
        const float4 r0 = *reinterpret_cast<const float4*>(&rsp[w * 32]);
        const float4 r1 = *reinterpret_cast<const float4*>(&rsp[w * 32 + 4]);
        const float av[4] = {a.x, a.y, a.z, a.w};
        const float rv[8] = {r0.x, r0.y, r0.z, r0.w, r1.x, r1.y, r1.z, r1.w};
#pragma unroll
        for (int d = 0; d < 8; d++)
#pragma unroll
            for (int p = 0; p < 4; p++)
                acc[d][p] += rv[d] * av[p];
    }

#pragma unroll
    for (int d = 0; d < 8; d++) {
        const size_t o = ((size_t)(bh * 32 + dv0 + d) * 64 + h0 + hloc) * 64 + wp0;
        *reinterpret_cast<float4*>(&g_r2[o]) =
            make_float4(acc[d][0], acc[d][1], acc[d][2], acc[d][3]);
    }
}

// ---------------------------------------------------------------------------
// Launch
// ---------------------------------------------------------------------------
extern "C" void kernel_launch(void* const* d_in, const int* in_sizes, int n_in,
                              void* d_out, int out_size)
{
    const float* x       = (const float*)d_in[0];
    const float* dw_qh_w = (const float*)d_in[1];
    const float* dw_qh_b = (const float*)d_in[2];
    const float* fc_qh_w = (const float*)d_in[3];
    const float* fc_qh_b = (const float*)d_in[4];
    const float* dw_kh_w = (const float*)d_in[5];
    const float* dw_kh_b = (const float*)d_in[6];
    const float* fc_kh_w = (const float*)d_in[7];
    const float* fc_kh_b = (const float*)d_in[8];
    const float* Bh      = (const float*)d_in[9];
    const float* dw_v_w  = (const float*)d_in[10];
    const float* dw_v_b  = (const float*)d_in[11];
    const float* fc_v_w  = (const float*)d_in[12];
    const float* fc_v_b  = (const float*)d_in[13];
    const float* dw_qw_w = (const float*)d_in[14];
    const float* dw_qw_b = (const float*)d_in[15];
    const float* fc_qw_w = (const float*)d_in[16];
    const float* fc_qw_b = (const float*)d_in[17];
    const float* dw_kw_w = (const float*)d_in[18];
    const float* dw_kw_b = (const float*)d_in[19];
    const float* fc_kw_w = (const float*)d_in[20];
    const float* fc_kw_b = (const float*)d_in[21];
    const float* Bw      = (const float*)d_in[22];
    const float* fc_o_w  = (const float*)d_in[23];
    const float* fc_o_b  = (const float*)d_in[24];
    float* out = (float*)d_out;

    const dim3 gconv(Cc, Bb);
    conv_pool_kernel<<<gconv, 256>>>(x, dw_qh_w, dw_qh_b, dw_kh_w, dw_kh_b,
                                     dw_qw_w, dw_qw_b, dw_kw_w, dw_kw_b);
    conv_v_kernel<<<gconv, 256>>>(x, dw_v_w, dw_v_b);

    // q/k linears: M=1024, N=256
    const dim3 gqk(16, 4, 1);
    gemm_kernel<0><<<gqk, 256>>>(fc_qh_w, fc_qh_b, nullptr, 0);
    gemm_kernel<0><<<gqk, 256>>>(fc_kh_w, fc_kh_b, nullptr, 1);
    gemm_kernel<0><<<gqk, 256>>>(fc_qw_w, fc_qw_b, nullptr, 2);
    gemm_kernel<0><<<gqk, 256>>>(fc_kw_w, fc_kw_b, nullptr, 3);

    attn_kernel<<<dim3(Bb * Hh, 2), 64>>>(Bh, Bw);

    // V linear: per-batch M=4096, N=256
    gemm_kernel<1><<<dim3(64, 4, Bb), 256>>>(fc_v_w, fc_v_b, nullptr, 0);

    axialh_kernel<<<dim3(8, Bb * Hh), 256>>>();
    axialw_kernel<<<dim3(32, Bb * Hh), 128>>>();

    // output linear: per-batch M=4096, N=256, writes d_out in torch-view layout
    gemm_kernel<2><<<dim3(64, 4, Bb), 256>>>(fc_o_w, fc_o_b, out, 0);
}

// round 3
// speedup vs baseline: 1.3058x; 1.3058x over previous
#include <cuda_runtime.h>
#include <mma.h>
#include <cstdint>

using namespace nvcuda;

// Problem constants
#define Bb 16
#define Cc 256
#define Ss 64
#define Hh 8
#define Dd 32

// ---------------------------------------------------------------------------
// Scratch (device globals)
// ---------------------------------------------------------------------------
__device__ float g_pool[4][Cc * Bb * Ss];              // [c][b*64+s]
__device__ float g_qk[4][Bb * Hh * Ss * Dd];           // [b][head][s][d]
__device__ float g_attn[2][Bb * Hh * Ss * Ss];
__device__ float g_vconv[(size_t)Bb * Cc * 4096];      // [b][c][hw]
__device__ float g_vt[(size_t)Bb * 4096 * Cc];         // [b][hw][c]   (A for V GEMM)
__device__ float g_v[(size_t)Bb * Hh * Ss * Ss * Dd];  // [b][head][h][w*32+dv]
__device__ float g_r[(size_t)Bb * Hh * Ss * Ss * Dd];  // [b][head][h][w*32+dv]
__device__ float g_r2[(size_t)Bb * 4096 * Cc];         // [b][m=hw][k=head*32+dv] (A for O GEMM)

// ---------------------------------------------------------------------------
// Kernel 1: depthwise 3x3 conv + axis-mean pooling (4 branches)
// ---------------------------------------------------------------------------
__global__ void __launch_bounds__(256) conv_pool_kernel(
    const float* __restrict__ x,
    const float* __restrict__ wqh, const float* __restrict__ bqh,
    const float* __restrict__ wkh, const float* __restrict__ bkh,
    const float* __restrict__ wqw, const float* __restrict__ bqw,
    const float* __restrict__ wkw, const float* __restrict__ bkw)
{
    const int c = blockIdx.x;
    const int b = blockIdx.y;
    __shared__ float xs[66][66];
    __shared__ float rowq[64], rowk[64], colq[64], colk[64];
    const int tid = threadIdx.x;

    for (int i = tid; i < 66 * 66; i += 256) (&xs[0][0])[i] = 0.f;
    if (tid < 64) { rowq[tid] = 0.f; rowk[tid] = 0.f; colq[tid] = 0.f; colk[tid] = 0.f; }
    __syncthreads();

    const float* xp = x + ((size_t)b * Cc + c) * 4096;
    for (int i = tid; i < 4096; i += 256) xs[(i >> 6) + 1][(i & 63) + 1] = xp[i];

    float w0[9], w1[9], w2[9], w3[9];
#pragma unroll
    for (int i = 0; i < 9; i++) {
        w0[i] = wqh[c * 9 + i]; w1[i] = wkh[c * 9 + i];
        w2[i] = wqw[c * 9 + i]; w3[i] = wkw[c * 9 + i];
    }
    __syncthreads();

    const int wcol = tid & 63;
    const int hgrp = tid >> 6;
    float cq = 0.f, ck = 0.f;

    for (int k = 0; k < 16; k++) {
        const int h = hgrp * 16 + k;
        float s0 = 0.f, s1 = 0.f, s2 = 0.f, s3 = 0.f;
#pragma unroll
        for (int dy = 0; dy < 3; dy++)
#pragma unroll
            for (int dx = 0; dx < 3; dx++) {
                const float v = xs[h + dy][wcol + dx];
                const int wi = dy * 3 + dx;
                s0 += w0[wi] * v; s1 += w1[wi] * v;
                s2 += w2[wi] * v; s3 += w3[wi] * v;
            }
#pragma unroll
        for (int off = 16; off; off >>= 1) {
            s0 += __shfl_down_sync(0xffffffffu, s0, off);
            s1 += __shfl_down_sync(0xffffffffu, s1, off);
        }
        if ((tid & 31) == 0) { atomicAdd(&rowq[h], s0); atomicAdd(&rowk[h], s1); }
        cq += s2; ck += s3;
    }
    atomicAdd(&colq[wcol], cq);
    atomicAdd(&colk[wcol], ck);
    __syncthreads();

    if (tid < 64) {
        const float inv = 1.f / 64.f;
        const int mi = b * 64 + tid;
        g_pool[0][c * 1024 + mi] = rowq[tid] * inv + bqh[c];
        g_pool[1][c * 1024 + mi] = rowk[tid] * inv + bkh[c];
        g_pool[2][c * 1024 + mi] = colq[tid] * inv + bqw[c];
        g_pool[3][c * 1024 + mi] = colk[tid] * inv + bkw[c];
    }
}

// ---------------------------------------------------------------------------
// Kernel 2: depthwise 3x3 conv for V branch -> g_vconv [b][c][hw]
// ---------------------------------------------------------------------------
__global__ void __launch_bounds__(256) conv_v_kernel(
    const float* __restrict__ x,
    const float* __restrict__ wv, const float* __restrict__ bv)
{
    const int c = blockIdx.x;
    const int b = blockIdx.y;
    __shared__ float xs[66][66];
    const int tid = threadIdx.x;

    for (int i = tid; i < 66 * 66; i += 256) (&xs[0][0])[i] = 0.f;
    __syncthreads();

    const float* xp = x + ((size_t)b * Cc + c) * 4096;
    for (int i = tid; i < 4096; i += 256) xs[(i >> 6) + 1][(i & 63) + 1] = xp[i];

    float w[9];
#pragma unroll
    for (int i = 0; i < 9; i++) w[i] = wv[c * 9 + i];
    const float bias = bv[c];
    __syncthreads();

    float* op = g_vconv + ((size_t)b * Cc + c) * 4096;
    const int wcol = tid & 63;
    const int hgrp = tid >> 6;
    for (int k = 0; k < 16; k++) {
        const int h = hgrp * 16 + k;
        float s = bias;
#pragma unroll
        for (int dy = 0; dy < 3; dy++)
#pragma unroll
            for (int dx = 0; dx < 3; dx++)
                s += w[dy * 3 + dx] * xs[h + dy][wcol + dx];
        op[h * 64 + wcol] = s;
    }
}

// ---------------------------------------------------------------------------
// Kernel 3: transpose g_vconv [b][256][4096] -> g_vt [b][4096][256]
// ---------------------------------------------------------------------------
__global__ void __launch_bounds__(256) transpose_v_kernel()
{
    __shared__ float t[32][33];
    const int b = blockIdx.z;
    const int c0 = blockIdx.y * 32;
    const int m0 = blockIdx.x * 32;
    const float* in = g_vconv + (size_t)b * 1048576;
    float* out = g_vt + (size_t)b * 1048576;
    const int tx = threadIdx.x, ty = threadIdx.y;
#pragma unroll
    for (int j = 0; j < 32; j += 8)
        t[ty + j][tx] = in[(size_t)(c0 + ty + j) * 4096 + m0 + tx];
    __syncthreads();
#pragma unroll
    for (int j = 0; j < 32; j += 8)
        out[(size_t)(m0 + ty + j) * 256 + c0 + tx] = t[tx][ty + j];
}

// ---------------------------------------------------------------------------
// Kernel 4: merged q/k linears (fp32 SIMT, z = which branch)
// ---------------------------------------------------------------------------
__global__ void __launch_bounds__(256) qk_gemm_kernel(
    const float* __restrict__ W0, const float* __restrict__ b0,
    const float* __restrict__ W1, const float* __restrict__ b1,
    const float* __restrict__ W2, const float* __restrict__ b2,
    const float* __restrict__ W3, const float* __restrict__ b3)
{
    const int which = blockIdx.z;
    const float* W = (which == 0) ? W0 : (which == 1) ? W1 : (which == 2) ? W2 : W3;
    const float* bias = (which == 0) ? b0 : (which == 1) ? b1 : (which == 2) ? b2 : b3;
    const float* A = g_pool[which];
    float* C = g_qk[which];
    constexpr int K = 256, M = 1024;

    __shared__ float As[16][64];
    __shared__ float Bs[16][68];

    const int tid = threadIdx.x;
    const int m0 = blockIdx.x * 64;
    const int n0 = blockIdx.y * 64;
    const int tm = (tid >> 4) * 4;
    const int tn = (tid & 15) * 4;
    const int lr = tid >> 6;
    const int lc = tid & 63;
    const int wn = tid >> 2;
    const int wk = (tid & 3) * 4;

    float acc[4][4] = {};
    for (int k0 = 0; k0 < K; k0 += 16) {
#pragma unroll
        for (int i = 0; i < 4; i++)
            As[lr + i * 4][lc] = A[(size_t)(k0 + lr + i * 4) * M + m0 + lc];
        const float4 w4 = *reinterpret_cast<const float4*>(&W[(size_t)(n0 + wn) * K + k0 + wk]);
        Bs[wk + 0][wn] = w4.x; Bs[wk + 1][wn] = w4.y;
        Bs[wk + 2][wn] = w4.z; Bs[wk + 3][wn] = w4.w;
        __syncthreads();
#pragma unroll
        for (int kk = 0; kk < 16; kk++) {
            const float4 a4 = *reinterpret_cast<const float4*>(&As[kk][tm]);
            const float4 b4 = *reinterpret_cast<const float4*>(&Bs[kk][tn]);
            const float av[4] = {a4.x, a4.y, a4.z, a4.w};
            const float bv[4] = {b4.x, b4.y, b4.z, b4.w};
#pragma unroll
            for (int i = 0; i < 4; i++)
#pragma unroll
                for (int j = 0; j < 4; j++) acc[i][j] += av[i] * bv[j];
        }
        __syncthreads();
    }
#pragma unroll
    for (int i = 0; i < 4; i++) {
        const int mg = m0 + tm + i;
#pragma unroll
        for (int j = 0; j < 4; j++) {
            const int ng = n0 + tn + j;
            C[(size_t)(mg >> 6) * 16384 + (size_t)(ng >> 5) * 2048 + (size_t)(mg & 63) * 32 + (ng & 31)]
                = acc[i][j] + bias[ng];
        }
    }
}

// ---------------------------------------------------------------------------
// Kernel 5: attention scores + softmax (both axes)
// ---------------------------------------------------------------------------
__global__ void __launch_bounds__(64) attn_kernel(
    const float* __restrict__ Bh, const float* __restrict__ Bw)
{
    const int bh = blockIdx.x;
    const int head = bh & 7;
    const int axis = blockIdx.y;
    const float scale = 0.17677669529663687f;

    const float* q = g_qk[axis == 0 ? 0 : 2];
    const float* k = g_qk[axis == 0 ? 1 : 3];
    const float* Bm = (axis == 0) ? Bh : Bw;
    float* o = g_attn[axis];

    __shared__ float ks[64][32];
    const int tid = threadIdx.x;
    for (int i = tid; i < 2048; i += 64) (&ks[0][0])[i] = k[(size_t)bh * 2048 + i];
    __syncthreads();

    float qr[32];
#pragma unroll
    for (int d = 0; d < 32; d++) qr[d] = q[(size_t)bh * 2048 + tid * 32 + d];

    float s[64];
    float mx = -1e30f;
#pragma unroll
    for (int j = 0; j < 64; j++) {
        float acc = 0.f;
#pragma unroll
        for (int d = 0; d < 32; d++) acc += qr[d] * ks[j][d];
        acc = acc * scale + Bm[head * 4096 + tid * 64 + j];
        s[j] = acc;
        mx = fmaxf(mx, acc);
    }
    float sum = 0.f;
#pragma unroll
    for (int j = 0; j < 64; j++) { s[j] = __expf(s[j] - mx); sum += s[j]; }
    const float r = 1.f / sum;
#pragma unroll
    for (int j = 0; j < 64; j++) o[(size_t)bh * 4096 + tid * 64 + j] = s[j] * r;
}

// ---------------------------------------------------------------------------
// Kernel 6: tf32 wmma GEMM  C[4096][256] = A[4096][256] @ W[256][256]^T + bias
//   BM=128, BN=64, BK=32. 8 warps in a 4x2 grid, 32x32 warp tiles.
//   MODE 1: A = g_vt,  out -> g_v [b][head][m][dv]
//   MODE 2: A = g_r2,  out -> d_out flat [b][m*256 + n]
// ---------------------------------------------------------------------------
#define BM 128
#define BN 64
#define BK 32
#define PADA 36
#define PADC 68

template <int MODE>
__global__ void __launch_bounds__(256) wmma_gemm_kernel(
    const float* __restrict__ W, const float* __restrict__ bias,
    float* __restrict__ outp)
{
    __shared__ float sm[BM * PADC > (BM + BN) * PADA ? BM * PADC : (BM + BN) * PADA];
    float* As = sm;                 // [128][36]
    float* Ws = sm + BM * PADA;     // [64][36]
    float* Cs = sm;                 // [128][68] staging (reused)

    const int tid = threadIdx.x;
    const int wid = tid >> 5;
    const int wm = wid >> 1;        // 0..3
    const int wn = wid & 1;         // 0..1

    const float* A = ((MODE == 1) ? g_vt : g_r2)
                   + (size_t)blockIdx.z * 1048576 + (size_t)(blockIdx.x * BM) * 256;
    const float* Wp = W + (size_t)(blockIdx.y * BN) * 256;

    wmma::fragment<wmma::accumulator, 16, 16, 8, float> acc[2][2];
#pragma unroll
    for (int i = 0; i < 2; i++)
#pragma unroll
        for (int j = 0; j < 2; j++) wmma::fill_fragment(acc[i][j], 0.f);

    for (int k0 = 0; k0 < 256; k0 += BK) {
        // A tile: 128 rows x 32 k (8 float4 per row), 4 float4 per thread
#pragma unroll
        for (int i = 0; i < 4; i++) {
            const int f = tid + 256 * i;
            const int row = f >> 3, q = f & 7;
            float4 v = *reinterpret_cast<const float4*>(A + (size_t)row * 256 + k0 + q * 4);
            float* d = &As[row * PADA + q * 4];
            d[0] = wmma::__float_to_tf32(v.x);
            d[1] = wmma::__float_to_tf32(v.y);
            d[2] = wmma::__float_to_tf32(v.z);
            d[3] = wmma::__float_to_tf32(v.w);
        }
        // W tile: 64 rows x 32 k, 2 float4 per thread
#pragma unroll
        for (int i = 0; i < 2; i++) {
            const int f = tid + 256 * i;
            const int row = f >> 3, q = f & 7;
            float4 v = *reinterpret_cast<const float4*>(Wp + (size_t)row * 256 + k0 + q * 4);
            float* d = &Ws[row * PADA + q * 4];
            d[0] = wmma::__float_to_tf32(v.x);
            d[1] = wmma::__float_to_tf32(v.y);
            d[2] = wmma::__float_to_tf32(v.z);
            d[3] = wmma::__float_to_tf32(v.w);
        }
        __syncthreads();
#pragma unroll
        for (int kk = 0; kk < BK; kk += 8) {
            wmma::fragment<wmma::matrix_a, 16, 16, 8, wmma::precision::tf32, wmma::row_major> af[2];
            wmma::fragment<wmma::matrix_b, 16, 16, 8, wmma::precision::tf32, wmma::col_major> bf[2];
            wmma::load_matrix_sync(af[0], &As[(wm * 32) * PADA + kk], PADA);
            wmma::load_matrix_sync(af[1], &As[(wm * 32 + 16) * PADA + kk], PADA);
            wmma::load_matrix_sync(bf[0], &Ws[(wn * 32) * PADA + kk], PADA);
            wmma::load_matrix_sync(bf[1], &Ws[(wn * 32 + 16) * PADA + kk], PADA);
#pragma unroll
            for (int i = 0; i < 2; i++)
#pragma unroll
                for (int j = 0; j < 2; j++)
                    wmma::mma_sync(acc[i][j], af[i], bf[j], acc[i][j]);
        }
        __syncthreads();
    }

    // stage to smem, then coalesced global writes with bias
#pragma unroll
    for (int i = 0; i < 2; i++)
#pragma unroll
        for (int j = 0; j < 2; j++)
            wmma::store_matrix_sync(&Cs[(wm * 32 + i * 16) * PADC + wn * 32 + j * 16],
                                    acc[i][j], PADC, wmma::mem_row_major);
    __syncthreads();

    const int m_base = blockIdx.x * BM;
    const int n_base = blockIdx.y * BN;
#pragma unroll
    for (int i = 0; i < 8; i++) {
        const int f = tid + 256 * i;       // 2048 float4 total
        const int row = f >> 4;            // 16 float4 per 64-wide row
        const int q = f & 15;
        const float4 c4 = *reinterpret_cast<const float4*>(&Cs[row * PADC + q * 4]);
        const float4 b4 = *reinterpret_cast<const float4*>(&bias[n_base + q * 4]);
        float4 o;
        o.x = c4.x + b4.x; o.y = c4.y + b4.y;
        o.z = c4.z + b4.z; o.w = c4.w + b4.w;
        const int n = n_base + q * 4;
        float* dst;
        if (MODE == 1) {
            dst = g_v + (size_t)blockIdx.z * 1048576 + (size_t)(n >> 5) * 131072
                + (size_t)(m_base + row) * 32 + (n & 31);
        } else {
            dst = outp + (size_t)blockIdx.z * 1048576 + (size_t)(m_base + row) * 256 + n;
        }
        *reinterpret_cast<float4*>(dst) = o;
    }
}

// ---------------------------------------------------------------------------
// Kernel 7: r = attn_h @ v  per (b,head):  [64,64] x [64,2048]
// ---------------------------------------------------------------------------
__global__ void __launch_bounds__(256) axialh_kernel()
{
    const int bh = blockIdx.y;
    const int n = blockIdx.x * 256 + threadIdx.x;
    __shared__ float At[64][68];
    const int tid = threadIdx.x;
    const float* ap = g_attn[0] + (size_t)bh * 4096;
    for (int idx = tid; idx < 4096; idx += 256)
        At[idx & 63][idx >> 6] = ap[idx];
    __syncthreads();

    float acc[64];
#pragma unroll
    for (int i = 0; i < 64; i++) acc[i] = 0.f;

    const float* Vp = g_v + (size_t)bh * 131072 + n;
    for (int j = 0; j < 64; j++) {
        const float v = Vp[(size_t)j * 2048];
#pragma unroll
        for (int i = 0; i < 64; i += 4) {
            const float4 a = *reinterpret_cast<const float4*>(&At[j][i]);
            acc[i + 0] += a.x * v; acc[i + 1] += a.y * v;
            acc[i + 2] += a.z * v; acc[i + 3] += a.w * v;
        }
    }
    float* Rp = g_r + (size_t)bh * 131072 + n;
#pragma unroll
    for (int i = 0; i < 64; i++) Rp[(size_t)i * 2048] = acc[i];
}

// ---------------------------------------------------------------------------
// Kernel 8: r2 = (r viewed [h*dv, w]) @ attn_w  per (b,head).
// Writes g_r2 directly in [b][m=hw][k=head*32+dv] layout for the O GEMM.
// ---------------------------------------------------------------------------
__global__ void __launch_bounds__(128) axialw_kernel()
{
    const int bh = blockIdx.y;
    const int h0 = blockIdx.x * 2;
    __shared__ float rs[2 * 2048];
    __shared__ float aw[64][64];
    const int tid = threadIdx.x;

    {
        const float4* Rp4 = reinterpret_cast<const float4*>(
            g_r + (size_t)bh * 131072 + (size_t)h0 * 2048);
        float4* rs4 = reinterpret_cast<float4*>(rs);
        for (int i = tid; i < 1024; i += 128) rs4[i] = Rp4[i];
        const float4* Ap4 = reinterpret_cast<const float4*>(g_attn[1] + (size_t)bh * 4096);
        float4* aw4 = reinterpret_cast<float4*>(&aw[0][0]);
        for (int i = tid; i < 1024; i += 128) aw4[i] = Ap4[i];
    }
    __syncthreads();

    const int hloc = tid >> 6;
    const int l = tid & 63;
    const int wp0 = (l & 15) * 4;
    const int dv0 = (l >> 4) * 8;
    const float* rsp = rs + hloc * 2048 + dv0;

    float acc[8][4];
#pragma unroll
    for (int d = 0; d < 8; d++)
#pragma unroll
        for (int p = 0; p < 4; p++) acc[d][p] = 0.f;

    for (int w = 0; w < 64; w++) {
        const float4 a = *reinterpret_cast<const float4*>(&aw[w][wp0]);
        const float4 r0 = *reinterpret_cast<const float4*>(&rsp[w * 32]);
        const float4 r1 = *reinterpret_cast<const float4*>(&rsp[w * 32 + 4]);
        const float av[4] = {a.x, a.y, a.z, a.w};
        const float rv[8] = {r0.x, r0.y, r0.z, r0.w, r1.x, r1.y, r1.z, r1.w};
#pragma unroll
        for (int d = 0; d < 8; d++)
#pragma unroll
            for (int p = 0; p < 4; p++)
                acc[d][p] += rv[d] * av[p];
    }

    const int bq = bh >> 3;
    const int kbase = (bh & 7) * 32 + dv0;
    const int mrow = (h0 + hloc) * 64;
#pragma unroll
    for (int p = 0; p < 4; p++) {
        const size_t o = (size_t)bq * 1048576 + (size_t)(mrow + wp0 + p) * 256 + kbase;
        *reinterpret_cast<float4*>(&g_r2[o]) =
            make_float4(acc[0][p], acc[1][p], acc[2][p], acc[3][p]);
        *reinterpret_cast<float4*>(&g_r2[o + 4]) =
            make_float4(acc[4][p], acc[5][p], acc[6][p], acc[7][p]);
    }
}

// ---------------------------------------------------------------------------
// Launch
// ---------------------------------------------------------------------------
extern "C" void kernel_launch(void* const* d_in, const int* in_sizes, int n_in,
                              void* d_out, int out_size)
{
    const float* x       = (const float*)d_in[0];
    const float* dw_qh_w = (const float*)d_in[1];
    const float* dw_qh_b = (const float*)d_in[2];
    const float* fc_qh_w = (const float*)d_in[3];
    const float* fc_qh_b = (const float*)d_in[4];
    const float* dw_kh_w = (const float*)d_in[5];
    const float* dw_kh_b = (const float*)d_in[6];
    const float* fc_kh_w = (const float*)d_in[7];
    const float* fc_kh_b = (const float*)d_in[8];
    const float* Bh      = (const float*)d_in[9];
    const float* dw_v_w  = (const float*)d_in[10];
    const float* dw_v_b  = (const float*)d_in[11];
    const float* fc_v_w  = (const float*)d_in[12];
    const float* fc_v_b  = (const float*)d_in[13];
    const float* dw_qw_w = (const float*)d_in[14];
    const float* dw_qw_b = (const float*)d_in[15];
    const float* fc_qw_w = (const float*)d_in[16];
    const float* fc_qw_b = (const float*)d_in[17];
    const float* dw_kw_w = (const float*)d_in[18];
    const float* dw_kw_b = (const float*)d_in[19];
    const float* fc_kw_w = (const float*)d_in[20];
    const float* fc_kw_b = (const float*)d_in[21];
    const float* Bw      = (const float*)d_in[22];
    const float* fc_o_w  = (const float*)d_in[23];
    const float* fc_o_b  = (const float*)d_in[24];
    float* out = (float*)d_out;

    const dim3 gconv(Cc, Bb);
    conv_pool_kernel<<<gconv, 256>>>(x, dw_qh_w, dw_qh_b, dw_kh_w, dw_kh_b,
                                     dw_qw_w, dw_qw_b, dw_kw_w, dw_kw_b);
    conv_v_kernel<<<gconv, 256>>>(x, dw_v_w, dw_v_b);
    transpose_v_kernel<<<dim3(128, 8, Bb), dim3(32, 8)>>>();

    qk_gemm_kernel<<<dim3(16, 4, 4), 256>>>(fc_qh_w, fc_qh_b, fc_kh_w, fc_kh_b,
                                            fc_qw_w, fc_qw_b, fc_kw_w, fc_kw_b);
    attn_kernel<<<dim3(Bb * Hh, 2), 64>>>(Bh, Bw);

    wmma_gemm_kernel<1><<<dim3(32, 4, Bb), 256>>>(fc_v_w, fc_v_b, nullptr);

    axialh_kernel<<<dim3(8, Bb * Hh), 256>>>();
    axialw_kernel<<<dim3(32, Bb * Hh), 128>>>();

    wmma_gemm_kernel<2><<<dim3(32, 4, Bb), 256>>>(fc_o_w, fc_o_b, out);
}

// round 4
// speedup vs baseline: 1.6810x; 1.2873x over previous
#include <cuda_runtime.h>
#include <mma.h>
#include <cstdint>

using namespace nvcuda;

#define Bb 16
#define Cc 256
#define Ss 64
#define Hh 8
#define Dd 32

// ---------------------------------------------------------------------------
// Scratch
// ---------------------------------------------------------------------------
__device__ float g_pool[4][Cc * Bb * Ss];              // [c][b*64+s]  (A^T for MODE0)
__device__ float g_qk[4][Bb * Hh * Ss * Dd];           // [b][head][s][d]
__device__ float g_attn[2][Bb * Hh * Ss * Ss];         // tf32-rounded
__device__ float g_vconv[(size_t)Bb * Cc * 4096];      // [b][c][hw]  (A^T for MODE1)
__device__ float g_v[(size_t)Bb * Hh * 4096 * 32 / 32 * 32]; // [b][head][hw][dv], tf32-rounded
__device__ float g_r[(size_t)Bb * Hh * Ss * Ss * Dd];  // [b][head][h][w*32+dv], tf32-rounded
__device__ float g_r2[(size_t)Bb * 4096 * Cc];         // [b][m=hw][k=head*32+dv]

__device__ __forceinline__ float to_tf32(float x) {
    float r;
    asm("cvt.rna.tf32.f32 %0, %1;" : "=f"(r) : "f"(x));
    return r;
}

// ---------------------------------------------------------------------------
// Kernel 1: analytic dwconv+axis-mean pooling for 4 q/k branches.
// mean_w(conv(x))[h] and mean_h(conv(x))[w] need only row sums S, col sums T
// and the 4 edge rows/cols of x (zero-pad corrections).
// ---------------------------------------------------------------------------
__global__ void __launch_bounds__(256) conv_pool_fast(
    const float* __restrict__ x,
    const float* __restrict__ wqh, const float* __restrict__ bqh,
    const float* __restrict__ wkh, const float* __restrict__ bkh,
    const float* __restrict__ wqw, const float* __restrict__ bqw,
    const float* __restrict__ wkw, const float* __restrict__ bkw)
{
    const int c = blockIdx.x;
    const int b = blockIdx.y;
    const int tid = threadIdx.x;

    __shared__ float rowp[2][64], colp[4][64];
    __shared__ float el[64], er[64], et[64], eb[64], T[64];
    __shared__ float wsm[4][9];
    __shared__ float bsm[4];

    if (tid < 9)        wsm[0][tid]      = wqh[c * 9 + tid];
    else if (tid < 18)  wsm[1][tid - 9]  = wkh[c * 9 + tid - 9];
    else if (tid < 27)  wsm[2][tid - 18] = wqw[c * 9 + tid - 18];
    else if (tid < 36)  wsm[3][tid - 27] = wkw[c * 9 + tid - 27];
    if (tid == 36) bsm[0] = bqh[c];
    if (tid == 37) bsm[1] = bkh[c];
    if (tid == 38) bsm[2] = bqw[c];
    if (tid == 39) bsm[3] = bkw[c];

    const int wcol = tid & 63;
    const int hgrp = tid >> 6;
    const float* xp = x + ((size_t)b * Cc + c) * 4096;

    float colacc = 0.f;
    for (int k = 0; k < 16; k++) {
        const int r = hgrp * 16 + k;
        const float v = xp[r * 64 + wcol];
        colacc += v;
        if (r == 0)     et[wcol] = v;
        if (r == 63)    eb[wcol] = v;
        if (wcol == 0)  el[r] = v;
        if (wcol == 63) er[r] = v;
        float rsum = v;
#pragma unroll
        for (int off = 16; off; off >>= 1)
            rsum += __shfl_down_sync(0xffffffffu, rsum, off);
        if ((tid & 31) == 0) rowp[(tid >> 5) & 1][r] = rsum;
    }
    colp[hgrp][wcol] = colacc;
    __syncthreads();
    if (tid < 64) T[tid] = colp[0][tid] + colp[1][tid] + colp[2][tid] + colp[3][tid];
    __syncthreads();

    if (tid < 64) {
        const int s = tid;
        float o0 = 0.f, o1 = 0.f, o2 = 0.f, o3 = 0.f;
#pragma unroll
        for (int d = 0; d < 3; d++) {
            const int r = s + d - 1;
            if (r >= 0 && r < 64) {
                const float Sv = rowp[0][r] + rowp[1][r];
                const float eL = el[r], eR = er[r];
                o0 += (wsm[0][d*3] + wsm[0][d*3+1] + wsm[0][d*3+2]) * Sv
                    - wsm[0][d*3] * eR - wsm[0][d*3+2] * eL;
                o1 += (wsm[1][d*3] + wsm[1][d*3+1] + wsm[1][d*3+2]) * Sv
                    - wsm[1][d*3] * eR - wsm[1][d*3+2] * eL;
                const float Tv = T[r], eT = et[r], eB = eb[r];
                o2 += (wsm[2][d] + wsm[2][3+d] + wsm[2][6+d]) * Tv
                    - wsm[2][d] * eB - wsm[2][6+d] * eT;
                o3 += (wsm[3][d] + wsm[3][3+d] + wsm[3][6+d]) * Tv
                    - wsm[3][d] * eB - wsm[3][6+d] * eT;
            }
        }
        const float inv = 1.f / 64.f;
        const int mi = b * 64 + s;
        g_pool[0][c * 1024 + mi] = o0 * inv + bsm[0];
        g_pool[1][c * 1024 + mi] = o1 * inv + bsm[1];
        g_pool[2][c * 1024 + mi] = o2 * inv + bsm[2];
        g_pool[3][c * 1024 + mi] = o3 * inv + bsm[3];
    }
}

// ---------------------------------------------------------------------------
// Kernel 2: depthwise 3x3 conv for V branch -> g_vconv [b][c][hw]
// ---------------------------------------------------------------------------
__global__ void __launch_bounds__(256) conv_v_kernel(
    const float* __restrict__ x,
    const float* __restrict__ wv, const float* __restrict__ bv)
{
    const int c = blockIdx.x;
    const int b = blockIdx.y;
    __shared__ float xs[66][66];
    const int tid = threadIdx.x;

    for (int i = tid; i < 66 * 66; i += 256) (&xs[0][0])[i] = 0.f;
    __syncthreads();

    const float* xp = x + ((size_t)b * Cc + c) * 4096;
    for (int i = tid; i < 4096; i += 256) xs[(i >> 6) + 1][(i & 63) + 1] = xp[i];

    float w[9];
#pragma unroll
    for (int i = 0; i < 9; i++) w[i] = wv[c * 9 + i];
    const float bias = bv[c];
    __syncthreads();

    float* op = g_vconv + ((size_t)b * Cc + c) * 4096;
    const int wcol = tid & 63;
    const int hgrp = tid >> 6;
    for (int k = 0; k < 16; k++) {
        const int h = hgrp * 16 + k;
        float s = bias;
#pragma unroll
        for (int dy = 0; dy < 3; dy++)
#pragma unroll
            for (int dx = 0; dx < 3; dx++)
                s += w[dy * 3 + dx] * xs[h + dy][wcol + dx];
        op[h * 64 + wcol] = s;
    }
}

// ---------------------------------------------------------------------------
// Kernel 3: attention scores + softmax (both axes); outputs tf32-rounded.
// ---------------------------------------------------------------------------
__global__ void __launch_bounds__(64) attn_kernel(
    const float* __restrict__ Bh, const float* __restrict__ Bw)
{
    const int bh = blockIdx.x;
    const int head = bh & 7;
    const int axis = blockIdx.y;
    const float scale = 0.17677669529663687f;

    const float* q = g_qk[axis == 0 ? 0 : 2];
    const float* k = g_qk[axis == 0 ? 1 : 3];
    const float* Bm = (axis == 0) ? Bh : Bw;
    float* o = g_attn[axis];

    __shared__ float ks[64][32];
    const int tid = threadIdx.x;
    for (int i = tid; i < 2048; i += 64) (&ks[0][0])[i] = k[(size_t)bh * 2048 + i];
    __syncthreads();

    float qr[32];
#pragma unroll
    for (int d = 0; d < 32; d++) qr[d] = q[(size_t)bh * 2048 + tid * 32 + d];

    float s[64];
    float mx = -1e30f;
#pragma unroll
    for (int j = 0; j < 64; j++) {
        float acc = 0.f;
#pragma unroll
        for (int d = 0; d < 32; d++) acc += qr[d] * ks[j][d];
        acc = acc * scale + Bm[head * 4096 + tid * 64 + j];
        s[j] = acc;
        mx = fmaxf(mx, acc);
    }
    float sum = 0.f;
#pragma unroll
    for (int j = 0; j < 64; j++) { s[j] = __expf(s[j] - mx); sum += s[j]; }
    const float r = 1.f / sum;
#pragma unroll
    for (int j = 0; j < 64; j++)
        o[(size_t)bh * 4096 + tid * 64 + j] = to_tf32(s[j] * r);
}

// ---------------------------------------------------------------------------
// Unified tf32 wmma GEMM: C[M][256] = A @ W^T + bias, K=256.
// BM=128, BN=128, BK=32; 8 warps (4x2), warp tile 32x64, bias via acc-init.
// MODE 0: A=g_pool[z] col-major ld1024 (M=1024), out->g_qk[z]
// MODE 1: A=g_vconv[b]  col-major ld4096 (M=4096), out->g_v (tf32-rounded)
// MODE 2: A=g_r2[b]     row-major ld256  (M=4096), out->d_out
// ---------------------------------------------------------------------------
template <int MODE>
__global__ void __launch_bounds__(256) wmma_gemm_kernel(
    const float* __restrict__ W0, const float* __restrict__ b0,
    const float* __restrict__ W1, const float* __restrict__ b1,
    const float* __restrict__ W2, const float* __restrict__ b2,
    const float* __restrict__ W3, const float* __restrict__ b3,
    float* __restrict__ outp)
{
    __shared__ float As[4608];          // 32x132 (col-major) or 128x36 (row-major)
    __shared__ float Ws[128 * 36];      // [n][k]
    __shared__ float sbias[16 * 132];   // 16 identical rows of bias

    const int tid = threadIdx.x;
    const int wid = tid >> 5;
    const int wm = wid >> 1;            // 0..3
    const int wn = wid & 1;             // 0..1
    const int m0 = blockIdx.x * 128;
    const int nb = blockIdx.y * 128;
    const int z = blockIdx.z;

    const float* A;
    const float* W;
    const float* bias;
    int ldA;
    if constexpr (MODE == 0) {
        A = g_pool[z]; ldA = 1024;
        W = (z == 0) ? W0 : (z == 1) ? W1 : (z == 2) ? W2 : W3;
        bias = (z == 0) ? b0 : (z == 1) ? b1 : (z == 2) ? b2 : b3;
    } else if constexpr (MODE == 1) {
        A = g_vconv + (size_t)z * 1048576; ldA = 4096; W = W0; bias = b0;
    } else {
        A = g_r2 + (size_t)z * 1048576; ldA = 256; W = W0; bias = b0;
    }

    for (int i = tid; i < 16 * 128; i += 256)
        sbias[(i >> 7) * 132 + (i & 127)] = bias[nb + (i & 127)];
    __syncthreads();

    wmma::fragment<wmma::accumulator, 16, 16, 8, float> acc[2][4];
#pragma unroll
    for (int i = 0; i < 2; i++)
#pragma unroll
        for (int j = 0; j < 4; j++)
            wmma::load_matrix_sync(acc[i][j], &sbias[wn * 64 + j * 16], 132,
                                   wmma::mem_row_major);

    for (int k0 = 0; k0 < 256; k0 += 32) {
        if constexpr (MODE != 2) {
            // A tile: 32 k-rows x 128 m-cols, store col-major As[k][m] ld 132
#pragma unroll
            for (int i = 0; i < 4; i++) {
                const int f = tid + 256 * i;
                const int k = f >> 5, mq = f & 31;
                float4 v = *reinterpret_cast<const float4*>(
                    A + (size_t)(k0 + k) * ldA + m0 + mq * 4);
                float* d = &As[k * 132 + mq * 4];
                d[0] = to_tf32(v.x); d[1] = to_tf32(v.y);
                d[2] = to_tf32(v.z); d[3] = to_tf32(v.w);
            }
        } else {
            // A tile: 128 m-rows x 32 k, store row-major As[m][k] ld 36
#pragma unroll
            for (int i = 0; i < 4; i++) {
                const int f = tid + 256 * i;
                const int m = f >> 3, kq = f & 7;
                float4 v = *reinterpret_cast<const float4*>(
                    A + (size_t)(m0 + m) * 256 + k0 + kq * 4);
                float* d = &As[m * 36 + kq * 4];
                d[0] = to_tf32(v.x); d[1] = to_tf32(v.y);
                d[2] = to_tf32(v.z); d[3] = to_tf32(v.w);
            }
        }
        // W tile: 128 n-rows x 32 k, Ws[n][k] ld 36
#pragma unroll
        for (int i = 0; i < 4; i++) {
            const int f = tid + 256 * i;
            const int n = f >> 3, kq = f & 7;
            float4 v = *reinterpret_cast<const float4*>(
                W + (size_t)(nb + n) * 256 + k0 + kq * 4);
            float* d = &Ws[n * 36 + kq * 4];
            d[0] = to_tf32(v.x); d[1] = to_tf32(v.y);
            d[2] = to_tf32(v.z); d[3] = to_tf32(v.w);
        }
        __syncthreads();

#pragma unroll
        for (int kk = 0; kk < 32; kk += 8) {
            wmma::fragment<wmma::matrix_b, 16, 16, 8, wmma::precision::tf32,
                           wmma::col_major> bf[4];
#pragma unroll
            for (int j = 0; j < 4; j++)
                wmma::load_matrix_sync(bf[j], &Ws[(wn * 64 + j * 16) * 36 + kk], 36);
            if constexpr (MODE != 2) {
                wmma::fragment<wmma::matrix_a, 16, 16, 8, wmma::precision::tf32,
                               wmma::col_major> af[2];
                wmma::load_matrix_sync(af[0], &As[kk * 132 + wm * 32], 132);
                wmma::load_matrix_sync(af[1], &As[kk * 132 + wm * 32 + 16], 132);
#pragma unroll
                for (int i = 0; i < 2; i++)
#pragma unroll
                    for (int j = 0; j < 4; j++)
                        wmma::mma_sync(acc[i][j], af[i], bf[j], acc[i][j]);
            } else {
                wmma::fragment<wmma::matrix_a, 16, 16, 8, wmma::precision::tf32,
                               wmma::row_major> af[2];
                wmma::load_matrix_sync(af[0], &As[(wm * 32) * 36 + kk], 36);
                wmma::load_matrix_sync(af[1], &As[(wm * 32 + 16) * 36 + kk], 36);
#pragma unroll
                for (int i = 0; i < 2; i++)
#pragma unroll
                    for (int j = 0; j < 4; j++)
                        wmma::mma_sync(acc[i][j], af[i], bf[j], acc[i][j]);
            }
        }
        __syncthreads();
    }

    // direct fragment stores
#pragma unroll
    for (int i = 0; i < 2; i++) {
#pragma unroll
        for (int j = 0; j < 4; j++) {
            const int mg = m0 + wm * 32 + i * 16;
            const int ng = nb + wn * 64 + j * 16;
            if constexpr (MODE == 1) {
#pragma unroll
                for (int t = 0; t < acc[i][j].num_elements; t++)
                    acc[i][j].x[t] = to_tf32(acc[i][j].x[t]);
            }
            float* dst;
            int ldc;
            if constexpr (MODE == 0) {
                dst = g_qk[z] + (size_t)(mg >> 6) * 16384 + (size_t)(ng >> 5) * 2048
                    + (size_t)(mg & 63) * 32 + (ng & 31);
                ldc = 32;
            } else if constexpr (MODE == 1) {
                dst = g_v + (size_t)z * 1048576 + (size_t)(ng >> 5) * 131072
                    + (size_t)mg * 32 + (ng & 31);
                ldc = 32;
            } else {
                dst = outp + (size_t)z * 1048576 + (size_t)mg * 256 + ng;
                ldc = 256;
            }
            wmma::store_matrix_sync(dst, acc[i][j], ldc, wmma::mem_row_major);
        }
    }
}

// ---------------------------------------------------------------------------
// Kernel 5: r = attn_h @ v  (wmma tf32, fragments straight from gmem)
// per bh: [64,64] x [64,2048]. Block covers 64 x 256; grid (8, 128).
// ---------------------------------------------------------------------------
__global__ void __launch_bounds__(256) axialh_wmma()
{
    const int bh = blockIdx.y;
    const int wid = threadIdx.x >> 5;
    const int wm = wid >> 2;                 // 0..1
    const int wn = wid & 3;                  // 0..3
    const float* Ag = g_attn[0] + (size_t)bh * 4096;
    const float* Bg = g_v + (size_t)bh * 131072;
    float* Rg = g_r + (size_t)bh * 131072;
    const int m0w = wm * 32;
    const int n0w = blockIdx.x * 256 + wn * 64;

    wmma::fragment<wmma::accumulator, 16, 16, 8, float> acc[2][4];
#pragma unroll
    for (int i = 0; i < 2; i++)
#pragma unroll
        for (int j = 0; j < 4; j++) wmma::fill_fragment(acc[i][j], 0.f);

#pragma unroll
    for (int k0 = 0; k0 < 64; k0 += 8) {
        wmma::fragment<wmma::matrix_a, 16, 16, 8, wmma::precision::tf32,
                       wmma::row_major> af[2];
        wmma::load_matrix_sync(af[0], Ag + (size_t)m0w * 64 + k0, 64);
        wmma::load_matrix_sync(af[1], Ag + (size_t)(m0w + 16) * 64 + k0, 64);
        wmma::fragment<wmma::matrix_b, 16, 16, 8, wmma::precision::tf32,
                       wmma::row_major> bf[4];
#pragma unroll
        for (int j = 0; j < 4; j++)
            wmma::load_matrix_sync(bf[j], Bg + (size_t)k0 * 2048 + n0w + j * 16, 2048);
#pragma unroll
        for (int i = 0; i < 2; i++)
#pragma unroll
            for (int j = 0; j < 4; j++)
                wmma::mma_sync(acc[i][j], af[i], bf[j], acc[i][j]);
    }
#pragma unroll
    for (int i = 0; i < 2; i++)
#pragma unroll
        for (int j = 0; j < 4; j++) {
#pragma unroll
            for (int t = 0; t < acc[i][j].num_elements; t++)
                acc[i][j].x[t] = to_tf32(acc[i][j].x[t]);
            wmma::store_matrix_sync(
                Rg + (size_t)(m0w + i * 16) * 2048 + n0w + j * 16,
                acc[i][j], 2048, wmma::mem_row_major);
        }
}

// ---------------------------------------------------------------------------
// Kernel 6: r2 = (r viewed [h*dv, w]) @ attn_w  (wmma tf32, gmem fragments).
// Per (bh,h): A = r[h] as col-major [dv][w] ld 32; output stored col-major
// ld 256 directly into g_r2 [b][hw][head*32+dv]. Grid (8, 128), warp = one h.
// ---------------------------------------------------------------------------
__global__ void __launch_bounds__(256) axialw_wmma()
{
    const int bh = blockIdx.y;
    const int wid = threadIdx.x >> 5;
    const int h = blockIdx.x * 8 + wid;
    const float* Ar = g_r + (size_t)bh * 131072 + (size_t)h * 2048;
    const float* Bg = g_attn[1] + (size_t)bh * 4096;
    float* dstb = g_r2 + (size_t)(bh >> 3) * 1048576
                + (size_t)h * 64 * 256 + (bh & 7) * 32;

    wmma::fragment<wmma::accumulator, 16, 16, 8, float> acc[2][4];
#pragma unroll
    for (int i = 0; i < 2; i++)
#pragma unroll
        for (int j = 0; j < 4; j++) wmma::fill_fragment(acc[i][j], 0.f);

#pragma unroll
    for (int k0 = 0; k0 < 64; k0 += 8) {
        wmma::fragment<wmma::matrix_a, 16, 16, 8, wmma::precision::tf32,
                       wmma::col_major> af[2];
        wmma::load_matrix_sync(af[0], Ar + (size_t)k0 * 32, 32);
        wmma::load_matrix_sync(af[1], Ar + (size_t)k0 * 32 + 16, 32);
        wmma::fragment<wmma::matrix_b, 16, 16, 8, wmma::precision::tf32,
                       wmma::row_major> bf[4];
#pragma unroll
        for (int j = 0; j < 4; j++)
            wmma::load_matrix_sync(bf[j], Bg + (size_t)k0 * 64 + j * 16, 64);
#pragma unroll
        for (int i = 0; i < 2; i++)
#pragma unroll
            for (int j = 0; j < 4; j++)
                wmma::mma_sync(acc[i][j], af[i], bf[j], acc[i][j]);
    }
#pragma unroll
    for (int i = 0; i < 2; i++)
#pragma unroll
        for (int j = 0; j < 4; j++)
            wmma::store_matrix_sync(dstb + (size_t)(j * 16) * 256 + i * 16,
                                    acc[i][j], 256, wmma::mem_col_major);
}

// ---------------------------------------------------------------------------
// Launch
// ---------------------------------------------------------------------------
extern "C" void kernel_launch(void* const* d_in, const int* in_sizes, int n_in,
                              void* d_out, int out_size)
{
    const float* x       = (const float*)d_in[0];
    const float* dw_qh_w = (const float*)d_in[1];
    const float* dw_qh_b = (const float*)d_in[2];
    const float* fc_qh_w = (const float*)d_in[3];
    const float* fc_qh_b = (const float*)d_in[4];
    const float* dw_kh_w = (const float*)d_in[5];
    const float* dw_kh_b = (const float*)d_in[6];
    const float* fc_kh_w = (const float*)d_in[7];
    const float* fc_kh_b = (const float*)d_in[8];
    const float* Bh      = (const float*)d_in[9];
    const float* dw_v_w  = (const float*)d_in[10];
    const float* dw_v_b  = (const float*)d_in[11];
    const float* fc_v_w  = (const float*)d_in[12];
    const float* fc_v_b  = (const float*)d_in[13];
    const float* dw_qw_w = (const float*)d_in[14];
    const float* dw_qw_b = (const float*)d_in[15];
    const float* fc_qw_w = (const float*)d_in[16];
    const float* fc_qw_b = (const float*)d_in[17];
    const float* dw_kw_w = (const float*)d_in[18];
    const float* dw_kw_b = (const float*)d_in[19];
    const float* fc_kw_w = (const float*)d_in[20];
    const float* fc_kw_b = (const float*)d_in[21];
    const float* Bw      = (const float*)d_in[22];
    const float* fc_o_w  = (const float*)d_in[23];
    const float* fc_o_b  = (const float*)d_in[24];
    float* out = (float*)d_out;

    const dim3 gconv(Cc, Bb);
    conv_pool_fast<<<gconv, 256>>>(x, dw_qh_w, dw_qh_b, dw_kh_w, dw_kh_b,
                                   dw_qw_w, dw_qw_b, dw_kw_w, dw_kw_b);
    conv_v_kernel<<<gconv, 256>>>(x, dw_v_w, dw_v_b);

    // q/k linears: M=1024, N=256, z=branch
    wmma_gemm_kernel<0><<<dim3(8, 2, 4), 256>>>(
        fc_qh_w, fc_qh_b, fc_kh_w, fc_kh_b,
        fc_qw_w, fc_qw_b, fc_kw_w, fc_kw_b, nullptr);

    attn_kernel<<<dim3(Bb * Hh, 2), 64>>>(Bh, Bw);

    // V linear: per-batch M=4096
    wmma_gemm_kernel<1><<<dim3(32, 2, Bb), 256>>>(
        fc_v_w, fc_v_b, fc_v_w, fc_v_b, fc_v_w, fc_v_b, fc_v_w, fc_v_b, nullptr);

    axialh_wmma<<<dim3(8, Bb * Hh), 256>>>();
    axialw_wmma<<<dim3(8, Bb * Hh), 256>>>();

    // output linear
    wmma_gemm_kernel<2><<<dim3(32, 2, Bb), 256>>>(
        fc_o_w, fc_o_b, fc_o_w, fc_o_b, fc_o_w, fc_o_b, fc_o_w, fc_o_b, out);
}

// round 5
// speedup vs baseline: 1.9229x; 1.1439x over previous
#include <cuda_runtime.h>
#include <mma.h>
#include <cstdint>

using namespace nvcuda;

#define Bb 16
#define Cc 256
#define Ss 64
#define Hh 8
#define Dd 32

// ---------------------------------------------------------------------------
// Scratch
// ---------------------------------------------------------------------------
__device__ float g_pool[4][Cc * Bb * Ss];              // [c][b*64+s]  (A^T for MODE0)
__device__ float g_qk[4][Bb * Hh * Ss * Dd];           // [b][head][s][d]
__device__ float g_attn[2][Bb * Hh * Ss * Ss];
__device__ float g_vconv[(size_t)Bb * Cc * 4096];      // [b][c][hw]  (A^T for MODE1)
__device__ float g_v[(size_t)Bb * Hh * 4096 * 32];     // [b][head][hw][dv]
__device__ float g_r[(size_t)Bb * Hh * Ss * Ss * Dd];  // [b][head][h][w*32+dv]
__device__ float g_r2[(size_t)Bb * 4096 * Cc];         // [b][m=hw][k=head*32+dv]

__device__ __forceinline__ void cp_async16(void* smem, const void* gmem) {
    uint32_t s = (uint32_t)__cvta_generic_to_shared(smem);
    asm volatile("cp.async.cg.shared.global [%0], [%1], 16;" :: "r"(s), "l"(gmem));
}
#define CP_COMMIT() asm volatile("cp.async.commit_group;" ::: "memory")
#define CP_WAIT(n)  asm volatile("cp.async.wait_group %0;" :: "n"(n) : "memory")

// ---------------------------------------------------------------------------
// Kernel 1: fused depthwise 3x3 conv (V branch, full grid) + analytic
// dwconv+axis-mean pooling for the 4 q/k branches. One read of x.
// ---------------------------------------------------------------------------
__global__ void __launch_bounds__(256) conv_fused_kernel(
    const float* __restrict__ x,
    const float* __restrict__ wv,  const float* __restrict__ bv,
    const float* __restrict__ wqh, const float* __restrict__ bqh,
    const float* __restrict__ wkh, const float* __restrict__ bkh,
    const float* __restrict__ wqw, const float* __restrict__ bqw,
    const float* __restrict__ wkw, const float* __restrict__ bkw)
{
    const int c = blockIdx.x;
    const int b = blockIdx.y;
    const int tid = threadIdx.x;

    __shared__ float xs[66][66];
    __shared__ float rowp[2][64], colp[4][64];
    __shared__ float T[64];
    __shared__ float wsm[4][9];
    __shared__ float bsm[4];

    for (int i = tid; i < 66 * 66; i += 256) (&xs[0][0])[i] = 0.f;
    __syncthreads();

    const float* xp = x + ((size_t)b * Cc + c) * 4096;
    for (int i = tid; i < 4096; i += 256) xs[(i >> 6) + 1][(i & 63) + 1] = xp[i];

    if (tid < 9)        wsm[0][tid]      = wqh[c * 9 + tid];
    else if (tid < 18)  wsm[1][tid - 9]  = wkh[c * 9 + tid - 9];
    else if (tid < 27)  wsm[2][tid - 18] = wqw[c * 9 + tid - 18];
    else if (tid < 36)  wsm[3][tid - 27] = wkw[c * 9 + tid - 27];
    if (tid == 36) bsm[0] = bqh[c];
    if (tid == 37) bsm[1] = bkh[c];
    if (tid == 38) bsm[2] = bqw[c];
    if (tid == 39) bsm[3] = bkw[c];

    float w[9];
#pragma unroll
    for (int i = 0; i < 9; i++) w[i] = wv[c * 9 + i];
    const float bias = bv[c];
    __syncthreads();

    const int wcol = tid & 63;
    const int hgrp = tid >> 6;
    float* op = g_vconv + ((size_t)b * Cc + c) * 4096;

    float colacc = 0.f;
    for (int k = 0; k < 16; k++) {
        const int h = hgrp * 16 + k;
        // V conv output at (h, wcol)
        float s = bias;
#pragma unroll
        for (int dy = 0; dy < 3; dy++)
#pragma unroll
            for (int dx = 0; dx < 3; dx++)
                s += w[dy * 3 + dx] * xs[h + dy][wcol + dx];
        op[h * 64 + wcol] = s;
        // pooled statistics from the same tile
        const float v = xs[h + 1][wcol + 1];
        colacc += v;
        float rsum = v;
#pragma unroll
        for (int off = 16; off; off >>= 1)
            rsum += __shfl_down_sync(0xffffffffu, rsum, off);
        if ((tid & 31) == 0) rowp[(tid >> 5) & 1][h] = rsum;
    }
    colp[hgrp][wcol] = colacc;
    __syncthreads();
    if (tid < 64) T[tid] = colp[0][tid] + colp[1][tid] + colp[2][tid] + colp[3][tid];
    __syncthreads();

    if (tid < 64) {
        const int s = tid;
        float o0 = 0.f, o1 = 0.f, o2 = 0.f, o3 = 0.f;
#pragma unroll
        for (int d = 0; d < 3; d++) {
            const int r = s + d - 1;
            if (r >= 0 && r < 64) {
                const float Sv = rowp[0][r] + rowp[1][r];
                const float eL = xs[r + 1][1], eR = xs[r + 1][64];
                o0 += (wsm[0][d*3] + wsm[0][d*3+1] + wsm[0][d*3+2]) * Sv
                    - wsm[0][d*3] * eR - wsm[0][d*3+2] * eL;
                o1 += (wsm[1][d*3] + wsm[1][d*3+1] + wsm[1][d*3+2]) * Sv
                    - wsm[1][d*3] * eR - wsm[1][d*3+2] * eL;
                const float Tv = T[r];
                const float eT = xs[1][r + 1], eB = xs[64][r + 1];
                o2 += (wsm[2][d] + wsm[2][3+d] + wsm[2][6+d]) * Tv
                    - wsm[2][d] * eB - wsm[2][6+d] * eT;
                o3 += (wsm[3][d] + wsm[3][3+d] + wsm[3][6+d]) * Tv
                    - wsm[3][d] * eB - wsm[3][6+d] * eT;
            }
        }
        const float inv = 1.f / 64.f;
        const int mi = b * 64 + s;
        g_pool[0][c * 1024 + mi] = o0 * inv + bsm[0];
        g_pool[1][c * 1024 + mi] = o1 * inv + bsm[1];
        g_pool[2][c * 1024 + mi] = o2 * inv + bsm[2];
        g_pool[3][c * 1024 + mi] = o3 * inv + bsm[3];
    }
}

// ---------------------------------------------------------------------------
// Kernel 2: attention scores + softmax; 4 bh per 256-thread block.
// ---------------------------------------------------------------------------
__global__ void __launch_bounds__(256) attn_kernel(
    const float* __restrict__ Bh, const float* __restrict__ Bw)
{
    const int grp = threadIdx.x >> 6;           // 0..3: which bh in this block
    const int bh = blockIdx.x * 4 + grp;
    const int head = bh & 7;
    const int axis = blockIdx.y;
    const float scale = 0.17677669529663687f;

    const float* q = g_qk[axis == 0 ? 0 : 2];
    const float* k = g_qk[axis == 0 ? 1 : 3];
    const float* Bm = (axis == 0) ? Bh : Bw;
    float* o = g_attn[axis];

    __shared__ float ks[4][64][32];
    const int tid = threadIdx.x & 63;
    for (int i = tid; i < 2048; i += 64)
        (&ks[grp][0][0])[i] = k[(size_t)bh * 2048 + i];
    __syncthreads();

    float qr[32];
#pragma unroll
    for (int d = 0; d < 32; d++) qr[d] = q[(size_t)bh * 2048 + tid * 32 + d];

    float s[64];
    float mx = -1e30f;
#pragma unroll
    for (int j = 0; j < 64; j++) {
        float acc = 0.f;
#pragma unroll
        for (int d = 0; d < 32; d++) acc += qr[d] * ks[grp][j][d];
        acc = acc * scale + Bm[head * 4096 + tid * 64 + j];
        s[j] = acc;
        mx = fmaxf(mx, acc);
    }
    float sum = 0.f;
#pragma unroll
    for (int j = 0; j < 64; j++) { s[j] = __expf(s[j] - mx); sum += s[j]; }
    const float r = 1.f / sum;
#pragma unroll
    for (int j = 0; j < 64; j++) o[(size_t)bh * 4096 + tid * 64 + j] = s[j] * r;
}

// ---------------------------------------------------------------------------
// Unified tf32 wmma GEMM with cp.async double buffering.
// C[M][256] = A @ W^T + bias, K=256. BM=128, BN=128, BK=32; 8 warps (4x2).
// Raw fp32 staged; HMMA.tf32 truncates mantissa in HW.
// MODE 0: A=g_pool[z] col-major ld1024, out->g_qk[z]
// MODE 1: A=g_vconv[b] col-major ld4096, out->g_v
// MODE 2: A=g_r2[b]    row-major ld256,  out->d_out
// ---------------------------------------------------------------------------
template <int MODE>
__global__ void __launch_bounds__(256) wmma_gemm_kernel(
    const float* __restrict__ W0, const float* __restrict__ b0,
    const float* __restrict__ W1, const float* __restrict__ b1,
    const float* __restrict__ W2, const float* __restrict__ b2,
    const float* __restrict__ W3, const float* __restrict__ b3,
    float* __restrict__ outp)
{
    __shared__ float As[2][4608];       // 32x132 (col-major) or 128x36 (row-major)
    __shared__ float Ws[2][128 * 36];   // [n][k]
    __shared__ float sbias[16 * 132];

    const int tid = threadIdx.x;
    const int wid = tid >> 5;
    const int wm = wid >> 1;
    const int wn = wid & 1;
    const int m0 = blockIdx.x * 128;
    const int nb = blockIdx.y * 128;
    const int z = blockIdx.z;

    const float* A;
    const float* W;
    const float* bias;
    int ldA;
    if constexpr (MODE == 0) {
        A = g_pool[z]; ldA = 1024;
        W = (z == 0) ? W0 : (z == 1) ? W1 : (z == 2) ? W2 : W3;
        bias = (z == 0) ? b0 : (z == 1) ? b1 : (z == 2) ? b2 : b3;
    } else if constexpr (MODE == 1) {
        A = g_vconv + (size_t)z * 1048576; ldA = 4096; W = W0; bias = b0;
    } else {
        A = g_r2 + (size_t)z * 1048576; ldA = 256; W = W0; bias = b0;
    }

    // async tile loader (1024 16B-chunks per operand tile, 4 per thread each)
    auto load_tiles = [&](int k0, int buf) {
#pragma unroll
        for (int i = 0; i < 4; i++) {
            const int f = tid + 256 * i;
            if constexpr (MODE != 2) {
                const int k = f >> 5, mq = f & 31;
                cp_async16(&As[buf][k * 132 + mq * 4],
                           A + (size_t)(k0 + k) * ldA + m0 + mq * 4);
            } else {
                const int m = f >> 3, kq = f & 7;
                cp_async16(&As[buf][m * 36 + kq * 4],
                           A + (size_t)(m0 + m) * 256 + k0 + kq * 4);
            }
            const int n = f >> 3, kq = f & 7;
            cp_async16(&Ws[buf][n * 36 + kq * 4],
                       W + (size_t)(nb + n) * 256 + k0 + kq * 4);
        }
        CP_COMMIT();
    };

    for (int i = tid; i < 16 * 128; i += 256)
        sbias[(i >> 7) * 132 + (i & 127)] = bias[nb + (i & 127)];

    load_tiles(0, 0);
    __syncthreads();   // sbias visible

    wmma::fragment<wmma::accumulator, 16, 16, 8, float> acc[2][4];
#pragma unroll
    for (int i = 0; i < 2; i++)
#pragma unroll
        for (int j = 0; j < 4; j++)
            wmma::load_matrix_sync(acc[i][j], &sbias[wn * 64 + j * 16], 132,
                                   wmma::mem_row_major);

    int buf = 0;
    for (int it = 0; it < 8; it++) {
        if (it < 7) load_tiles((it + 1) * 32, buf ^ 1);
        if (it < 7) { CP_WAIT(1); } else { CP_WAIT(0); }
        __syncthreads();

#pragma unroll
        for (int kk = 0; kk < 32; kk += 8) {
            wmma::fragment<wmma::matrix_b, 16, 16, 8, wmma::precision::tf32,
                           wmma::col_major> bf[4];
#pragma unroll
            for (int j = 0; j < 4; j++)
                wmma::load_matrix_sync(bf[j], &Ws[buf][(wn * 64 + j * 16) * 36 + kk], 36);
            if constexpr (MODE != 2) {
                wmma::fragment<wmma::matrix_a, 16, 16, 8, wmma::precision::tf32,
                               wmma::col_major> af[2];
                wmma::load_matrix_sync(af[0], &As[buf][kk * 132 + wm * 32], 132);
                wmma::load_matrix_sync(af[1], &As[buf][kk * 132 + wm * 32 + 16], 132);
#pragma unroll
                for (int i = 0; i < 2; i++)
#pragma unroll
                    for (int j = 0; j < 4; j++)
                        wmma::mma_sync(acc[i][j], af[i], bf[j], acc[i][j]);
            } else {
                wmma::fragment<wmma::matrix_a, 16, 16, 8, wmma::precision::tf32,
                               wmma::row_major> af[2];
                wmma::load_matrix_sync(af[0], &As[buf][(wm * 32) * 36 + kk], 36);
                wmma::load_matrix_sync(af[1], &As[buf][(wm * 32 + 16) * 36 + kk], 36);
#pragma unroll
                for (int i = 0; i < 2; i++)
#pragma unroll
                    for (int j = 0; j < 4; j++)
                        wmma::mma_sync(acc[i][j], af[i], bf[j], acc[i][j]);
            }
        }
        __syncthreads();
        buf ^= 1;
    }

#pragma unroll
    for (int i = 0; i < 2; i++) {
#pragma unroll
        for (int j = 0; j < 4; j++) {
            const int mg = m0 + wm * 32 + i * 16;
            const int ng = nb + wn * 64 + j * 16;
            float* dst;
            int ldc;
            if constexpr (MODE == 0) {
                dst = g_qk[z] + (size_t)(mg >> 6) * 16384 + (size_t)(ng >> 5) * 2048
                    + (size_t)(mg & 63) * 32 + (ng & 31);
                ldc = 32;
            } else if constexpr (MODE == 1) {
                dst = g_v + (size_t)z * 1048576 + (size_t)(ng >> 5) * 131072
                    + (size_t)mg * 32 + (ng & 31);
                ldc = 32;
            } else {
                dst = outp + (size_t)z * 1048576 + (size_t)mg * 256 + ng;
                ldc = 256;
            }
            wmma::store_matrix_sync(dst, acc[i][j], ldc, wmma::mem_row_major);
        }
    }
}

// ---------------------------------------------------------------------------
// Kernel 4: r = attn_h @ v  (wmma tf32, fragments straight from gmem)
// ---------------------------------------------------------------------------
__global__ void __launch_bounds__(256) axialh_wmma()
{
    const int bh = blockIdx.y;
    const int wid = threadIdx.x >> 5;
    const int wm = wid >> 2;
    const int wn = wid & 3;
    const float* Ag = g_attn[0] + (size_t)bh * 4096;
    const float* Bg = g_v + (size_t)bh * 131072;
    float* Rg = g_r + (size_t)bh * 131072;
    const int m0w = wm * 32;
    const int n0w = blockIdx.x * 256 + wn * 64;

    wmma::fragment<wmma::accumulator, 16, 16, 8, float> acc[2][4];
#pragma unroll
    for (int i = 0; i < 2; i++)
#pragma unroll
        for (int j = 0; j < 4; j++) wmma::fill_fragment(acc[i][j], 0.f);

#pragma unroll
    for (int k0 = 0; k0 < 64; k0 += 8) {
        wmma::fragment<wmma::matrix_a, 16, 16, 8, wmma::precision::tf32,
                       wmma::row_major> af[2];
        wmma::load_matrix_sync(af[0], Ag + (size_t)m0w * 64 + k0, 64);
        wmma::load_matrix_sync(af[1], Ag + (size_t)(m0w + 16) * 64 + k0, 64);
        wmma::fragment<wmma::matrix_b, 16, 16, 8, wmma::precision::tf32,
                       wmma::row_major> bf[4];
#pragma unroll
        for (int j = 0; j < 4; j++)
            wmma::load_matrix_sync(bf[j], Bg + (size_t)k0 * 2048 + n0w + j * 16, 2048);
#pragma unroll
        for (int i = 0; i < 2; i++)
#pragma unroll
            for (int j = 0; j < 4; j++)
                wmma::mma_sync(acc[i][j], af[i], bf[j], acc[i][j]);
    }
#pragma unroll
    for (int i = 0; i < 2; i++)
#pragma unroll
        for (int j = 0; j < 4; j++)
            wmma::store_matrix_sync(
                Rg + (size_t)(m0w + i * 16) * 2048 + n0w + j * 16,
                acc[i][j], 2048, wmma::mem_row_major);
}

// ---------------------------------------------------------------------------
// Kernel 5: r2 = (r viewed [h*dv, w]) @ attn_w; output col-major into g_r2.
// ---------------------------------------------------------------------------
__global__ void __launch_bounds__(256) axialw_wmma()
{
    const int bh = blockIdx.y;
    const int wid = threadIdx.x >> 5;
    const int h = blockIdx.x * 8 + wid;
    const float* Ar = g_r + (size_t)bh * 131072 + (size_t)h * 2048;
    const float* Bg = g_attn[1] + (size_t)bh * 4096;
    float* dstb = g_r2 + (size_t)(bh >> 3) * 1048576
                + (size_t)h * 64 * 256 + (bh & 7) * 32;

    wmma::fragment<wmma::accumulator, 16, 16, 8, float> acc[2][4];
#pragma unroll
    for (int i = 0; i < 2; i++)
#pragma unroll
        for (int j = 0; j < 4; j++) wmma::fill_fragment(acc[i][j], 0.f);

#pragma unroll
    for (int k0 = 0; k0 < 64; k0 += 8) {
        wmma::fragment<wmma::matrix_a, 16, 16, 8, wmma::precision::tf32,
                       wmma::col_major> af[2];
        wmma::load_matrix_sync(af[0], Ar + (size_t)k0 * 32, 32);
        wmma::load_matrix_sync(af[1], Ar + (size_t)k0 * 32 + 16, 32);
        wmma::fragment<wmma::matrix_b, 16, 16, 8, wmma::precision::tf32,
                       wmma::row_major> bf[4];
#pragma unroll
        for (int j = 0; j < 4; j++)
            wmma::load_matrix_sync(bf[j], Bg + (size_t)k0 * 64 + j * 16, 64);
#pragma unroll
        for (int i = 0; i < 2; i++)
#pragma unroll
            for (int j = 0; j < 4; j++)
                wmma::mma_sync(acc[i][j], af[i], bf[j], acc[i][j]);
    }
#pragma unroll
    for (int i = 0; i < 2; i++)
#pragma unroll
        for (int j = 0; j < 4; j++)
            wmma::store_matrix_sync(dstb + (size_t)(j * 16) * 256 + i * 16,
                                    acc[i][j], 256, wmma::mem_col_major);
}

// ---------------------------------------------------------------------------
// Launch
// ---------------------------------------------------------------------------
extern "C" void kernel_launch(void* const* d_in, const int* in_sizes, int n_in,
                              void* d_out, int out_size)
{
    const float* x       = (const float*)d_in[0];
    const float* dw_qh_w = (const float*)d_in[1];
    const float* dw_qh_b = (const float*)d_in[2];
    const float* fc_qh_w = (const float*)d_in[3];
    const float* fc_qh_b = (const float*)d_in[4];
    const float* dw_kh_w = (const float*)d_in[5];
    const float* dw_kh_b = (const float*)d_in[6];
    const float* fc_kh_w = (const float*)d_in[7];
    const float* fc_kh_b = (const float*)d_in[8];
    const float* Bh      = (const float*)d_in[9];
    const float* dw_v_w  = (const float*)d_in[10];
    const float* dw_v_b  = (const float*)d_in[11];
    const float* fc_v_w  = (const float*)d_in[12];
    const float* fc_v_b  = (const float*)d_in[13];
    const float* dw_qw_w = (const float*)d_in[14];
    const float* dw_qw_b = (const float*)d_in[15];
    const float* fc_qw_w = (const float*)d_in[16];
    const float* fc_qw_b = (const float*)d_in[17];
    const float* dw_kw_w = (const float*)d_in[18];
    const float* dw_kw_b = (const float*)d_in[19];
    const float* fc_kw_w = (const float*)d_in[20];
    const float* fc_kw_b = (const float*)d_in[21];
    const float* Bw      = (const float*)d_in[22];
    const float* fc_o_w  = (const float*)d_in[23];
    const float* fc_o_b  = (const float*)d_in[24];
    float* out = (float*)d_out;

    conv_fused_kernel<<<dim3(Cc, Bb), 256>>>(
        x, dw_v_w, dw_v_b,
        dw_qh_w, dw_qh_b, dw_kh_w, dw_kh_b,
        dw_qw_w, dw_qw_b, dw_kw_w, dw_kw_b);

    wmma_gemm_kernel<0><<<dim3(8, 2, 4), 256>>>(
        fc_qh_w, fc_qh_b, fc_kh_w, fc_kh_b,
        fc_qw_w, fc_qw_b, fc_kw_w, fc_kw_b, nullptr);

    attn_kernel<<<dim3(32, 2), 256>>>(Bh, Bw);

    wmma_gemm_kernel<1><<<dim3(32, 2, Bb), 256>>>(
        fc_v_w, fc_v_b, fc_v_w, fc_v_b, fc_v_w, fc_v_b, fc_v_w, fc_v_b, nullptr);

    axialh_wmma<<<dim3(8, Bb * Hh), 256>>>();
    axialw_wmma<<<dim3(8, Bb * Hh), 256>>>();

    wmma_gemm_kernel<2><<<dim3(32, 2, Bb), 256>>>(
        fc_o_w, fc_o_b, fc_o_w, fc_o_b, fc_o_w, fc_o_b, fc_o_w, fc_o_b, out);
}

// round 6
// speedup vs baseline: 1.9815x; 1.0304x over previous
#include <cuda_runtime.h>
#include <mma.h>
#include <cstdint>

using namespace nvcuda;

#define Bb 16
#define Cc 256
#define Ss 64
#define Hh 8
#define Dd 32

// ---------------------------------------------------------------------------
// Scratch
// ---------------------------------------------------------------------------
__device__ float g_pool[4][Cc * Bb * Ss];              // [c][b*64+s]  (A^T, tf32)
__device__ float g_qk[4][Bb * Hh * Ss * Dd];           // [b][head][s][d] fp32
__device__ float g_attn[2][Bb * Hh * Ss * Ss];         // tf32
__device__ float g_vconv[(size_t)Bb * Cc * 4096];      // [b][c][hw] (A^T, tf32)
__device__ float g_v[(size_t)Bb * Hh * 4096 * 32];     // [b][head][hw][dv] tf32
__device__ float g_r2[(size_t)Bb * 4096 * Cc];         // [b][m=hw][k] tf32
__device__ float g_w[6][Cc * Cc];                      // pre-rounded tf32 weights

__device__ __forceinline__ float to_tf32(float x) {
    float r;
    asm("cvt.rna.tf32.f32 %0, %1;" : "=f"(r) : "f"(x));
    return r;
}
__device__ __forceinline__ void cp_async16(void* smem, const void* gmem) {
    uint32_t s = (uint32_t)__cvta_generic_to_shared(smem);
    asm volatile("cp.async.cg.shared.global [%0], [%1], 16;" :: "r"(s), "l"(gmem));
}
#define CP_COMMIT() asm volatile("cp.async.commit_group;" ::: "memory")
#define CP_WAIT(n)  asm volatile("cp.async.wait_group %0;" :: "n"(n) : "memory")

// ---------------------------------------------------------------------------
// Kernel 0: RNA-round the 6 fc weight matrices into g_w.
// ---------------------------------------------------------------------------
__global__ void __launch_bounds__(1024) round_weights(
    const float* __restrict__ w0, const float* __restrict__ w1,
    const float* __restrict__ w2, const float* __restrict__ w3,
    const float* __restrict__ w4, const float* __restrict__ w5)
{
    const float* src = (blockIdx.y == 0) ? w0 : (blockIdx.y == 1) ? w1
                     : (blockIdx.y == 2) ? w2 : (blockIdx.y == 3) ? w3
                     : (blockIdx.y == 4) ? w4 : w5;
    const int i = blockIdx.x * 1024 + threadIdx.x;
    g_w[blockIdx.y][i] = to_tf32(src[i]);
}

// ---------------------------------------------------------------------------
// Kernel 1: fused V dwconv + analytic pooled q/k branches. One read of x.
// Outputs RNA-rounded (they feed tf32 GEMM A operands).
// ---------------------------------------------------------------------------
__global__ void __launch_bounds__(256) conv_fused_kernel(
    const float* __restrict__ x,
    const float* __restrict__ wv,  const float* __restrict__ bv,
    const float* __restrict__ wqh, const float* __restrict__ bqh,
    const float* __restrict__ wkh, const float* __restrict__ bkh,
    const float* __restrict__ wqw, const float* __restrict__ bqw,
    const float* __restrict__ wkw, const float* __restrict__ bkw)
{
    const int c = blockIdx.x;
    const int b = blockIdx.y;
    const int tid = threadIdx.x;

    __shared__ float xs[66][66];
    __shared__ float rowp[2][64], colp[4][64];
    __shared__ float T[64];
    __shared__ float wsm[4][9];
    __shared__ float bsm[4];

    for (int i = tid; i < 66 * 66; i += 256) (&xs[0][0])[i] = 0.f;
    __syncthreads();

    const float* xp = x + ((size_t)b * Cc + c) * 4096;
    for (int i = tid; i < 4096; i += 256) xs[(i >> 6) + 1][(i & 63) + 1] = xp[i];

    if (tid < 9)        wsm[0][tid]      = wqh[c * 9 + tid];
    else if (tid < 18)  wsm[1][tid - 9]  = wkh[c * 9 + tid - 9];
    else if (tid < 27)  wsm[2][tid - 18] = wqw[c * 9 + tid - 18];
    else if (tid < 36)  wsm[3][tid - 27] = wkw[c * 9 + tid - 27];
    if (tid == 36) bsm[0] = bqh[c];
    if (tid == 37) bsm[1] = bkh[c];
    if (tid == 38) bsm[2] = bqw[c];
    if (tid == 39) bsm[3] = bkw[c];

    float w[9];
#pragma unroll
    for (int i = 0; i < 9; i++) w[i] = wv[c * 9 + i];
    const float bias = bv[c];
    __syncthreads();

    const int wcol = tid & 63;
    const int hgrp = tid >> 6;
    float* op = g_vconv + ((size_t)b * Cc + c) * 4096;

    float colacc = 0.f;
    for (int k = 0; k < 16; k++) {
        const int h = hgrp * 16 + k;
        float s = bias;
#pragma unroll
        for (int dy = 0; dy < 3; dy++)
#pragma unroll
            for (int dx = 0; dx < 3; dx++)
                s += w[dy * 3 + dx] * xs[h + dy][wcol + dx];
        op[h * 64 + wcol] = to_tf32(s);
        const float v = xs[h + 1][wcol + 1];
        colacc += v;
        float rsum = v;
#pragma unroll
        for (int off = 16; off; off >>= 1)
            rsum += __shfl_down_sync(0xffffffffu, rsum, off);
        if ((tid & 31) == 0) rowp[(tid >> 5) & 1][h] = rsum;
    }
    colp[hgrp][wcol] = colacc;
    __syncthreads();
    if (tid < 64) T[tid] = colp[0][tid] + colp[1][tid] + colp[2][tid] + colp[3][tid];
    __syncthreads();

    if (tid < 64) {
        const int s = tid;
        float o0 = 0.f, o1 = 0.f, o2 = 0.f, o3 = 0.f;
#pragma unroll
        for (int d = 0; d < 3; d++) {
            const int r = s + d - 1;
            if (r >= 0 && r < 64) {
                const float Sv = rowp[0][r] + rowp[1][r];
                const float eL = xs[r + 1][1], eR = xs[r + 1][64];
                o0 += (wsm[0][d*3] + wsm[0][d*3+1] + wsm[0][d*3+2]) * Sv
                    - wsm[0][d*3] * eR - wsm[0][d*3+2] * eL;
                o1 += (wsm[1][d*3] + wsm[1][d*3+1] + wsm[1][d*3+2]) * Sv
                    - wsm[1][d*3] * eR - wsm[1][d*3+2] * eL;
                const float Tv = T[r];
                const float eT = xs[1][r + 1], eB = xs[64][r + 1];
                o2 += (wsm[2][d] + wsm[2][3+d] + wsm[2][6+d]) * Tv
                    - wsm[2][d] * eB - wsm[2][6+d] * eT;
                o3 += (wsm[3][d] + wsm[3][3+d] + wsm[3][6+d]) * Tv
                    - wsm[3][d] * eB - wsm[3][6+d] * eT;
            }
        }
        const float inv = 1.f / 64.f;
        const int mi = b * 64 + s;
        g_pool[0][c * 1024 + mi] = to_tf32(o0 * inv + bsm[0]);
        g_pool[1][c * 1024 + mi] = to_tf32(o1 * inv + bsm[1]);
        g_pool[2][c * 1024 + mi] = to_tf32(o2 * inv + bsm[2]);
        g_pool[3][c * 1024 + mi] = to_tf32(o3 * inv + bsm[3]);
    }
}

// ---------------------------------------------------------------------------
// Kernel 2: attention scores + softmax; 4 bh per block; rounds output.
// ---------------------------------------------------------------------------
__global__ void __launch_bounds__(256) attn_kernel(
    const float* __restrict__ Bh, const float* __restrict__ Bw)
{
    const int grp = threadIdx.x >> 6;
    const int bh = blockIdx.x * 4 + grp;
    const int head = bh & 7;
    const int axis = blockIdx.y;
    const float scale = 0.17677669529663687f;

    const float* q = g_qk[axis == 0 ? 0 : 2];
    const float* k = g_qk[axis == 0 ? 1 : 3];
    const float* Bm = (axis == 0) ? Bh : Bw;
    float* o = g_attn[axis];

    __shared__ float ks[4][64][32];
    const int tid = threadIdx.x & 63;
    for (int i = tid; i < 2048; i += 64)
        (&ks[grp][0][0])[i] = k[(size_t)bh * 2048 + i];
    __syncthreads();

    float qr[32];
#pragma unroll
    for (int d = 0; d < 32; d++) qr[d] = q[(size_t)bh * 2048 + tid * 32 + d];

    float s[64];
    float mx = -1e30f;
#pragma unroll
    for (int j = 0; j < 64; j++) {
        float acc = 0.f;
#pragma unroll
        for (int d = 0; d < 32; d++) acc += qr[d] * ks[grp][j][d];
        acc = acc * scale + Bm[head * 4096 + tid * 64 + j];
        s[j] = acc;
        mx = fmaxf(mx, acc);
    }
    float sum = 0.f;
#pragma unroll
    for (int j = 0; j < 64; j++) { s[j] = __expf(s[j] - mx); sum += s[j]; }
    const float r = 1.f / sum;
#pragma unroll
    for (int j = 0; j < 64; j++)
        o[(size_t)bh * 4096 + tid * 64 + j] = to_tf32(s[j] * r);
}

// ---------------------------------------------------------------------------
// Unified tf32 wmma GEMM, cp.async double buffered, 2 CTAs/SM.
// Weights read from pre-rounded g_w. All A operands pre-rounded.
// MODE 0: A=g_pool[z] col-major, W=g_w[z],  out->g_qk[z] (fp32)
// MODE 1: A=g_vconv[b] col-major, W=g_w[4], out->g_v (rounded)
// MODE 2: A=g_r2[b] row-major,    W=g_w[5], out->d_out (fp32)
// ---------------------------------------------------------------------------
template <int MODE>
__global__ void __launch_bounds__(256, 2) wmma_gemm_kernel(
    const float* __restrict__ b0, const float* __restrict__ b1,
    const float* __restrict__ b2, const float* __restrict__ b3,
    float* __restrict__ outp)
{
    __shared__ float As[2][4608];
    __shared__ float Ws[2][128 * 36];
    __shared__ float sbias[16 * 132];

    const int tid = threadIdx.x;
    const int wid = tid >> 5;
    const int wm = wid >> 1;
    const int wn = wid & 1;
    const int m0 = blockIdx.x * 128;
    const int nb = blockIdx.y * 128;
    const int z = blockIdx.z;

    const float* A;
    const float* bias;
    int ldA;
    const float* W = g_w[(MODE == 0) ? z : (MODE == 1) ? 4 : 5];
    if constexpr (MODE == 0) {
        A = g_pool[z]; ldA = 1024;
        bias = (z == 0) ? b0 : (z == 1) ? b1 : (z == 2) ? b2 : b3;
    } else if constexpr (MODE == 1) {
        A = g_vconv + (size_t)z * 1048576; ldA = 4096; bias = b0;
    } else {
        A = g_r2 + (size_t)z * 1048576; ldA = 256; bias = b0;
    }

    auto load_tiles = [&](int k0, int buf) {
#pragma unroll
        for (int i = 0; i < 4; i++) {
            const int f = tid + 256 * i;
            if constexpr (MODE != 2) {
                const int k = f >> 5, mq = f & 31;
                cp_async16(&As[buf][k * 132 + mq * 4],
                           A + (size_t)(k0 + k) * ldA + m0 + mq * 4);
            } else {
                const int m = f >> 3, kq = f & 7;
                cp_async16(&As[buf][m * 36 + kq * 4],
                           A + (size_t)(m0 + m) * 256 + k0 + kq * 4);
            }
            const int n = f >> 3, kq = f & 7;
            cp_async16(&Ws[buf][n * 36 + kq * 4],
                       W + (size_t)(nb + n) * 256 + k0 + kq * 4);
        }
        CP_COMMIT();
    };

    for (int i = tid; i < 16 * 128; i += 256)
        sbias[(i >> 7) * 132 + (i & 127)] = bias[nb + (i & 127)];

    load_tiles(0, 0);
    __syncthreads();

    wmma::fragment<wmma::accumulator, 16, 16, 8, float> acc[2][4];
#pragma unroll
    for (int i = 0; i < 2; i++)
#pragma unroll
        for (int j = 0; j < 4; j++)
            wmma::load_matrix_sync(acc[i][j], &sbias[wn * 64 + j * 16], 132,
                                   wmma::mem_row_major);

    int buf = 0;
    for (int it = 0; it < 8; it++) {
        if (it < 7) load_tiles((it + 1) * 32, buf ^ 1);
        if (it < 7) { CP_WAIT(1); } else { CP_WAIT(0); }
        __syncthreads();

#pragma unroll
        for (int kk = 0; kk < 32; kk += 8) {
            wmma::fragment<wmma::matrix_b, 16, 16, 8, wmma::precision::tf32,
                           wmma::col_major> bf[4];
#pragma unroll
            for (int j = 0; j < 4; j++)
                wmma::load_matrix_sync(bf[j], &Ws[buf][(wn * 64 + j * 16) * 36 + kk], 36);
            if constexpr (MODE != 2) {
                wmma::fragment<wmma::matrix_a, 16, 16, 8, wmma::precision::tf32,
                               wmma::col_major> af[2];
                wmma::load_matrix_sync(af[0], &As[buf][kk * 132 + wm * 32], 132);
                wmma::load_matrix_sync(af[1], &As[buf][kk * 132 + wm * 32 + 16], 132);
#pragma unroll
                for (int i = 0; i < 2; i++)
#pragma unroll
                    for (int j = 0; j < 4; j++)
                        wmma::mma_sync(acc[i][j], af[i], bf[j], acc[i][j]);
            } else {
                wmma::fragment<wmma::matrix_a, 16, 16, 8, wmma::precision::tf32,
                               wmma::row_major> af[2];
                wmma::load_matrix_sync(af[0], &As[buf][(wm * 32) * 36 + kk], 36);
                wmma::load_matrix_sync(af[1], &As[buf][(wm * 32 + 16) * 36 + kk], 36);
#pragma unroll
                for (int i = 0; i < 2; i++)
#pragma unroll
                    for (int j = 0; j < 4; j++)
                        wmma::mma_sync(acc[i][j], af[i], bf[j], acc[i][j]);
            }
        }
        __syncthreads();
        buf ^= 1;
    }

#pragma unroll
    for (int i = 0; i < 2; i++) {
#pragma unroll
        for (int j = 0; j < 4; j++) {
            const int mg = m0 + wm * 32 + i * 16;
            const int ng = nb + wn * 64 + j * 16;
            if constexpr (MODE == 1) {
#pragma unroll
                for (int t = 0; t < acc[i][j].num_elements; t++)
                    acc[i][j].x[t] = to_tf32(acc[i][j].x[t]);
            }
            float* dst;
            int ldc;
            if constexpr (MODE == 0) {
                dst = g_qk[z] + (size_t)(mg >> 6) * 16384 + (size_t)(ng >> 5) * 2048
                    + (size_t)(mg & 63) * 32 + (ng & 31);
                ldc = 32;
            } else if constexpr (MODE == 1) {
                dst = g_v + (size_t)z * 1048576 + (size_t)(ng >> 5) * 131072
                    + (size_t)mg * 32 + (ng & 31);
                ldc = 32;
            } else {
                dst = outp + (size_t)z * 1048576 + (size_t)mg * 256 + ng;
                ldc = 256;
            }
            wmma::store_matrix_sync(dst, acc[i][j], ldc, wmma::mem_row_major);
        }
    }
}

// ---------------------------------------------------------------------------
// Kernel 4: fused axial mixing. Block = (hgroup of 16, bh), 512 threads.
// Stage 1: R[16][2048] = attn_h[16 rows] @ v   (wmma, rounded into smem)
// Stage 2: warp h: r2 = (R[h] as [dv][w] col-maj) @ attn_w -> g_r2 (rounded)
// ---------------------------------------------------------------------------
__global__ void __launch_bounds__(512) axial_fused_kernel()
{
    __shared__ float R[16 * 2048];
    const int bh = blockIdx.y;
    const int hg = blockIdx.x;                 // 0..3
    const int wid = threadIdx.x >> 5;          // 0..15

    const float* Ah = g_attn[0] + (size_t)bh * 4096 + (size_t)(hg * 16) * 64;
    const float* Vg = g_v + (size_t)bh * 131072;

    // ---- stage 1: warp wid covers N chunk [wid*128, wid*128+128)
    {
        const int n0 = wid * 128;
        wmma::fragment<wmma::accumulator, 16, 16, 8, float> acc[8];
#pragma unroll
        for (int j = 0; j < 8; j++) wmma::fill_fragment(acc[j], 0.f);
#pragma unroll
        for (int k0 = 0; k0 < 64; k0 += 8) {
            wmma::fragment<wmma::matrix_a, 16, 16, 8, wmma::precision::tf32,
                           wmma::row_major> af;
            wmma::load_matrix_sync(af, Ah + k0, 64);
            wmma::fragment<wmma::matrix_b, 16, 16, 8, wmma::precision::tf32,
                           wmma::row_major> bf[8];
#pragma unroll
            for (int j = 0; j < 8; j++)
                wmma::load_matrix_sync(bf[j], Vg + (size_t)k0 * 2048 + n0 + j * 16, 2048);
#pragma unroll
            for (int j = 0; j < 8; j++)
                wmma::mma_sync(acc[j], af, bf[j], acc[j]);
        }
#pragma unroll
        for (int j = 0; j < 8; j++) {
#pragma unroll
            for (int t = 0; t < acc[j].num_elements; t++)
                acc[j].x[t] = to_tf32(acc[j].x[t]);
            wmma::store_matrix_sync(&R[n0 + j * 16], acc[j], 2048,
                                    wmma::mem_row_major);
        }
    }
    __syncthreads();

    // ---- stage 2: warp wid handles h = hg*16 + wid
    {
        const int h = hg * 16 + wid;
        const float* Ar = &R[wid * 2048];      // [w][dv] = col-major [dv][w] ld 32
        const float* Bg = g_attn[1] + (size_t)bh * 4096;
        float* dstb = g_r2 + (size_t)(bh >> 3) * 1048576
                    + (size_t)h * 64 * 256 + (bh & 7) * 32;

        wmma::fragment<wmma::accumulator, 16, 16, 8, float> acc[2][4];
#pragma unroll
        for (int i = 0; i < 2; i++)
#pragma unroll
            for (int j = 0; j < 4; j++) wmma::fill_fragment(acc[i][j], 0.f);

#pragma unroll
        for (int k0 = 0; k0 < 64; k0 += 8) {
            wmma::fragment<wmma::matrix_a, 16, 16, 8, wmma::precision::tf32,
                           wmma::col_major> af[2];
            wmma::load_matrix_sync(af[0], Ar + k0 * 32, 32);
            wmma::load_matrix_sync(af[1], Ar + k0 * 32 + 16, 32);
            wmma::fragment<wmma::matrix_b, 16, 16, 8, wmma::precision::tf32,
                           wmma::row_major> bf[4];
#pragma unroll
            for (int j = 0; j < 4; j++)
                wmma::load_matrix_sync(bf[j], Bg + (size_t)k0 * 64 + j * 16, 64);
#pragma unroll
            for (int i = 0; i < 2; i++)
#pragma unroll
                for (int j = 0; j < 4; j++)
                    wmma::mma_sync(acc[i][j], af[i], bf[j], acc[i][j]);
        }
#pragma unroll
        for (int i = 0; i < 2; i++)
#pragma unroll
            for (int j = 0; j < 4; j++) {
#pragma unroll
                for (int t = 0; t < acc[i][j].num_elements; t++)
                    acc[i][j].x[t] = to_tf32(acc[i][j].x[t]);
                wmma::store_matrix_sync(dstb + (size_t)(j * 16) * 256 + i * 16,
                                        acc[i][j], 256, wmma::mem_col_major);
            }
    }
}

// ---------------------------------------------------------------------------
// Launch
// ---------------------------------------------------------------------------
extern "C" void kernel_launch(void* const* d_in, const int* in_sizes, int n_in,
                              void* d_out, int out_size)
{
    const float* x       = (const float*)d_in[0];
    const float* dw_qh_w = (const float*)d_in[1];
    const float* dw_qh_b = (const float*)d_in[2];
    const float* fc_qh_w = (const float*)d_in[3];
    const float* fc_qh_b = (const float*)d_in[4];
    const float* dw_kh_w = (const float*)d_in[5];
    const float* dw_kh_b = (const float*)d_in[6];
    const float* fc_kh_w = (const float*)d_in[7];
    const float* fc_kh_b = (const float*)d_in[8];
    const float* Bh      = (const float*)d_in[9];
    const float* dw_v_w  = (const float*)d_in[10];
    const float* dw_v_b  = (const float*)d_in[11];
    const float* fc_v_w  = (const float*)d_in[12];
    const float* fc_v_b  = (const float*)d_in[13];
    const float* dw_qw_w = (const float*)d_in[14];
    const float* dw_qw_b = (const float*)d_in[15];
    const float* fc_qw_w = (const float*)d_in[16];
    const float* fc_qw_b = (const float*)d_in[17];
    const float* dw_kw_w = (const float*)d_in[18];
    const float* dw_kw_b = (const float*)d_in[19];
    const float* fc_kw_w = (const float*)d_in[20];
    const float* fc_kw_b = (const float*)d_in[21];
    const float* Bw      = (const float*)d_in[22];
    const float* fc_o_w  = (const float*)d_in[23];
    const float* fc_o_b  = (const float*)d_in[24];
    float* out = (float*)d_out;

    round_weights<<<dim3(64, 6), 1024>>>(fc_qh_w, fc_kh_w, fc_qw_w, fc_kw_w,
                                         fc_v_w, fc_o_w);

    conv_fused_kernel<<<dim3(Cc, Bb), 256>>>(
        x, dw_v_w, dw_v_b,
        dw_qh_w, dw_qh_b, dw_kh_w, dw_kh_b,
        dw_qw_w, dw_qw_b, dw_kw_w, dw_kw_b);

    wmma_gemm_kernel<0><<<dim3(8, 2, 4), 256>>>(
        fc_qh_b, fc_kh_b, fc_qw_b, fc_kw_b, nullptr);

    attn_kernel<<<dim3(32, 2), 256>>>(Bh, Bw);

    wmma_gemm_kernel<1><<<dim3(32, 2, Bb), 256>>>(
        fc_v_b, fc_v_b, fc_v_b, fc_v_b, nullptr);

    axial_fused_kernel<<<dim3(4, Bb * Hh), 512>>>();

    wmma_gemm_kernel<2><<<dim3(32, 2, Bb), 256>>>(
        fc_o_b, fc_o_b, fc_o_b, fc_o_b, out);
}

// round 7
// speedup vs baseline: 2.0061x; 1.0124x over previous
#include <cuda_runtime.h>
#include <mma.h>
#include <cstdint>

using namespace nvcuda;

#define Bb 16
#define Cc 256
#define Ss 64
#define Hh 8
#define Dd 32

// ---------------------------------------------------------------------------
// Scratch
// ---------------------------------------------------------------------------
__device__ float g_pool[4][Cc * Bb * Ss];              // [c][b*64+s]  (A^T, tf32)
__device__ float g_qk[4][Bb * Hh * Ss * Dd];           // [b][head][s][d] tf32
__device__ float g_attn[2][Bb * Hh * Ss * Ss];         // tf32
__device__ float g_vconv[(size_t)Bb * Cc * 4096];      // [b][c][hw] (A^T, tf32)
__device__ float g_v[(size_t)Bb * Hh * 4096 * 32];     // [b][head][hw][dv] tf32
__device__ float g_r2[(size_t)Bb * 4096 * Cc];         // [b][m=hw][k] tf32
__device__ float g_w[6][Cc * Cc];                      // pre-rounded tf32 weights

__device__ __forceinline__ float to_tf32(float x) {
    float r;
    asm("cvt.rna.tf32.f32 %0, %1;" : "=f"(r) : "f"(x));
    return r;
}
__device__ __forceinline__ void cp_async16(void* smem, const void* gmem) {
    uint32_t s = (uint32_t)__cvta_generic_to_shared(smem);
    asm volatile("cp.async.cg.shared.global [%0], [%1], 16;" :: "r"(s), "l"(gmem));
}
#define CP_COMMIT() asm volatile("cp.async.commit_group;" ::: "memory")
#define CP_WAIT(n)  asm volatile("cp.async.wait_group %0;" :: "n"(n) : "memory")

// ---------------------------------------------------------------------------
// Kernel 0: RNA-round the 6 fc weight matrices into g_w.
// ---------------------------------------------------------------------------
__global__ void __launch_bounds__(1024) round_weights(
    const float* __restrict__ w0, const float* __restrict__ w1,
    const float* __restrict__ w2, const float* __restrict__ w3,
    const float* __restrict__ w4, const float* __restrict__ w5)
{
    const float* src = (blockIdx.y == 0) ? w0 : (blockIdx.y == 1) ? w1
                     : (blockIdx.y == 2) ? w2 : (blockIdx.y == 3) ? w3
                     : (blockIdx.y == 4) ? w4 : w5;
    const int i = blockIdx.x * 1024 + threadIdx.x;
    g_w[blockIdx.y][i] = to_tf32(src[i]);
}

// ---------------------------------------------------------------------------
// Kernel 1: fused V dwconv + analytic pooled q/k branches. One read of x.
// ---------------------------------------------------------------------------
__global__ void __launch_bounds__(256) conv_fused_kernel(
    const float* __restrict__ x,
    const float* __restrict__ wv,  const float* __restrict__ bv,
    const float* __restrict__ wqh, const float* __restrict__ bqh,
    const float* __restrict__ wkh, const float* __restrict__ bkh,
    const float* __restrict__ wqw, const float* __restrict__ bqw,
    const float* __restrict__ wkw, const float* __restrict__ bkw)
{
    const int c = blockIdx.x;
    const int b = blockIdx.y;
    const int tid = threadIdx.x;

    __shared__ float xs[66][66];
    __shared__ float rowp[2][64], colp[4][64];
    __shared__ float T[64];
    __shared__ float wsm[4][9];
    __shared__ float bsm[4];

    for (int i = tid; i < 66 * 66; i += 256) (&xs[0][0])[i] = 0.f;
    __syncthreads();

    const float* xp = x + ((size_t)b * Cc + c) * 4096;
    for (int i = tid; i < 4096; i += 256) xs[(i >> 6) + 1][(i & 63) + 1] = xp[i];

    if (tid < 9)        wsm[0][tid]      = wqh[c * 9 + tid];
    else if (tid < 18)  wsm[1][tid - 9]  = wkh[c * 9 + tid - 9];
    else if (tid < 27)  wsm[2][tid - 18] = wqw[c * 9 + tid - 18];
    else if (tid < 36)  wsm[3][tid - 27] = wkw[c * 9 + tid - 27];
    if (tid == 36) bsm[0] = bqh[c];
    if (tid == 37) bsm[1] = bkh[c];
    if (tid == 38) bsm[2] = bqw[c];
    if (tid == 39) bsm[3] = bkw[c];

    float w[9];
#pragma unroll
    for (int i = 0; i < 9; i++) w[i] = wv[c * 9 + i];
    const float bias = bv[c];
    __syncthreads();

    const int wcol = tid & 63;
    const int hgrp = tid >> 6;
    float* op = g_vconv + ((size_t)b * Cc + c) * 4096;

    float colacc = 0.f;
    for (int k = 0; k < 16; k++) {
        const int h = hgrp * 16 + k;
        float s = bias;
#pragma unroll
        for (int dy = 0; dy < 3; dy++)
#pragma unroll
            for (int dx = 0; dx < 3; dx++)
                s += w[dy * 3 + dx] * xs[h + dy][wcol + dx];
        op[h * 64 + wcol] = to_tf32(s);
        const float v = xs[h + 1][wcol + 1];
        colacc += v;
        float rsum = v;
#pragma unroll
        for (int off = 16; off; off >>= 1)
            rsum += __shfl_down_sync(0xffffffffu, rsum, off);
        if ((tid & 31) == 0) rowp[(tid >> 5) & 1][h] = rsum;
    }
    colp[hgrp][wcol] = colacc;
    __syncthreads();
    if (tid < 64) T[tid] = colp[0][tid] + colp[1][tid] + colp[2][tid] + colp[3][tid];
    __syncthreads();

    if (tid < 64) {
        const int s = tid;
        float o0 = 0.f, o1 = 0.f, o2 = 0.f, o3 = 0.f;
#pragma unroll
        for (int d = 0; d < 3; d++) {
            const int r = s + d - 1;
            if (r >= 0 && r < 64) {
                const float Sv = rowp[0][r] + rowp[1][r];
                const float eL = xs[r + 1][1], eR = xs[r + 1][64];
                o0 += (wsm[0][d*3] + wsm[0][d*3+1] + wsm[0][d*3+2]) * Sv
                    - wsm[0][d*3] * eR - wsm[0][d*3+2] * eL;
                o1 += (wsm[1][d*3] + wsm[1][d*3+1] + wsm[1][d*3+2]) * Sv
                    - wsm[1][d*3] * eR - wsm[1][d*3+2] * eL;
                const float Tv = T[r];
                const float eT = xs[1][r + 1], eB = xs[64][r + 1];
                o2 += (wsm[2][d] + wsm[2][3+d] + wsm[2][6+d]) * Tv
                    - wsm[2][d] * eB - wsm[2][6+d] * eT;
                o3 += (wsm[3][d] + wsm[3][3+d] + wsm[3][6+d]) * Tv
                    - wsm[3][d] * eB - wsm[3][6+d] * eT;
            }
        }
        const float inv = 1.f / 64.f;
        const int mi = b * 64 + s;
        g_pool[0][c * 1024 + mi] = to_tf32(o0 * inv + bsm[0]);
        g_pool[1][c * 1024 + mi] = to_tf32(o1 * inv + bsm[1]);
        g_pool[2][c * 1024 + mi] = to_tf32(o2 * inv + bsm[2]);
        g_pool[3][c * 1024 + mi] = to_tf32(o3 * inv + bsm[3]);
    }
}

// ---------------------------------------------------------------------------
// Kernel 2: attention. Scores via wmma (q,k tf32-rounded in gmem), then
// softmax with thread=(row, quarter) layout. One bh per 256-thread block.
// ---------------------------------------------------------------------------
__global__ void __launch_bounds__(256) attn_kernel(
    const float* __restrict__ Bh, const float* __restrict__ Bw)
{
    const int bh = blockIdx.x;
    const int head = bh & 7;
    const int axis = blockIdx.y;
    const float scale = 0.17677669529663687f;

    const float* q = g_qk[axis == 0 ? 0 : 2] + (size_t)bh * 2048;
    const float* k = g_qk[axis == 0 ? 1 : 3] + (size_t)bh * 2048;
    const float* Bm = ((axis == 0) ? Bh : Bw) + head * 4096;
    float* o = g_attn[axis] + (size_t)bh * 4096;

    __shared__ float sc[64 * 68];

    // scores: 8 warps; warp w -> m-tile (w>>1), n-tiles 2*(w&1)..+1
    {
        const int wid = threadIdx.x >> 5;
        const int wm = wid >> 1;
        const int wn = wid & 1;
        wmma::fragment<wmma::accumulator, 16, 16, 8, float> acc[2];
        wmma::fill_fragment(acc[0], 0.f);
        wmma::fill_fragment(acc[1], 0.f);
#pragma unroll
        for (int d0 = 0; d0 < 32; d0 += 8) {
            wmma::fragment<wmma::matrix_a, 16, 16, 8, wmma::precision::tf32,
                           wmma::row_major> af;
            wmma::load_matrix_sync(af, q + (size_t)(wm * 16) * 32 + d0, 32);
            wmma::fragment<wmma::matrix_b, 16, 16, 8, wmma::precision::tf32,
                           wmma::col_major> bf[2];
            wmma::load_matrix_sync(bf[0], k + (size_t)(wn * 32) * 32 + d0, 32);
            wmma::load_matrix_sync(bf[1], k + (size_t)(wn * 32 + 16) * 32 + d0, 32);
            wmma::mma_sync(acc[0], af, bf[0], acc[0]);
            wmma::mma_sync(acc[1], af, bf[1], acc[1]);
        }
        wmma::store_matrix_sync(&sc[wm * 16 * 68 + wn * 32], acc[0], 68,
                                wmma::mem_row_major);
        wmma::store_matrix_sync(&sc[wm * 16 * 68 + wn * 32 + 16], acc[1], 68,
                                wmma::mem_row_major);
    }
    __syncthreads();

    // softmax: thread (i = tid>>2, qq = tid&3) handles j in [qq*16, qq*16+16)
    {
        const int i = threadIdx.x >> 2;
        const int qq = threadIdx.x & 3;
        float s[16];
        float mx = -1e30f;
#pragma unroll
        for (int jj = 0; jj < 16; jj += 4) {
            const int j = qq * 16 + jj;
            const float4 c4 = *reinterpret_cast<const float4*>(&sc[i * 68 + j]);
            const float4 b4 = *reinterpret_cast<const float4*>(&Bm[i * 64 + j]);
            s[jj + 0] = c4.x * scale + b4.x;
            s[jj + 1] = c4.y * scale + b4.y;
            s[jj + 2] = c4.z * scale + b4.z;
            s[jj + 3] = c4.w * scale + b4.w;
            mx = fmaxf(mx, fmaxf(fmaxf(s[jj], s[jj + 1]), fmaxf(s[jj + 2], s[jj + 3])));
        }
        mx = fmaxf(mx, __shfl_xor_sync(0xffffffffu, mx, 1));
        mx = fmaxf(mx, __shfl_xor_sync(0xffffffffu, mx, 2));
        float sum = 0.f;
#pragma unroll
        for (int jj = 0; jj < 16; jj++) { s[jj] = __expf(s[jj] - mx); sum += s[jj]; }
        sum += __shfl_xor_sync(0xffffffffu, sum, 1);
        sum += __shfl_xor_sync(0xffffffffu, sum, 2);
        const float r = 1.f / sum;
#pragma unroll
        for (int jj = 0; jj < 16; jj += 4) {
            const int j = qq * 16 + jj;
            float4 o4;
            o4.x = to_tf32(s[jj + 0] * r);
            o4.y = to_tf32(s[jj + 1] * r);
            o4.z = to_tf32(s[jj + 2] * r);
            o4.w = to_tf32(s[jj + 3] * r);
            *reinterpret_cast<float4*>(&o[i * 64 + j]) = o4;
        }
    }
}

// ---------------------------------------------------------------------------
// Unified tf32 wmma GEMM, cp.async double buffered.
// BM=128, BN=64, BK=32; 8 warps 4x2, warp tile 32x32 (low reg pressure ->
// true 2 CTAs/SM without spills).
// MODE 0: A=g_pool[z] col-major, W=g_w[z],  out->g_qk[z] (rounded)
// MODE 1: A=g_vconv[b] col-major, W=g_w[4], out->g_v (rounded)
// MODE 2: A=g_r2[b] row-major,    W=g_w[5], out->d_out (fp32)
// ---------------------------------------------------------------------------
template <int MODE>
__global__ void __launch_bounds__(256, 2) wmma_gemm_kernel(
    const float* __restrict__ b0, const float* __restrict__ b1,
    const float* __restrict__ b2, const float* __restrict__ b3,
    float* __restrict__ outp)
{
    __shared__ float As[2][4608];       // 32x132 (col-major) or 128x36 (row-major)
    __shared__ float Ws[2][64 * 36];    // [n][k]
    __shared__ float sbias[16 * 68];

    const int tid = threadIdx.x;
    const int wid = tid >> 5;
    const int wm = wid >> 1;            // 0..3
    const int wn = wid & 1;             // 0..1
    const int m0 = blockIdx.x * 128;
    const int nb = blockIdx.y * 64;
    const int z = blockIdx.z;

    const float* A;
    const float* bias;
    int ldA;
    const float* W = g_w[(MODE == 0) ? z : (MODE == 1) ? 4 : 5];
    if constexpr (MODE == 0) {
        A = g_pool[z]; ldA = 1024;
        bias = (z == 0) ? b0 : (z == 1) ? b1 : (z == 2) ? b2 : b3;
    } else if constexpr (MODE == 1) {
        A = g_vconv + (size_t)z * 1048576; ldA = 4096; bias = b0;
    } else {
        A = g_r2 + (size_t)z * 1048576; ldA = 256; bias = b0;
    }

    auto load_tiles = [&](int k0, int buf) {
#pragma unroll
        for (int i = 0; i < 4; i++) {
            const int f = tid + 256 * i;
            if constexpr (MODE != 2) {
                const int k = f >> 5, mq = f & 31;
                cp_async16(&As[buf][k * 132 + mq * 4],
                           A + (size_t)(k0 + k) * ldA + m0 + mq * 4);
            } else {
                const int m = f >> 3, kq = f & 7;
                cp_async16(&As[buf][m * 36 + kq * 4],
                           A + (size_t)(m0 + m) * 256 + k0 + kq * 4);
            }
            if (i < 2) {
                const int n = f >> 3, kq = f & 7;
                cp_async16(&Ws[buf][n * 36 + kq * 4],
                           W + (size_t)(nb + n) * 256 + k0 + kq * 4);
            }
        }
        CP_COMMIT();
    };

    for (int i = tid; i < 16 * 64; i += 256)
        sbias[(i >> 6) * 68 + (i & 63)] = bias[nb + (i & 63)];

    load_tiles(0, 0);
    __syncthreads();

    wmma::fragment<wmma::accumulator, 16, 16, 8, float> acc[2][2];
#pragma unroll
    for (int i = 0; i < 2; i++)
#pragma unroll
        for (int j = 0; j < 2; j++)
            wmma::load_matrix_sync(acc[i][j], &sbias[wn * 32 + j * 16], 68,
                                   wmma::mem_row_major);

    int buf = 0;
    for (int it = 0; it < 8; it++) {
        if (it < 7) load_tiles((it + 1) * 32, buf ^ 1);
        if (it < 7) { CP_WAIT(1); } else { CP_WAIT(0); }
        __syncthreads();

#pragma unroll
        for (int kk = 0; kk < 32; kk += 8) {
            wmma::fragment<wmma::matrix_b, 16, 16, 8, wmma::precision::tf32,
                           wmma::col_major> bf[2];
            wmma::load_matrix_sync(bf[0], &Ws[buf][(wn * 32) * 36 + kk], 36);
            wmma::load_matrix_sync(bf[1], &Ws[buf][(wn * 32 + 16) * 36 + kk], 36);
            if constexpr (MODE != 2) {
                wmma::fragment<wmma::matrix_a, 16, 16, 8, wmma::precision::tf32,
                               wmma::col_major> af[2];
                wmma::load_matrix_sync(af[0], &As[buf][kk * 132 + wm * 32], 132);
                wmma::load_matrix_sync(af[1], &As[buf][kk * 132 + wm * 32 + 16], 132);
#pragma unroll
                for (int i = 0; i < 2; i++)
#pragma unroll
                    for (int j = 0; j < 2; j++)
                        wmma::mma_sync(acc[i][j], af[i], bf[j], acc[i][j]);
            } else {
                wmma::fragment<wmma::matrix_a, 16, 16, 8, wmma::precision::tf32,
                               wmma::row_major> af[2];
                wmma::load_matrix_sync(af[0], &As[buf][(wm * 32) * 36 + kk], 36);
                wmma::load_matrix_sync(af[1], &As[buf][(wm * 32 + 16) * 36 + kk], 36);
#pragma unroll
                for (int i = 0; i < 2; i++)
#pragma unroll
                    for (int j = 0; j < 2; j++)
                        wmma::mma_sync(acc[i][j], af[i], bf[j], acc[i][j]);
            }
        }
        __syncthreads();
        buf ^= 1;
    }

#pragma unroll
    for (int i = 0; i < 2; i++) {
#pragma unroll
        for (int j = 0; j < 2; j++) {
            const int mg = m0 + wm * 32 + i * 16;
            const int ng = nb + wn * 32 + j * 16;
            if constexpr (MODE != 2) {
#pragma unroll
                for (int t = 0; t < acc[i][j].num_elements; t++)
                    acc[i][j].x[t] = to_tf32(acc[i][j].x[t]);
            }
            float* dst;
            int ldc;
            if constexpr (MODE == 0) {
                dst = g_qk[z] + (size_t)(mg >> 6) * 16384 + (size_t)(ng >> 5) * 2048
                    + (size_t)(mg & 63) * 32 + (ng & 31);
                ldc = 32;
            } else if constexpr (MODE == 1) {
                dst = g_v + (size_t)z * 1048576 + (size_t)(ng >> 5) * 131072
                    + (size_t)mg * 32 + (ng & 31);
                ldc = 32;
            } else {
                dst = outp + (size_t)z * 1048576 + (size_t)mg * 256 + ng;
                ldc = 256;
            }
            wmma::store_matrix_sync(dst, acc[i][j], ldc, wmma::mem_row_major);
        }
    }
}

// ---------------------------------------------------------------------------
// Kernel 4: fused axial mixing. Block = (hgroup of 16, bh), 512 threads.
// ---------------------------------------------------------------------------
__global__ void __launch_bounds__(512) axial_fused_kernel()
{
    __shared__ float R[16 * 2048];
    const int bh = blockIdx.y;
    const int hg = blockIdx.x;
    const int wid = threadIdx.x >> 5;

    const float* Ah = g_attn[0] + (size_t)bh * 4096 + (size_t)(hg * 16) * 64;
    const float* Vg = g_v + (size_t)bh * 131072;

    {
        const int n0 = wid * 128;
        wmma::fragment<wmma::accumulator, 16, 16, 8, float> acc[8];
#pragma unroll
        for (int j = 0; j < 8; j++) wmma::fill_fragment(acc[j], 0.f);
#pragma unroll
        for (int k0 = 0; k0 < 64; k0 += 8) {
            wmma::fragment<wmma::matrix_a, 16, 16, 8, wmma::precision::tf32,
                           wmma::row_major> af;
            wmma::load_matrix_sync(af, Ah + k0, 64);
            wmma::fragment<wmma::matrix_b, 16, 16, 8, wmma::precision::tf32,
                           wmma::row_major> bf[8];
#pragma unroll
            for (int j = 0; j < 8; j++)
                wmma::load_matrix_sync(bf[j], Vg + (size_t)k0 * 2048 + n0 + j * 16, 2048);
#pragma unroll
            for (int j = 0; j < 8; j++)
                wmma::mma_sync(acc[j], af, bf[j], acc[j]);
        }
#pragma unroll
        for (int j = 0; j < 8; j++) {
#pragma unroll
            for (int t = 0; t < acc[j].num_elements; t++)
                acc[j].x[t] = to_tf32(acc[j].x[t]);
            wmma::store_matrix_sync(&R[n0 + j * 16], acc[j], 2048,
                                    wmma::mem_row_major);
        }
    }
    __syncthreads();

    {
        const int h = hg * 16 + wid;
        const float* Ar = &R[wid * 2048];
        const float* Bg = g_attn[1] + (size_t)bh * 4096;
        float* dstb = g_r2 + (size_t)(bh >> 3) * 1048576
                    + (size_t)h * 64 * 256 + (bh & 7) * 32;

        wmma::fragment<wmma::accumulator, 16, 16, 8, float> acc[2][4];
#pragma unroll
        for (int i = 0; i < 2; i++)
#pragma unroll
            for (int j = 0; j < 4; j++) wmma::fill_fragment(acc[i][j], 0.f);

#pragma unroll
        for (int k0 = 0; k0 < 64; k0 += 8) {
            wmma::fragment<wmma::matrix_a, 16, 16, 8, wmma::precision::tf32,
                           wmma::col_major> af[2];
            wmma::load_matrix_sync(af[0], Ar + k0 * 32, 32);
            wmma::load_matrix_sync(af[1], Ar + k0 * 32 + 16, 32);
            wmma::fragment<wmma::matrix_b, 16, 16, 8, wmma::precision::tf32,
                           wmma::row_major> bf[4];
#pragma unroll
            for (int j = 0; j < 4; j++)
                wmma::load_matrix_sync(bf[j], Bg + (size_t)k0 * 64 + j * 16, 64);
#pragma unroll
            for (int i = 0; i < 2; i++)
#pragma unroll
                for (int j = 0; j < 4; j++)
                    wmma::mma_sync(acc[i][j], af[i], bf[j], acc[i][j]);
        }
#pragma unroll
        for (int i = 0; i < 2; i++)
#pragma unroll
            for (int j = 0; j < 4; j++) {
#pragma unroll
                for (int t = 0; t < acc[i][j].num_elements; t++)
                    acc[i][j].x[t] = to_tf32(acc[i][j].x[t]);
                wmma::store_matrix_sync(dstb + (size_t)(j * 16) * 256 + i * 16,
                                        acc[i][j], 256, wmma::mem_col_major);
            }
    }
}

// ---------------------------------------------------------------------------
// Launch
// ---------------------------------------------------------------------------
extern "C" void kernel_launch(void* const* d_in, const int* in_sizes, int n_in,
                              void* d_out, int out_size)
{
    const float* x       = (const float*)d_in[0];
    const float* dw_qh_w = (const float*)d_in[1];
    const float* dw_qh_b = (const float*)d_in[2];
    const float* fc_qh_w = (const float*)d_in[3];
    const float* fc_qh_b = (const float*)d_in[4];
    const float* dw_kh_w = (const float*)d_in[5];
    const float* dw_kh_b = (const float*)d_in[6];
    const float* fc_kh_w = (const float*)d_in[7];
    const float* fc_kh_b = (const float*)d_in[8];
    const float* Bh      = (const float*)d_in[9];
    const float* dw_v_w  = (const float*)d_in[10];
    const float* dw_v_b  = (const float*)d_in[11];
    const float* fc_v_w  = (const float*)d_in[12];
    const float* fc_v_b  = (const float*)d_in[13];
    const float* dw_qw_w = (const float*)d_in[14];
    const float* dw_qw_b = (const float*)d_in[15];
    const float* fc_qw_w = (const float*)d_in[16];
    const float* fc_qw_b = (const float*)d_in[17];
    const float* dw_kw_w = (const float*)d_in[18];
    const float* dw_kw_b = (const float*)d_in[19];
    const float* fc_kw_w = (const float*)d_in[20];
    const float* fc_kw_b = (const float*)d_in[21];
    const float* Bw      = (const float*)d_in[22];
    const float* fc_o_w  = (const float*)d_in[23];
    const float* fc_o_b  = (const float*)d_in[24];
    float* out = (float*)d_out;

    round_weights<<<dim3(64, 6), 1024>>>(fc_qh_w, fc_kh_w, fc_qw_w, fc_kw_w,
                                         fc_v_w, fc_o_w);

    conv_fused_kernel<<<dim3(Cc, Bb), 256>>>(
        x, dw_v_w, dw_v_b,
        dw_qh_w, dw_qh_b, dw_kh_w, dw_kh_b,
        dw_qw_w, dw_qw_b, dw_kw_w, dw_kw_b);

    wmma_gemm_kernel<0><<<dim3(8, 4, 4), 256>>>(
        fc_qh_b, fc_kh_b, fc_qw_b, fc_kw_b, nullptr);

    attn_kernel<<<dim3(Bb * Hh, 2), 256>>>(Bh, Bw);

    wmma_gemm_kernel<1><<<dim3(32, 4, Bb), 256>>>(
        fc_v_b, fc_v_b, fc_v_b, fc_v_b, nullptr);

    axial_fused_kernel<<<dim3(4, Bb * Hh), 512>>>();

    wmma_gemm_kernel<2><<<dim3(32, 4, Bb), 256>>>(
        fc_o_b, fc_o_b, fc_o_b, fc_o_b, out);
}

// round 8
// speedup vs baseline: 2.0981x; 1.0459x over previous
#include <cuda_runtime.h>
#include <mma.h>
#include <cstdint>

using namespace nvcuda;

#define Bb 16
#define Cc 256
#define Ss 64
#define Hh 8
#define Dd 32

// ---------------------------------------------------------------------------
// Scratch
// ---------------------------------------------------------------------------
__device__ float g_pool[4][Cc * Bb * Ss];              // [c][b*64+s]  (A^T, tf32)
__device__ float g_qk[4][Bb * Hh * Ss * Dd];           // [b][head][s][d] tf32
__device__ float g_attn[2][Bb * Hh * Ss * Ss];         // tf32
__device__ float g_vconv[(size_t)Bb * Cc * 4096];      // [b][c][hw] (A^T, tf32)
__device__ float g_v[(size_t)Bb * Hh * 4096 * 32];     // [b][head][hw][dv] tf32
__device__ float g_r2[(size_t)Bb * 4096 * Cc];         // [b][m=hw][k] tf32
__device__ float g_w[6][Cc * Cc];                      // pre-rounded tf32 weights

__device__ __forceinline__ float to_tf32(float x) {
    float r;
    asm("cvt.rna.tf32.f32 %0, %1;" : "=f"(r) : "f"(x));
    return r;
}
__device__ __forceinline__ void cp_async16(void* smem, const void* gmem) {
    uint32_t s = (uint32_t)__cvta_generic_to_shared(smem);
    asm volatile("cp.async.cg.shared.global [%0], [%1], 16;" :: "r"(s), "l"(gmem));
}
#define CP_COMMIT() asm volatile("cp.async.commit_group;" ::: "memory")
#define CP_WAIT(n)  asm volatile("cp.async.wait_group %0;" :: "n"(n) : "memory")

// ---------------------------------------------------------------------------
// Kernel 0: RNA-round the 6 fc weight matrices into g_w.
// ---------------------------------------------------------------------------
__global__ void __launch_bounds__(1024) round_weights(
    const float* __restrict__ w0, const float* __restrict__ w1,
    const float* __restrict__ w2, const float* __restrict__ w3,
    const float* __restrict__ w4, const float* __restrict__ w5)
{
    const float* src = (blockIdx.y == 0) ? w0 : (blockIdx.y == 1) ? w1
                     : (blockIdx.y == 2) ? w2 : (blockIdx.y == 3) ? w3
                     : (blockIdx.y == 4) ? w4 : w5;
    const int i = blockIdx.x * 1024 + threadIdx.x;
    g_w[blockIdx.y][i] = to_tf32(src[i]);
}

// ---------------------------------------------------------------------------
// Kernel 1: fused V dwconv + analytic pooled q/k branches. One read of x.
// ---------------------------------------------------------------------------
__global__ void __launch_bounds__(256) conv_fused_kernel(
    const float* __restrict__ x,
    const float* __restrict__ wv,  const float* __restrict__ bv,
    const float* __restrict__ wqh, const float* __restrict__ bqh,
    const float* __restrict__ wkh, const float* __restrict__ bkh,
    const float* __restrict__ wqw, const float* __restrict__ bqw,
    const float* __restrict__ wkw, const float* __restrict__ bkw)
{
    const int c = blockIdx.x;
    const int b = blockIdx.y;
    const int tid = threadIdx.x;

    __shared__ float xs[66][66];
    __shared__ float rowp[2][64], colp[4][64];
    __shared__ float T[64];
    __shared__ float wsm[4][9];
    __shared__ float bsm[4];

    for (int i = tid; i < 66 * 66; i += 256) (&xs[0][0])[i] = 0.f;
    __syncthreads();

    const float* xp = x + ((size_t)b * Cc + c) * 4096;
    for (int i = tid; i < 4096; i += 256) xs[(i >> 6) + 1][(i & 63) + 1] = xp[i];

    if (tid < 9)        wsm[0][tid]      = wqh[c * 9 + tid];
    else if (tid < 18)  wsm[1][tid - 9]  = wkh[c * 9 + tid - 9];
    else if (tid < 27)  wsm[2][tid - 18] = wqw[c * 9 + tid - 18];
    else if (tid < 36)  wsm[3][tid - 27] = wkw[c * 9 + tid - 27];
    if (tid == 36) bsm[0] = bqh[c];
    if (tid == 37) bsm[1] = bkh[c];
    if (tid == 38) bsm[2] = bqw[c];
    if (tid == 39) bsm[3] = bkw[c];

    float w[9];
#pragma unroll
    for (int i = 0; i < 9; i++) w[i] = wv[c * 9 + i];
    const float bias = bv[c];
    __syncthreads();

    const int wcol = tid & 63;
    const int hgrp = tid >> 6;
    float* op = g_vconv + ((size_t)b * Cc + c) * 4096;

    float colacc = 0.f;
    for (int k = 0; k < 16; k++) {
        const int h = hgrp * 16 + k;
        float s = bias;
#pragma unroll
        for (int dy = 0; dy < 3; dy++)
#pragma unroll
            for (int dx = 0; dx < 3; dx++)
                s += w[dy * 3 + dx] * xs[h + dy][wcol + dx];
        op[h * 64 + wcol] = to_tf32(s);
        const float v = xs[h + 1][wcol + 1];
        colacc += v;
        float rsum = v;
#pragma unroll
        for (int off = 16; off; off >>= 1)
            rsum += __shfl_down_sync(0xffffffffu, rsum, off);
        if ((tid & 31) == 0) rowp[(tid >> 5) & 1][h] = rsum;
    }
    colp[hgrp][wcol] = colacc;
    __syncthreads();
    if (tid < 64) T[tid] = colp[0][tid] + colp[1][tid] + colp[2][tid] + colp[3][tid];
    __syncthreads();

    if (tid < 64) {
        const int s = tid;
        float o0 = 0.f, o1 = 0.f, o2 = 0.f, o3 = 0.f;
#pragma unroll
        for (int d = 0; d < 3; d++) {
            const int r = s + d - 1;
            if (r >= 0 && r < 64) {
                const float Sv = rowp[0][r] + rowp[1][r];
                const float eL = xs[r + 1][1], eR = xs[r + 1][64];
                o0 += (wsm[0][d*3] + wsm[0][d*3+1] + wsm[0][d*3+2]) * Sv
                    - wsm[0][d*3] * eR - wsm[0][d*3+2] * eL;
                o1 += (wsm[1][d*3] + wsm[1][d*3+1] + wsm[1][d*3+2]) * Sv
                    - wsm[1][d*3] * eR - wsm[1][d*3+2] * eL;
                const float Tv = T[r];
                const float eT = xs[1][r + 1], eB = xs[64][r + 1];
                o2 += (wsm[2][d] + wsm[2][3+d] + wsm[2][6+d]) * Tv
                    - wsm[2][d] * eB - wsm[2][6+d] * eT;
                o3 += (wsm[3][d] + wsm[3][3+d] + wsm[3][6+d]) * Tv
                    - wsm[3][d] * eB - wsm[3][6+d] * eT;
            }
        }
        const float inv = 1.f / 64.f;
        const int mi = b * 64 + s;
        g_pool[0][c * 1024 + mi] = to_tf32(o0 * inv + bsm[0]);
        g_pool[1][c * 1024 + mi] = to_tf32(o1 * inv + bsm[1]);
        g_pool[2][c * 1024 + mi] = to_tf32(o2 * inv + bsm[2]);
        g_pool[3][c * 1024 + mi] = to_tf32(o3 * inv + bsm[3]);
    }
}

// ---------------------------------------------------------------------------
// Kernel 2: attention. Scores via wmma, low-register softmax.
// ---------------------------------------------------------------------------
__global__ void __launch_bounds__(256) attn_kernel(
    const float* __restrict__ Bh, const float* __restrict__ Bw)
{
    const int bh = blockIdx.x;
    const int head = bh & 7;
    const int axis = blockIdx.y;
    const float scale = 0.17677669529663687f;

    const float* q = g_qk[axis == 0 ? 0 : 2] + (size_t)bh * 2048;
    const float* k = g_qk[axis == 0 ? 1 : 3] + (size_t)bh * 2048;
    const float* Bm = ((axis == 0) ? Bh : Bw) + head * 4096;
    float* o = g_attn[axis] + (size_t)bh * 4096;

    __shared__ float sc[64 * 68];

    {
        const int wid = threadIdx.x >> 5;
        const int wm = wid >> 1;
        const int wn = wid & 1;
        wmma::fragment<wmma::accumulator, 16, 16, 8, float> acc[2];
        wmma::fill_fragment(acc[0], 0.f);
        wmma::fill_fragment(acc[1], 0.f);
#pragma unroll
        for (int d0 = 0; d0 < 32; d0 += 8) {
            wmma::fragment<wmma::matrix_a, 16, 16, 8, wmma::precision::tf32,
                           wmma::row_major> af;
            wmma::load_matrix_sync(af, q + (size_t)(wm * 16) * 32 + d0, 32);
            wmma::fragment<wmma::matrix_b, 16, 16, 8, wmma::precision::tf32,
                           wmma::col_major> bf[2];
            wmma::load_matrix_sync(bf[0], k + (size_t)(wn * 32) * 32 + d0, 32);
            wmma::load_matrix_sync(bf[1], k + (size_t)(wn * 32 + 16) * 32 + d0, 32);
            wmma::mma_sync(acc[0], af, bf[0], acc[0]);
            wmma::mma_sync(acc[1], af, bf[1], acc[1]);
        }
        wmma::store_matrix_sync(&sc[wm * 16 * 68 + wn * 32], acc[0], 68,
                                wmma::mem_row_major);
        wmma::store_matrix_sync(&sc[wm * 16 * 68 + wn * 32 + 16], acc[1], 68,
                                wmma::mem_row_major);
    }
    __syncthreads();

    {
        const int i = threadIdx.x >> 2;
        const int qq = threadIdx.x & 3;
        float s[16];
        float mx = -1e30f;
#pragma unroll
        for (int jj = 0; jj < 16; jj += 4) {
            const int j = qq * 16 + jj;
            const float4 c4 = *reinterpret_cast<const float4*>(&sc[i * 68 + j]);
            const float4 b4 = *reinterpret_cast<const float4*>(&Bm[i * 64 + j]);
            s[jj + 0] = c4.x * scale + b4.x;
            s[jj + 1] = c4.y * scale + b4.y;
            s[jj + 2] = c4.z * scale + b4.z;
            s[jj + 3] = c4.w * scale + b4.w;
            mx = fmaxf(mx, fmaxf(fmaxf(s[jj], s[jj + 1]), fmaxf(s[jj + 2], s[jj + 3])));
        }
        mx = fmaxf(mx, __shfl_xor_sync(0xffffffffu, mx, 1));
        mx = fmaxf(mx, __shfl_xor_sync(0xffffffffu, mx, 2));
        float sum = 0.f;
#pragma unroll
        for (int jj = 0; jj < 16; jj++) { s[jj] = __expf(s[jj] - mx); sum += s[jj]; }
        sum += __shfl_xor_sync(0xffffffffu, sum, 1);
        sum += __shfl_xor_sync(0xffffffffu, sum, 2);
        const float r = 1.f / sum;
#pragma unroll
        for (int jj = 0; jj < 16; jj += 4) {
            const int j = qq * 16 + jj;
            float4 o4;
            o4.x = to_tf32(s[jj + 0] * r);
            o4.y = to_tf32(s[jj + 1] * r);
            o4.z = to_tf32(s[jj + 2] * r);
            o4.w = to_tf32(s[jj + 3] * r);
            *reinterpret_cast<float4*>(&o[i * 64 + j]) = o4;
        }
    }
}

// ---------------------------------------------------------------------------
// Unified tf32 wmma GEMM, cp.async double buffered.
// BM=64, BN=128, BK=32; 128 threads = 4 warps (2x2), warp tile 32x64.
// Small CTA -> 3 CTAs/SM (12 warps) with no register cap, no spills.
// MODE 0: A=g_pool[z] col-major, W=g_w[z],  out->g_qk[z] (rounded)
// MODE 1: A=g_vconv[b] col-major, W=g_w[4], out->g_v (rounded)
// MODE 2: A=g_r2[b] row-major,    W=g_w[5], out->d_out (fp32)
// ---------------------------------------------------------------------------
template <int MODE>
__global__ void __launch_bounds__(128, 3) wmma_gemm_kernel(
    const float* __restrict__ b0, const float* __restrict__ b1,
    const float* __restrict__ b2, const float* __restrict__ b3,
    float* __restrict__ outp)
{
    __shared__ float As[2][2368];       // 32x68 (col-major) or 64x36 (row-major)
    __shared__ float Ws[2][128 * 36];   // [n][k]
    __shared__ float sbias[16 * 132];

    const int tid = threadIdx.x;
    const int wid = tid >> 5;
    const int wm = wid >> 1;            // 0..1
    const int wn = wid & 1;             // 0..1
    const int m0 = blockIdx.x * 64;
    const int nb = blockIdx.y * 128;
    const int z = blockIdx.z;

    const float* A;
    const float* bias;
    int ldA;
    const float* W = g_w[(MODE == 0) ? z : (MODE == 1) ? 4 : 5];
    if constexpr (MODE == 0) {
        A = g_pool[z]; ldA = 1024;
        bias = (z == 0) ? b0 : (z == 1) ? b1 : (z == 2) ? b2 : b3;
    } else if constexpr (MODE == 1) {
        A = g_vconv + (size_t)z * 1048576; ldA = 4096; bias = b0;
    } else {
        A = g_r2 + (size_t)z * 1048576; ldA = 256; bias = b0;
    }

    auto load_tiles = [&](int k0, int buf) {
#pragma unroll
        for (int i = 0; i < 4; i++) {
            const int f = tid + 128 * i;            // 0..511
            if constexpr (MODE != 2) {
                const int k = f >> 4, mq = f & 15;  // A col-major 32k x 64m
                cp_async16(&As[buf][k * 68 + mq * 4],
                           A + (size_t)(k0 + k) * ldA + m0 + mq * 4);
            } else {
                const int m = f >> 3, kq = f & 7;   // A row-major 64m x 32k
                cp_async16(&As[buf][m * 36 + kq * 4],
                           A + (size_t)(m0 + m) * 256 + k0 + kq * 4);
            }
        }
#pragma unroll
        for (int i = 0; i < 8; i++) {
            const int f = tid + 128 * i;            // 0..1023
            const int n = f >> 3, kq = f & 7;
            cp_async16(&Ws[buf][n * 36 + kq * 4],
                       W + (size_t)(nb + n) * 256 + k0 + kq * 4);
        }
        CP_COMMIT();
    };

    for (int i = tid; i < 16 * 128; i += 128)
        sbias[(i >> 7) * 132 + (i & 127)] = bias[nb + (i & 127)];

    load_tiles(0, 0);
    __syncthreads();

    wmma::fragment<wmma::accumulator, 16, 16, 8, float> acc[2][4];
#pragma unroll
    for (int i = 0; i < 2; i++)
#pragma unroll
        for (int j = 0; j < 4; j++)
            wmma::load_matrix_sync(acc[i][j], &sbias[wn * 64 + j * 16], 132,
                                   wmma::mem_row_major);

    int buf = 0;
    for (int it = 0; it < 8; it++) {
        if (it < 7) load_tiles((it + 1) * 32, buf ^ 1);
        if (it < 7) { CP_WAIT(1); } else { CP_WAIT(0); }
        __syncthreads();

#pragma unroll
        for (int kk = 0; kk < 32; kk += 8) {
            wmma::fragment<wmma::matrix_b, 16, 16, 8, wmma::precision::tf32,
                           wmma::col_major> bf[4];
#pragma unroll
            for (int j = 0; j < 4; j++)
                wmma::load_matrix_sync(bf[j], &Ws[buf][(wn * 64 + j * 16) * 36 + kk], 36);
            if constexpr (MODE != 2) {
                wmma::fragment<wmma::matrix_a, 16, 16, 8, wmma::precision::tf32,
                               wmma::col_major> af[2];
                wmma::load_matrix_sync(af[0], &As[buf][kk * 68 + wm * 32], 68);
                wmma::load_matrix_sync(af[1], &As[buf][kk * 68 + wm * 32 + 16], 68);
#pragma unroll
                for (int i = 0; i < 2; i++)
#pragma unroll
                    for (int j = 0; j < 4; j++)
                        wmma::mma_sync(acc[i][j], af[i], bf[j], acc[i][j]);
            } else {
                wmma::fragment<wmma::matrix_a, 16, 16, 8, wmma::precision::tf32,
                               wmma::row_major> af[2];
                wmma::load_matrix_sync(af[0], &As[buf][(wm * 32) * 36 + kk], 36);
                wmma::load_matrix_sync(af[1], &As[buf][(wm * 32 + 16) * 36 + kk], 36);
#pragma unroll
                for (int i = 0; i < 2; i++)
#pragma unroll
                    for (int j = 0; j < 4; j++)
                        wmma::mma_sync(acc[i][j], af[i], bf[j], acc[i][j]);
            }
        }
        __syncthreads();
        buf ^= 1;
    }

#pragma unroll
    for (int i = 0; i < 2; i++) {
#pragma unroll
        for (int j = 0; j < 4; j++) {
            const int mg = m0 + wm * 32 + i * 16;
            const int ng = nb + wn * 64 + j * 16;
            if constexpr (MODE != 2) {
#pragma unroll
                for (int t = 0; t < acc[i][j].num_elements; t++)
                    acc[i][j].x[t] = to_tf32(acc[i][j].x[t]);
            }
            float* dst;
            int ldc;
            if constexpr (MODE == 0) {
                dst = g_qk[z] + (size_t)(mg >> 6) * 16384 + (size_t)(ng >> 5) * 2048
                    + (size_t)(mg & 63) * 32 + (ng & 31);
                ldc = 32;
            } else if constexpr (MODE == 1) {
                dst = g_v + (size_t)z * 1048576 + (size_t)(ng >> 5) * 131072
                    + (size_t)mg * 32 + (ng & 31);
                ldc = 32;
            } else {
                dst = outp + (size_t)z * 1048576 + (size_t)mg * 256 + ng;
                ldc = 256;
            }
            wmma::store_matrix_sync(dst, acc[i][j], ldc, wmma::mem_row_major);
        }
    }
}

// ---------------------------------------------------------------------------
// Kernel 4: fused axial mixing. Block = (hgroup of 16, bh), 512 threads.
// ---------------------------------------------------------------------------
__global__ void __launch_bounds__(512) axial_fused_kernel()
{
    __shared__ float R[16 * 2048];
    const int bh = blockIdx.y;
    const int hg = blockIdx.x;
    const int wid = threadIdx.x >> 5;

    const float* Ah = g_attn[0] + (size_t)bh * 4096 + (size_t)(hg * 16) * 64;
    const float* Vg = g_v + (size_t)bh * 131072;

    {
        const int n0 = wid * 128;
        wmma::fragment<wmma::accumulator, 16, 16, 8, float> acc[8];
#pragma unroll
        for (int j = 0; j < 8; j++) wmma::fill_fragment(acc[j], 0.f);
#pragma unroll
        for (int k0 = 0; k0 < 64; k0 += 8) {
            wmma::fragment<wmma::matrix_a, 16, 16, 8, wmma::precision::tf32,
                           wmma::row_major> af;
            wmma::load_matrix_sync(af, Ah + k0, 64);
            wmma::fragment<wmma::matrix_b, 16, 16, 8, wmma::precision::tf32,
                           wmma::row_major> bf[8];
#pragma unroll
            for (int j = 0; j < 8; j++)
                wmma::load_matrix_sync(bf[j], Vg + (size_t)k0 * 2048 + n0 + j * 16, 2048);
#pragma unroll
            for (int j = 0; j < 8; j++)
                wmma::mma_sync(acc[j], af, bf[j], acc[j]);
        }
#pragma unroll
        for (int j = 0; j < 8; j++) {
#pragma unroll
            for (int t = 0; t < acc[j].num_elements; t++)
                acc[j].x[t] = to_tf32(acc[j].x[t]);
            wmma::store_matrix_sync(&R[n0 + j * 16], acc[j], 2048,
                                    wmma::mem_row_major);
        }
    }
    __syncthreads();

    {
        const int h = hg * 16 + wid;
        const float* Ar = &R[wid * 2048];
        const float* Bg = g_attn[1] + (size_t)bh * 4096;
        float* dstb = g_r2 + (size_t)(bh >> 3) * 1048576
                    + (size_t)h * 64 * 256 + (bh & 7) * 32;

        wmma::fragment<wmma::accumulator, 16, 16, 8, float> acc[2][4];
#pragma unroll
        for (int i = 0; i < 2; i++)
#pragma unroll
            for (int j = 0; j < 4; j++) wmma::fill_fragment(acc[i][j], 0.f);

#pragma unroll
        for (int k0 = 0; k0 < 64; k0 += 8) {
            wmma::fragment<wmma::matrix_a, 16, 16, 8, wmma::precision::tf32,
                           wmma::col_major> af[2];
            wmma::load_matrix_sync(af[0], Ar + k0 * 32, 32);
            wmma::load_matrix_sync(af[1], Ar + k0 * 32 + 16, 32);
            wmma::fragment<wmma::matrix_b, 16, 16, 8, wmma::precision::tf32,
                           wmma::row_major> bf[4];
#pragma unroll
            for (int j = 0; j < 4; j++)
                wmma::load_matrix_sync(bf[j], Bg + (size_t)k0 * 64 + j * 16, 64);
#pragma unroll
            for (int i = 0; i < 2; i++)
#pragma unroll
                for (int j = 0; j < 4; j++)
                    wmma::mma_sync(acc[i][j], af[i], bf[j], acc[i][j]);
        }
#pragma unroll
        for (int i = 0; i < 2; i++)
#pragma unroll
            for (int j = 0; j < 4; j++) {
#pragma unroll
                for (int t = 0; t < acc[i][j].num_elements; t++)
                    acc[i][j].x[t] = to_tf32(acc[i][j].x[t]);
                wmma::store_matrix_sync(dstb + (size_t)(j * 16) * 256 + i * 16,
                                        acc[i][j], 256, wmma::mem_col_major);
            }
    }
}

// ---------------------------------------------------------------------------
// Launch
// ---------------------------------------------------------------------------
extern "C" void kernel_launch(void* const* d_in, const int* in_sizes, int n_in,
                              void* d_out, int out_size)
{
    const float* x       = (const float*)d_in[0];
    const float* dw_qh_w = (const float*)d_in[1];
    const float* dw_qh_b = (const float*)d_in[2];
    const float* fc_qh_w = (const float*)d_in[3];
    const float* fc_qh_b = (const float*)d_in[4];
    const float* dw_kh_w = (const float*)d_in[5];
    const float* dw_kh_b = (const float*)d_in[6];
    const float* fc_kh_w = (const float*)d_in[7];
    const float* fc_kh_b = (const float*)d_in[8];
    const float* Bh      = (const float*)d_in[9];
    const float* dw_v_w  = (const float*)d_in[10];
    const float* dw_v_b  = (const float*)d_in[11];
    const float* fc_v_w  = (const float*)d_in[12];
    const float* fc_v_b  = (const float*)d_in[13];
    const float* dw_qw_w = (const float*)d_in[14];
    const float* dw_qw_b = (const float*)d_in[15];
    const float* fc_qw_w = (const float*)d_in[16];
    const float* fc_qw_b = (const float*)d_in[17];
    const float* dw_kw_w = (const float*)d_in[18];
    const float* dw_kw_b = (const float*)d_in[19];
    const float* fc_kw_w = (const float*)d_in[20];
    const float* fc_kw_b = (const float*)d_in[21];
    const float* Bw      = (const float*)d_in[22];
    const float* fc_o_w  = (const float*)d_in[23];
    const float* fc_o_b  = (const float*)d_in[24];
    float* out = (float*)d_out;

    round_weights<<<dim3(64, 6), 1024>>>(fc_qh_w, fc_kh_w, fc_qw_w, fc_kw_w,
                                         fc_v_w, fc_o_w);

    conv_fused_kernel<<<dim3(Cc, Bb), 256>>>(
        x, dw_v_w, dw_v_b,
        dw_qh_w, dw_qh_b, dw_kh_w, dw_kh_b,
        dw_qw_w, dw_qw_b, dw_kw_w, dw_kw_b);

    wmma_gemm_kernel<0><<<dim3(16, 2, 4), 128>>>(
        fc_qh_b, fc_kh_b, fc_qw_b, fc_kw_b, nullptr);

    attn_kernel<<<dim3(Bb * Hh, 2), 256>>>(Bh, Bw);

    wmma_gemm_kernel<1><<<dim3(64, 2, Bb), 128>>>(
        fc_v_b, fc_v_b, fc_v_b, fc_v_b, nullptr);

    axial_fused_kernel<<<dim3(4, Bb * Hh), 512>>>();

    wmma_gemm_kernel<2><<<dim3(64, 2, Bb), 128>>>(
        fc_o_b, fc_o_b, fc_o_b, fc_o_b, out);
}

// round 10
// speedup vs baseline: 3.5625x; 1.6980x over previous
#include <cuda_runtime.h>
#include <cuda_fp16.h>
#include <mma.h>
#include <cstdint>

using namespace nvcuda;

#define Bb 16
#define Cc 256
#define Ss 64
#define Hh 8
#define Dd 32

typedef __half hf;

// ---------------------------------------------------------------------------
// Scratch (all intermediates fp16, rounded at producers; fp32 accum in MMA)
// ---------------------------------------------------------------------------
__device__ hf g_pool[4][Cc * Bb * Ss];               // [c][b*64+s]  (A^T)
__device__ hf g_qkh[4][Bb * Hh * Ss * Dd];           // [b][head][s][d]
__device__ hf g_attn[2][Bb * Hh * Ss * Ss];
__device__ hf g_vconv[(size_t)Bb * Cc * 4096];       // [b][c][hw] (A^T)
__device__ hf g_v[(size_t)Bb * Hh * 4096 * 32];      // [b][head][hw][dv]
__device__ hf g_r2[(size_t)Bb * 4096 * Cc];          // [b][m=hw][k]
__device__ hf g_wh[6][Cc * Cc];                      // pre-rounded weights

__device__ __forceinline__ hf to_h(float x) { return __float2half_rn(x); }

__device__ __forceinline__ void cp_async16(void* smem, const void* gmem) {
    uint32_t s = (uint32_t)__cvta_generic_to_shared(smem);
    asm volatile("cp.async.cg.shared.global [%0], [%1], 16;" :: "r"(s), "l"(gmem));
}
#define CP_COMMIT() asm volatile("cp.async.commit_group;" ::: "memory")
#define CP_WAIT(n)  asm volatile("cp.async.wait_group %0;" :: "n"(n) : "memory")

// ---------------------------------------------------------------------------
// Kernel 0: round the 6 fc weight matrices to fp16.
// ---------------------------------------------------------------------------
__global__ void __launch_bounds__(1024) round_weights(
    const float* __restrict__ w0, const float* __restrict__ w1,
    const float* __restrict__ w2, const float* __restrict__ w3,
    const float* __restrict__ w4, const float* __restrict__ w5)
{
    const float* src = (blockIdx.y == 0) ? w0 : (blockIdx.y == 1) ? w1
                     : (blockIdx.y == 2) ? w2 : (blockIdx.y == 3) ? w3
                     : (blockIdx.y == 4) ? w4 : w5;
    const int i = blockIdx.x * 1024 + threadIdx.x;
    g_wh[blockIdx.y][i] = to_h(src[i]);
}

// ---------------------------------------------------------------------------
// Kernel 1: fused V dwconv + analytic pooled q/k branches. One read of x.
// ---------------------------------------------------------------------------
__global__ void __launch_bounds__(256) conv_fused_kernel(
    const float* __restrict__ x,
    const float* __restrict__ wv,  const float* __restrict__ bv,
    const float* __restrict__ wqh, const float* __restrict__ bqh,
    const float* __restrict__ wkh, const float* __restrict__ bkh,
    const float* __restrict__ wqw, const float* __restrict__ bqw,
    const float* __restrict__ wkw, const float* __restrict__ bkw)
{
    const int c = blockIdx.x;
    const int b = blockIdx.y;
    const int tid = threadIdx.x;

    __shared__ float xs[66][66];
    __shared__ float rowp[2][64], colp[4][64];
    __shared__ float T[64];
    __shared__ float wsm[4][9];
    __shared__ float bsm[4];

    for (int i = tid; i < 66 * 66; i += 256) (&xs[0][0])[i] = 0.f;
    __syncthreads();

    const float* xp = x + ((size_t)b * Cc + c) * 4096;
    for (int i = tid; i < 4096; i += 256) xs[(i >> 6) + 1][(i & 63) + 1] = xp[i];

    if (tid < 9)        wsm[0][tid]      = wqh[c * 9 + tid];
    else if (tid < 18)  wsm[1][tid - 9]  = wkh[c * 9 + tid - 9];
    else if (tid < 27)  wsm[2][tid - 18] = wqw[c * 9 + tid - 18];
    else if (tid < 36)  wsm[3][tid - 27] = wkw[c * 9 + tid - 27];
    if (tid == 36) bsm[0] = bqh[c];
    if (tid == 37) bsm[1] = bkh[c];
    if (tid == 38) bsm[2] = bqw[c];
    if (tid == 39) bsm[3] = bkw[c];

    float w[9];
#pragma unroll
    for (int i = 0; i < 9; i++) w[i] = wv[c * 9 + i];
    const float bias = bv[c];
    __syncthreads();

    const int wcol = tid & 63;
    const int hgrp = tid >> 6;
    hf* op = g_vconv + ((size_t)b * Cc + c) * 4096;

    float colacc = 0.f;
    for (int k = 0; k < 16; k++) {
        const int h = hgrp * 16 + k;
        float s = bias;
#pragma unroll
        for (int dy = 0; dy < 3; dy++)
#pragma unroll
            for (int dx = 0; dx < 3; dx++)
                s += w[dy * 3 + dx] * xs[h + dy][wcol + dx];
        op[h * 64 + wcol] = to_h(s);
        const float v = xs[h + 1][wcol + 1];
        colacc += v;
        float rsum = v;
#pragma unroll
        for (int off = 16; off; off >>= 1)
            rsum += __shfl_down_sync(0xffffffffu, rsum, off);
        if ((tid & 31) == 0) rowp[(tid >> 5) & 1][h] = rsum;
    }
    colp[hgrp][wcol] = colacc;
    __syncthreads();
    if (tid < 64) T[tid] = colp[0][tid] + colp[1][tid] + colp[2][tid] + colp[3][tid];
    __syncthreads();

    if (tid < 64) {
        const int s = tid;
        float o0 = 0.f, o1 = 0.f, o2 = 0.f, o3 = 0.f;
#pragma unroll
        for (int d = 0; d < 3; d++) {
            const int r = s + d - 1;
            if (r >= 0 && r < 64) {
                const float Sv = rowp[0][r] + rowp[1][r];
                const float eL = xs[r + 1][1], eR = xs[r + 1][64];
                o0 += (wsm[0][d*3] + wsm[0][d*3+1] + wsm[0][d*3+2]) * Sv
                    - wsm[0][d*3] * eR - wsm[0][d*3+2] * eL;
                o1 += (wsm[1][d*3] + wsm[1][d*3+1] + wsm[1][d*3+2]) * Sv
                    - wsm[1][d*3] * eR - wsm[1][d*3+2] * eL;
                const float Tv = T[r];
                const float eT = xs[1][r + 1], eB = xs[64][r + 1];
                o2 += (wsm[2][d] + wsm[2][3+d] + wsm[2][6+d]) * Tv
                    - wsm[2][d] * eB - wsm[2][6+d] * eT;
                o3 += (wsm[3][d] + wsm[3][3+d] + wsm[3][6+d]) * Tv
                    - wsm[3][d] * eB - wsm[3][6+d] * eT;
            }
        }
        const float inv = 1.f / 64.f;
        const int mi = b * 64 + s;
        g_pool[0][c * 1024 + mi] = to_h(o0 * inv + bsm[0]);
        g_pool[1][c * 1024 + mi] = to_h(o1 * inv + bsm[1]);
        g_pool[2][c * 1024 + mi] = to_h(o2 * inv + bsm[2]);
        g_pool[3][c * 1024 + mi] = to_h(o3 * inv + bsm[3]);
    }
}

// ---------------------------------------------------------------------------
// Kernel 2: attention. Scores via fp16 wmma, low-register softmax.
// ---------------------------------------------------------------------------
__global__ void __launch_bounds__(256) attn_kernel(
    const float* __restrict__ Bh, const float* __restrict__ Bw)
{
    const int bh = blockIdx.x;
    const int head = bh & 7;
    const int axis = blockIdx.y;
    const float scale = 0.17677669529663687f;

    const hf* q = g_qkh[axis == 0 ? 0 : 2] + (size_t)bh * 2048;
    const hf* k = g_qkh[axis == 0 ? 1 : 3] + (size_t)bh * 2048;
    const float* Bm = ((axis == 0) ? Bh : Bw) + head * 4096;
    hf* o = g_attn[axis] + (size_t)bh * 4096;

    __shared__ float sc[64 * 68];

    {
        const int wid = threadIdx.x >> 5;
        const int wm = wid >> 1;
        const int wn = wid & 1;
        wmma::fragment<wmma::accumulator, 16, 16, 16, float> acc[2];
        wmma::fill_fragment(acc[0], 0.f);
        wmma::fill_fragment(acc[1], 0.f);
#pragma unroll
        for (int d0 = 0; d0 < 32; d0 += 16) {
            wmma::fragment<wmma::matrix_a, 16, 16, 16, half, wmma::row_major> af;
            wmma::load_matrix_sync(af, q + (size_t)(wm * 16) * 32 + d0, 32);
            wmma::fragment<wmma::matrix_b, 16, 16, 16, half, wmma::col_major> bf_[2];
            wmma::load_matrix_sync(bf_[0], k + (size_t)(wn * 32) * 32 + d0, 32);
            wmma::load_matrix_sync(bf_[1], k + (size_t)(wn * 32 + 16) * 32 + d0, 32);
            wmma::mma_sync(acc[0], af, bf_[0], acc[0]);
            wmma::mma_sync(acc[1], af, bf_[1], acc[1]);
        }
        wmma::store_matrix_sync(&sc[wm * 16 * 68 + wn * 32], acc[0], 68,
                                wmma::mem_row_major);
        wmma::store_matrix_sync(&sc[wm * 16 * 68 + wn * 32 + 16], acc[1], 68,
                                wmma::mem_row_major);
    }
    __syncthreads();

    {
        const int i = threadIdx.x >> 2;
        const int qq = threadIdx.x & 3;
        float s[16];
        float mx = -1e30f;
#pragma unroll
        for (int jj = 0; jj < 16; jj += 4) {
            const int j = qq * 16 + jj;
            const float4 c4 = *reinterpret_cast<const float4*>(&sc[i * 68 + j]);
            const float4 b4 = *reinterpret_cast<const float4*>(&Bm[i * 64 + j]);
            s[jj + 0] = c4.x * scale + b4.x;
            s[jj + 1] = c4.y * scale + b4.y;
            s[jj + 2] = c4.z * scale + b4.z;
            s[jj + 3] = c4.w * scale + b4.w;
            mx = fmaxf(mx, fmaxf(fmaxf(s[jj], s[jj + 1]), fmaxf(s[jj + 2], s[jj + 3])));
        }
        mx = fmaxf(mx, __shfl_xor_sync(0xffffffffu, mx, 1));
        mx = fmaxf(mx, __shfl_xor_sync(0xffffffffu, mx, 2));
        float sum = 0.f;
#pragma unroll
        for (int jj = 0; jj < 16; jj++) { s[jj] = __expf(s[jj] - mx); sum += s[jj]; }
        sum += __shfl_xor_sync(0xffffffffu, sum, 1);
        sum += __shfl_xor_sync(0xffffffffu, sum, 2);
        const float r = 1.f / sum;
#pragma unroll
        for (int jj = 0; jj < 16; jj += 4) {
            const int j = qq * 16 + jj;
            __half2 lo, hi;
            lo.x = to_h(s[jj + 0] * r); lo.y = to_h(s[jj + 1] * r);
            hi.x = to_h(s[jj + 2] * r); hi.y = to_h(s[jj + 3] * r);
            uint2 pk;
            pk.x = *reinterpret_cast<uint32_t*>(&lo);
            pk.y = *reinterpret_cast<uint32_t*>(&hi);
            *reinterpret_cast<uint2*>(&o[i * 64 + j]) = pk;
        }
    }
}

// ---------------------------------------------------------------------------
// Unified fp16 wmma GEMM, cp.async double buffered.
// BM=64, BN=128, BK=32; 128 threads = 4 warps (2x2), warp tile 32x64.
// MODE 0: A=g_pool[z] col-major, W=g_wh[z],  out->g_qkh[z] (fp16)
// MODE 1: A=g_vconv[b] col-major, W=g_wh[4], out->g_v (fp16)
// MODE 2: A=g_r2[b] row-major,    W=g_wh[5], out->d_out (fp32)
// ---------------------------------------------------------------------------
#define APB 2560            // A elems per buffer (max of 32*72, 64*40)
#define WPB 5120            // W elems per buffer (128*40)

template <int MODE>
__global__ void __launch_bounds__(128, 3) wmma_gemm_kernel(
    const float* __restrict__ b0, const float* __restrict__ b1,
    const float* __restrict__ b2, const float* __restrict__ b3,
    float* __restrict__ outp)
{
    __shared__ __align__(16) unsigned char smem_raw[2 * APB * 2 + 2 * WPB * 2 + 16 * 132 * 4];
    hf* Asm = reinterpret_cast<hf*>(smem_raw);                 // 2 x APB
    hf* Wsm = reinterpret_cast<hf*>(smem_raw + 2 * APB * 2);   // 2 x WPB
    float* sbias = reinterpret_cast<float*>(smem_raw + 2 * APB * 2 + 2 * WPB * 2);
    float* Cs = reinterpret_cast<float*>(smem_raw);            // aliases operands (post-loop)

    const int tid = threadIdx.x;
    const int wid = tid >> 5;
    const int wm = wid >> 1;
    const int wn = wid & 1;
    const int m0 = blockIdx.x * 64;
    const int nb = blockIdx.y * 128;
    const int z = blockIdx.z;

    const hf* A;
    const float* bias;
    int ldA;
    const hf* W = g_wh[(MODE == 0) ? z : (MODE == 1) ? 4 : 5];
    if constexpr (MODE == 0) {
        A = g_pool[z]; ldA = 1024;
        bias = (z == 0) ? b0 : (z == 1) ? b1 : (z == 2) ? b2 : b3;
    } else if constexpr (MODE == 1) {
        A = g_vconv + (size_t)z * 1048576; ldA = 4096; bias = b0;
    } else {
        A = g_r2 + (size_t)z * 1048576; ldA = 256; bias = b0;
    }

    auto load_tiles = [&](int k0, int buf) {
        hf* As = Asm + buf * APB;
        hf* Ws = Wsm + buf * WPB;
#pragma unroll
        for (int i = 0; i < 2; i++) {
            const int f = tid + 128 * i;            // 256 chunks of 8 halves
            if constexpr (MODE != 2) {
                const int k = f >> 3, mq = f & 7;   // 32k x 64m col-major
                cp_async16(As + k * 72 + mq * 8,
                           A + (size_t)(k0 + k) * ldA + m0 + mq * 8);
            } else {
                const int m = f >> 2, kq = f & 3;   // 64m x 32k row-major
                cp_async16(As + m * 40 + kq * 8,
                           A + (size_t)(m0 + m) * 256 + k0 + kq * 8);
            }
        }
#pragma unroll
        for (int i = 0; i < 4; i++) {
            const int f = tid + 128 * i;            // 512 chunks
            const int n = f >> 2, kq = f & 3;
            cp_async16(Ws + n * 40 + kq * 8,
                       W + (size_t)(nb + n) * 256 + k0 + kq * 8);
        }
        CP_COMMIT();
    };

    for (int i = tid; i < 16 * 128; i += 128)
        sbias[(i >> 7) * 132 + (i & 127)] = bias[nb + (i & 127)];

    load_tiles(0, 0);
    __syncthreads();

    wmma::fragment<wmma::accumulator, 16, 16, 16, float> acc[2][4];
#pragma unroll
    for (int i = 0; i < 2; i++)
#pragma unroll
        for (int j = 0; j < 4; j++)
            wmma::load_matrix_sync(acc[i][j], &sbias[wn * 64 + j * 16], 132,
                                   wmma::mem_row_major);
    __syncthreads();

    int buf = 0;
    for (int it = 0; it < 8; it++) {
        if (it < 7) load_tiles((it + 1) * 32, buf ^ 1);
        if (it < 7) { CP_WAIT(1); } else { CP_WAIT(0); }
        __syncthreads();

        hf* As = Asm + buf * APB;
        hf* Ws = Wsm + buf * WPB;
#pragma unroll
        for (int kk = 0; kk < 32; kk += 16) {
            wmma::fragment<wmma::matrix_b, 16, 16, 16, half, wmma::col_major> bf_[4];
#pragma unroll
            for (int j = 0; j < 4; j++)
                wmma::load_matrix_sync(bf_[j], &Ws[(wn * 64 + j * 16) * 40 + kk], 40);
            if constexpr (MODE != 2) {
                wmma::fragment<wmma::matrix_a, 16, 16, 16, half, wmma::col_major> af[2];
                wmma::load_matrix_sync(af[0], &As[kk * 72 + wm * 32], 72);
                wmma::load_matrix_sync(af[1], &As[kk * 72 + wm * 32 + 16], 72);
#pragma unroll
                for (int i = 0; i < 2; i++)
#pragma unroll
                    for (int j = 0; j < 4; j++)
                        wmma::mma_sync(acc[i][j], af[i], bf_[j], acc[i][j]);
            } else {
                wmma::fragment<wmma::matrix_a, 16, 16, 16, half, wmma::row_major> af[2];
                wmma::load_matrix_sync(af[0], &As[(wm * 32) * 40 + kk], 40);
                wmma::load_matrix_sync(af[1], &As[(wm * 32 + 16) * 40 + kk], 40);
#pragma unroll
                for (int i = 0; i < 2; i++)
#pragma unroll
                    for (int j = 0; j < 4; j++)
                        wmma::mma_sync(acc[i][j], af[i], bf_[j], acc[i][j]);
            }
        }
        __syncthreads();
        buf ^= 1;
    }

    if constexpr (MODE == 2) {
#pragma unroll
        for (int i = 0; i < 2; i++)
#pragma unroll
            for (int j = 0; j < 4; j++) {
                const int mg = m0 + wm * 32 + i * 16;
                const int ng = nb + wn * 64 + j * 16;
                wmma::store_matrix_sync(
                    outp + (size_t)z * 1048576 + (size_t)mg * 256 + ng,
                    acc[i][j], 256, wmma::mem_row_major);
            }
    } else {
        // stage fp32 C in smem (operand buffers dead), convert to fp16
#pragma unroll
        for (int i = 0; i < 2; i++)
#pragma unroll
            for (int j = 0; j < 4; j++)
                wmma::store_matrix_sync(&Cs[(wm * 32 + i * 16) * 132 + wn * 64 + j * 16],
                                        acc[i][j], 132, wmma::mem_row_major);
        __syncthreads();
#pragma unroll
        for (int i = 0; i < 16; i++) {
            const int f = tid + 128 * i;        // 2048 chunks of 4
            const int row = f >> 5;
            const int cq = f & 31;
            const float4 v = *reinterpret_cast<const float4*>(&Cs[row * 132 + cq * 4]);
            __half2 lo, hi;
            lo.x = to_h(v.x); lo.y = to_h(v.y);
            hi.x = to_h(v.z); hi.y = to_h(v.w);
            uint2 pk;
            pk.x = *reinterpret_cast<uint32_t*>(&lo);
            pk.y = *reinterpret_cast<uint32_t*>(&hi);
            const int mg = m0 + row;
            const int ng = nb + cq * 4;
            const int head = ng >> 5;
            hf* dst;
            if constexpr (MODE == 0)
                dst = g_qkh[z] + (size_t)(mg >> 6) * 16384 + (size_t)head * 2048
                    + (size_t)(mg & 63) * 32 + (ng & 31);
            else
                dst = g_v + (size_t)z * 1048576 + (size_t)head * 131072
                    + (size_t)mg * 32 + (ng & 31);
            *reinterpret_cast<uint2*>(dst) = pk;
        }
    }
}

// ---------------------------------------------------------------------------
// Kernel 4: fused axial mixing, fp16. Block = (hgroup of 16, bh), 512 threads.
// tb staging uses ldm=20 (80B, 16B-multiple) — wmma ldm contract.
// ---------------------------------------------------------------------------
__global__ void __launch_bounds__(512) axial_fused_kernel()
{
    __shared__ hf R[16 * 2048];              // 64KB
    __shared__ float tb[16][320];            // per-warp 16x(ld=20) staging
    const int bh = blockIdx.y;
    const int hg = blockIdx.x;
    const int wid = threadIdx.x >> 5;
    const int lane = threadIdx.x & 31;

    const hf* Ah = g_attn[0] + (size_t)bh * 4096 + (size_t)(hg * 16) * 64;
    const hf* Vg = g_v + (size_t)bh * 131072;

    // ---- stage 1: R[16][2048] = attn_h(16 rows) @ V
    {
        const int n0 = wid * 128;
        wmma::fragment<wmma::accumulator, 16, 16, 16, float> acc[8];
#pragma unroll
        for (int j = 0; j < 8; j++) wmma::fill_fragment(acc[j], 0.f);
#pragma unroll
        for (int k0 = 0; k0 < 64; k0 += 16) {
            wmma::fragment<wmma::matrix_a, 16, 16, 16, half, wmma::row_major> af;
            wmma::load_matrix_sync(af, Ah + k0, 64);
            wmma::fragment<wmma::matrix_b, 16, 16, 16, half, wmma::row_major> bf_[8];
#pragma unroll
            for (int j = 0; j < 8; j++)
                wmma::load_matrix_sync(bf_[j], Vg + (size_t)k0 * 2048 + n0 + j * 16, 2048);
#pragma unroll
            for (int j = 0; j < 8; j++)
                wmma::mma_sync(acc[j], af, bf_[j], acc[j]);
        }
#pragma unroll
        for (int j = 0; j < 8; j++) {
            wmma::store_matrix_sync(&tb[wid][0], acc[j], 20, wmma::mem_row_major);
            __syncwarp();
            const int r = lane >> 1;
            const int c0 = (lane & 1) * 8;
            __half2 p[4];
#pragma unroll
            for (int t = 0; t < 4; t++) {
                p[t].x = to_h(tb[wid][r * 20 + c0 + t * 2]);
                p[t].y = to_h(tb[wid][r * 20 + c0 + t * 2 + 1]);
            }
            *reinterpret_cast<uint4*>(&R[r * 2048 + n0 + j * 16 + c0]) =
                *reinterpret_cast<uint4*>(p);
            __syncwarp();
        }
    }
    __syncthreads();

    // ---- stage 2: warp wid handles h = hg*16+wid; r2 = (R[h] as [dv][w]) @ attn_w
    {
        const hf* Ar = &R[wid * 2048];       // col-major [dv][w], ld 32
        const hf* Bg = g_attn[1] + (size_t)bh * 4096;
        const int h = hg * 16 + wid;
        hf* dstb = g_r2 + (size_t)(bh >> 3) * 1048576
                 + (size_t)h * 64 * 256 + (bh & 7) * 32;

        wmma::fragment<wmma::accumulator, 16, 16, 16, float> acc[2][4];
#pragma unroll
        for (int i = 0; i < 2; i++)
#pragma unroll
            for (int j = 0; j < 4; j++) wmma::fill_fragment(acc[i][j], 0.f);

#pragma unroll
        for (int k0 = 0; k0 < 64; k0 += 16) {
            wmma::fragment<wmma::matrix_a, 16, 16, 16, half, wmma::col_major> af[2];
            wmma::load_matrix_sync(af[0], Ar + k0 * 32, 32);
            wmma::load_matrix_sync(af[1], Ar + k0 * 32 + 16, 32);
            wmma::fragment<wmma::matrix_b, 16, 16, 16, half, wmma::row_major> bf_[4];
#pragma unroll
            for (int j = 0; j < 4; j++)
                wmma::load_matrix_sync(bf_[j], Bg + (size_t)k0 * 64 + j * 16, 64);
#pragma unroll
            for (int i = 0; i < 2; i++)
#pragma unroll
                for (int j = 0; j < 4; j++)
                    wmma::mma_sync(acc[i][j], af[i], bf_[j], acc[i][j]);
        }
#pragma unroll
        for (int i = 0; i < 2; i++)
#pragma unroll
            for (int j = 0; j < 4; j++) {
                wmma::store_matrix_sync(&tb[wid][0], acc[i][j], 20, wmma::mem_row_major);
                __syncwarp();
                const int c = lane >> 1;           // w' within tile
                const int r0 = (lane & 1) * 8;     // dv start
                __half2 p[4];
#pragma unroll
                for (int t = 0; t < 4; t++) {
                    p[t].x = to_h(tb[wid][(r0 + t * 2) * 20 + c]);
                    p[t].y = to_h(tb[wid][(r0 + t * 2 + 1) * 20 + c]);
                }
                *reinterpret_cast<uint4*>(dstb + (size_t)(j * 16 + c) * 256 + i * 16 + r0) =
                    *reinterpret_cast<uint4*>(p);
                __syncwarp();
            }
    }
}

// ---------------------------------------------------------------------------
// Launch
// ---------------------------------------------------------------------------
extern "C" void kernel_launch(void* const* d_in, const int* in_sizes, int n_in,
                              void* d_out, int out_size)
{
    const float* x       = (const float*)d_in[0];
    const float* dw_qh_w = (const float*)d_in[1];
    const float* dw_qh_b = (const float*)d_in[2];
    const float* fc_qh_w = (const float*)d_in[3];
    const float* fc_qh_b = (const float*)d_in[4];
    const float* dw_kh_w = (const float*)d_in[5];
    const float* dw_kh_b = (const float*)d_in[6];
    const float* fc_kh_w = (const float*)d_in[7];
    const float* fc_kh_b = (const float*)d_in[8];
    const float* Bh      = (const float*)d_in[9];
    const float* dw_v_w  = (const float*)d_in[10];
    const float* dw_v_b  = (const float*)d_in[11];
    const float* fc_v_w  = (const float*)d_in[12];
    const float* fc_v_b  = (const float*)d_in[13];
    const float* dw_qw_w = (const float*)d_in[14];
    const float* dw_qw_b = (const float*)d_in[15];
    const float* fc_qw_w = (const float*)d_in[16];
    const float* fc_qw_b = (const float*)d_in[17];
    const float* dw_kw_w = (const float*)d_in[18];
    const float* dw_kw_b = (const float*)d_in[19];
    const float* fc_kw_w = (const float*)d_in[20];
    const float* fc_kw_b = (const float*)d_in[21];
    const float* Bw      = (const float*)d_in[22];
    const float* fc_o_w  = (const float*)d_in[23];
    const float* fc_o_b  = (const float*)d_in[24];
    float* out = (float*)d_out;

    round_weights<<<dim3(64, 6), 1024>>>(fc_qh_w, fc_kh_w, fc_qw_w, fc_kw_w,
                                         fc_v_w, fc_o_w);

    conv_fused_kernel<<<dim3(Cc, Bb), 256>>>(
        x, dw_v_w, dw_v_b,
        dw_qh_w, dw_qh_b, dw_kh_w, dw_kh_b,
        dw_qw_w, dw_qw_b, dw_kw_w, dw_kw_b);

    wmma_gemm_kernel<0><<<dim3(16, 2, 4), 128>>>(
        fc_qh_b, fc_kh_b, fc_qw_b, fc_kw_b, nullptr);

    attn_kernel<<<dim3(Bb * Hh, 2), 256>>>(Bh, Bw);

    wmma_gemm_kernel<1><<<dim3(64, 2, Bb), 128>>>(
        fc_v_b, fc_v_b, fc_v_b, fc_v_b, nullptr);

    axial_fused_kernel<<<dim3(4, Bb * Hh), 512>>>();

    wmma_gemm_kernel<2><<<dim3(64, 2, Bb), 128>>>(
        fc_o_b, fc_o_b, fc_o_b, fc_o_b, out);
}

// round 11
// speedup vs baseline: 3.7970x; 1.0658x over previous
#include <cuda_runtime.h>
#include <cuda_fp16.h>
#include <mma.h>
#include <cstdint>

using namespace nvcuda;

#define Bb 16
#define Cc 256
#define Ss 64
#define Hh 8
#define Dd 32

typedef __half hf;

// ---------------------------------------------------------------------------
// Scratch (all intermediates fp16, rounded at producers; fp32 accum in MMA)
// ---------------------------------------------------------------------------
__device__ hf g_pool[4][Cc * Bb * Ss];               // [c][b*64+s]  (A^T)
__device__ hf g_qkh[4][Bb * Hh * Ss * Dd];           // [b][head][s][d]
__device__ hf g_attn[2][Bb * Hh * Ss * Ss];
__device__ hf g_vconv[(size_t)Bb * Cc * 4096];       // [b][c][hw] (A^T)
__device__ hf g_v[(size_t)Bb * Hh * 4096 * 32];      // [b][head][hw][dv]
__device__ hf g_r2[(size_t)Bb * 4096 * Cc];          // [b][m=hw][k]
__device__ hf g_wh[6][Cc * Cc];                      // pre-rounded weights

__device__ __forceinline__ hf to_h(float x) { return __float2half_rn(x); }

__device__ __forceinline__ void cp_async16(void* smem, const void* gmem) {
    uint32_t s = (uint32_t)__cvta_generic_to_shared(smem);
    asm volatile("cp.async.cg.shared.global [%0], [%1], 16;" :: "r"(s), "l"(gmem));
}
#define CP_COMMIT() asm volatile("cp.async.commit_group;" ::: "memory")
#define CP_WAIT(n)  asm volatile("cp.async.wait_group %0;" :: "n"(n) : "memory")

// ---------------------------------------------------------------------------
// Kernel 1: fused V dwconv + analytic pooled q/k branches + weight rounding.
// Grid (256, 17): y<16 = conv blocks (c, b); y==16 = weight-rounding blocks.
// ---------------------------------------------------------------------------
__global__ void __launch_bounds__(256) conv_fused_kernel(
    const float* __restrict__ x,
    const float* __restrict__ wv,  const float* __restrict__ bv,
    const float* __restrict__ wqh, const float* __restrict__ bqh,
    const float* __restrict__ wkh, const float* __restrict__ bkh,
    const float* __restrict__ wqw, const float* __restrict__ bqw,
    const float* __restrict__ wkw, const float* __restrict__ bkw,
    const float* __restrict__ fqh, const float* __restrict__ fkh,
    const float* __restrict__ fqw, const float* __restrict__ fkw,
    const float* __restrict__ fv,  const float* __restrict__ fo)
{
    const int tid = threadIdx.x;

    if (blockIdx.y == Bb) {
        // weight rounding: 256 blocks x 256 threads cover 65536 elements x 6
        const int i = blockIdx.x * 256 + tid;
        g_wh[0][i] = to_h(fqh[i]);
        g_wh[1][i] = to_h(fkh[i]);
        g_wh[2][i] = to_h(fqw[i]);
        g_wh[3][i] = to_h(fkw[i]);
        g_wh[4][i] = to_h(fv[i]);
        g_wh[5][i] = to_h(fo[i]);
        return;
    }

    const int c = blockIdx.x;
    const int b = blockIdx.y;

    __shared__ float xs[66][66];
    __shared__ float rowp[2][64], colp[4][64];
    __shared__ float T[64];
    __shared__ float wsm[4][9];
    __shared__ float bsm[4];

    for (int i = tid; i < 66 * 66; i += 256) (&xs[0][0])[i] = 0.f;
    __syncthreads();

    const float* xp = x + ((size_t)b * Cc + c) * 4096;
    for (int i = tid; i < 4096; i += 256) xs[(i >> 6) + 1][(i & 63) + 1] = xp[i];

    if (tid < 9)        wsm[0][tid]      = wqh[c * 9 + tid];
    else if (tid < 18)  wsm[1][tid - 9]  = wkh[c * 9 + tid - 9];
    else if (tid < 27)  wsm[2][tid - 18] = wqw[c * 9 + tid - 18];
    else if (tid < 36)  wsm[3][tid - 27] = wkw[c * 9 + tid - 27];
    if (tid == 36) bsm[0] = bqh[c];
    if (tid == 37) bsm[1] = bkh[c];
    if (tid == 38) bsm[2] = bqw[c];
    if (tid == 39) bsm[3] = bkw[c];

    float w[9];
#pragma unroll
    for (int i = 0; i < 9; i++) w[i] = wv[c * 9 + i];
    const float bias = bv[c];
    __syncthreads();

    const int wcol = tid & 63;
    const int hgrp = tid >> 6;
    hf* op = g_vconv + ((size_t)b * Cc + c) * 4096;

    float colacc = 0.f;
    for (int k = 0; k < 16; k++) {
        const int h = hgrp * 16 + k;
        float s = bias;
#pragma unroll
        for (int dy = 0; dy < 3; dy++)
#pragma unroll
            for (int dx = 0; dx < 3; dx++)
                s += w[dy * 3 + dx] * xs[h + dy][wcol + dx];
        op[h * 64 + wcol] = to_h(s);
        const float v = xs[h + 1][wcol + 1];
        colacc += v;
        float rsum = v;
#pragma unroll
        for (int off = 16; off; off >>= 1)
            rsum += __shfl_down_sync(0xffffffffu, rsum, off);
        if ((tid & 31) == 0) rowp[(tid >> 5) & 1][h] = rsum;
    }
    colp[hgrp][wcol] = colacc;
    __syncthreads();
    if (tid < 64) T[tid] = colp[0][tid] + colp[1][tid] + colp[2][tid] + colp[3][tid];
    __syncthreads();

    if (tid < 64) {
        const int s = tid;
        float o0 = 0.f, o1 = 0.f, o2 = 0.f, o3 = 0.f;
#pragma unroll
        for (int d = 0; d < 3; d++) {
            const int r = s + d - 1;
            if (r >= 0 && r < 64) {
                const float Sv = rowp[0][r] + rowp[1][r];
                const float eL = xs[r + 1][1], eR = xs[r + 1][64];
                o0 += (wsm[0][d*3] + wsm[0][d*3+1] + wsm[0][d*3+2]) * Sv
                    - wsm[0][d*3] * eR - wsm[0][d*3+2] * eL;
                o1 += (wsm[1][d*3] + wsm[1][d*3+1] + wsm[1][d*3+2]) * Sv
                    - wsm[1][d*3] * eR - wsm[1][d*3+2] * eL;
                const float Tv = T[r];
                const float eT = xs[1][r + 1], eB = xs[64][r + 1];
                o2 += (wsm[2][d] + wsm[2][3+d] + wsm[2][6+d]) * Tv
                    - wsm[2][d] * eB - wsm[2][6+d] * eT;
                o3 += (wsm[3][d] + wsm[3][3+d] + wsm[3][6+d]) * Tv
                    - wsm[3][d] * eB - wsm[3][6+d] * eT;
            }
        }
        const float inv = 1.f / 64.f;
        const int mi = b * 64 + s;
        g_pool[0][c * 1024 + mi] = to_h(o0 * inv + bsm[0]);
        g_pool[1][c * 1024 + mi] = to_h(o1 * inv + bsm[1]);
        g_pool[2][c * 1024 + mi] = to_h(o2 * inv + bsm[2]);
        g_pool[3][c * 1024 + mi] = to_h(o3 * inv + bsm[3]);
    }
}

// ---------------------------------------------------------------------------
// Kernel 2: attention. Scores via fp16 wmma, low-register softmax.
// ---------------------------------------------------------------------------
__global__ void __launch_bounds__(256) attn_kernel(
    const float* __restrict__ Bh, const float* __restrict__ Bw)
{
    const int bh = blockIdx.x;
    const int head = bh & 7;
    const int axis = blockIdx.y;
    const float scale = 0.17677669529663687f;

    const hf* q = g_qkh[axis == 0 ? 0 : 2] + (size_t)bh * 2048;
    const hf* k = g_qkh[axis == 0 ? 1 : 3] + (size_t)bh * 2048;
    const float* Bm = ((axis == 0) ? Bh : Bw) + head * 4096;
    hf* o = g_attn[axis] + (size_t)bh * 4096;

    __shared__ float sc[64 * 68];

    {
        const int wid = threadIdx.x >> 5;
        const int wm = wid >> 1;
        const int wn = wid & 1;
        wmma::fragment<wmma::accumulator, 16, 16, 16, float> acc[2];
        wmma::fill_fragment(acc[0], 0.f);
        wmma::fill_fragment(acc[1], 0.f);
#pragma unroll
        for (int d0 = 0; d0 < 32; d0 += 16) {
            wmma::fragment<wmma::matrix_a, 16, 16, 16, half, wmma::row_major> af;
            wmma::load_matrix_sync(af, q + (size_t)(wm * 16) * 32 + d0, 32);
            wmma::fragment<wmma::matrix_b, 16, 16, 16, half, wmma::col_major> bf_[2];
            wmma::load_matrix_sync(bf_[0], k + (size_t)(wn * 32) * 32 + d0, 32);
            wmma::load_matrix_sync(bf_[1], k + (size_t)(wn * 32 + 16) * 32 + d0, 32);
            wmma::mma_sync(acc[0], af, bf_[0], acc[0]);
            wmma::mma_sync(acc[1], af, bf_[1], acc[1]);
        }
        wmma::store_matrix_sync(&sc[wm * 16 * 68 + wn * 32], acc[0], 68,
                                wmma::mem_row_major);
        wmma::store_matrix_sync(&sc[wm * 16 * 68 + wn * 32 + 16], acc[1], 68,
                                wmma::mem_row_major);
    }
    __syncthreads();

    {
        const int i = threadIdx.x >> 2;
        const int qq = threadIdx.x & 3;
        float s[16];
        float mx = -1e30f;
#pragma unroll
        for (int jj = 0; jj < 16; jj += 4) {
            const int j = qq * 16 + jj;
            const float4 c4 = *reinterpret_cast<const float4*>(&sc[i * 68 + j]);
            const float4 b4 = *reinterpret_cast<const float4*>(&Bm[i * 64 + j]);
            s[jj + 0] = c4.x * scale + b4.x;
            s[jj + 1] = c4.y * scale + b4.y;
            s[jj + 2] = c4.z * scale + b4.z;
            s[jj + 3] = c4.w * scale + b4.w;
            mx = fmaxf(mx, fmaxf(fmaxf(s[jj], s[jj + 1]), fmaxf(s[jj + 2], s[jj + 3])));
        }
        mx = fmaxf(mx, __shfl_xor_sync(0xffffffffu, mx, 1));
        mx = fmaxf(mx, __shfl_xor_sync(0xffffffffu, mx, 2));
        float sum = 0.f;
#pragma unroll
        for (int jj = 0; jj < 16; jj++) { s[jj] = __expf(s[jj] - mx); sum += s[jj]; }
        sum += __shfl_xor_sync(0xffffffffu, sum, 1);
        sum += __shfl_xor_sync(0xffffffffu, sum, 2);
        const float r = 1.f / sum;
#pragma unroll
        for (int jj = 0; jj < 16; jj += 4) {
            const int j = qq * 16 + jj;
            __half2 lo, hi;
            lo.x = to_h(s[jj + 0] * r); lo.y = to_h(s[jj + 1] * r);
            hi.x = to_h(s[jj + 2] * r); hi.y = to_h(s[jj + 3] * r);
            uint2 pk;
            pk.x = *reinterpret_cast<uint32_t*>(&lo);
            pk.y = *reinterpret_cast<uint32_t*>(&hi);
            *reinterpret_cast<uint2*>(&o[i * 64 + j]) = pk;
        }
    }
}

// ---------------------------------------------------------------------------
// Unified fp16 wmma GEMM, cp.async double buffered, BK=64 (4 iterations).
// BM=64, BN=128; 128 threads = 4 warps (2x2), warp tile 32x64; 3 CTAs/SM.
// MODE 1 ("QKV"): z<16  -> V GEMM (A=g_vconv[z] col-major, W=g_wh[4]) -> g_v
//                 z==16 -> q/k GEMM (A=g_pool[x>>4] col-major, W=g_wh[x>>4])
//                          -> g_qkh   (x&15 = m tile)
// MODE 2: A=g_r2[z] row-major, W=g_wh[5], out -> d_out (fp32)
// ---------------------------------------------------------------------------
#define APB 4608            // A elems per buffer (64 x 72)
#define WPB 9216            // W elems per buffer (128 x 72)

template <int MODE>
__global__ void __launch_bounds__(128, 3) wmma_gemm_kernel(
    const float* __restrict__ b0, const float* __restrict__ b1,
    const float* __restrict__ b2, const float* __restrict__ b3,
    const float* __restrict__ bv, float* __restrict__ outp)
{
    __shared__ __align__(16) unsigned char smem_raw[2 * APB * 2 + 2 * WPB * 2 + 16 * 132 * 4];
    hf* Asm = reinterpret_cast<hf*>(smem_raw);                 // 2 x APB
    hf* Wsm = reinterpret_cast<hf*>(smem_raw + 2 * APB * 2);   // 2 x WPB
    float* sbias = reinterpret_cast<float*>(smem_raw + 2 * APB * 2 + 2 * WPB * 2);
    float* Cs = reinterpret_cast<float*>(smem_raw);            // aliases operands post-loop

    const int tid = threadIdx.x;
    const int wid = tid >> 5;
    const int wm = wid >> 1;
    const int wn = wid & 1;
    const int nb = blockIdx.y * 128;
    const int z = blockIdx.z;

    const hf* A;
    const hf* W;
    const float* bias;
    int ldA, m0;
    bool isqk = false;
    int qkbr = 0;
    if constexpr (MODE == 1) {
        if (z < 16) {
            A = g_vconv + (size_t)z * 1048576; ldA = 4096;
            W = g_wh[4]; bias = bv; m0 = blockIdx.x * 64;
        } else {
            isqk = true;
            qkbr = blockIdx.x >> 4;
            A = g_pool[qkbr]; ldA = 1024;
            W = g_wh[qkbr];
            bias = (qkbr == 0) ? b0 : (qkbr == 1) ? b1 : (qkbr == 2) ? b2 : b3;
            m0 = (blockIdx.x & 15) * 64;
        }
    } else {
        A = g_r2 + (size_t)z * 1048576; ldA = 256;
        W = g_wh[5]; bias = b0; m0 = blockIdx.x * 64;
    }

    auto load_tiles = [&](int k0, int buf) {
        hf* As = Asm + buf * APB;
        hf* Ws = Wsm + buf * WPB;
#pragma unroll
        for (int i = 0; i < 4; i++) {
            const int f = tid + 128 * i;            // 512 chunks of 8 halves
            if constexpr (MODE == 1) {
                const int k = f >> 3, mq = f & 7;   // 64k x 64m col-major
                cp_async16(As + k * 72 + mq * 8,
                           A + (size_t)(k0 + k) * ldA + m0 + mq * 8);
            } else {
                const int m = f >> 3, kq = f & 7;   // 64m x 64k row-major
                cp_async16(As + m * 72 + kq * 8,
                           A + (size_t)(m0 + m) * 256 + k0 + kq * 8);
            }
        }
#pragma unroll
        for (int i = 0; i < 8; i++) {
            const int f = tid + 128 * i;            // 1024 chunks
            const int n = f >> 3, kq = f & 7;
            cp_async16(Ws + n * 72 + kq * 8,
                       W + (size_t)(nb + n) * 256 + k0 + kq * 8);
        }
        CP_COMMIT();
    };

    for (int i = tid; i < 16 * 128; i += 128)
        sbias[(i >> 7) * 132 + (i & 127)] = bias[nb + (i & 127)];

    load_tiles(0, 0);
    __syncthreads();

    wmma::fragment<wmma::accumulator, 16, 16, 16, float> acc[2][4];
#pragma unroll
    for (int i = 0; i < 2; i++)
#pragma unroll
        for (int j = 0; j < 4; j++)
            wmma::load_matrix_sync(acc[i][j], &sbias[wn * 64 + j * 16], 132,
                                   wmma::mem_row_major);
    __syncthreads();

    int buf = 0;
    for (int it = 0; it < 4; it++) {
        if (it < 3) load_tiles((it + 1) * 64, buf ^ 1);
        if (it < 3) { CP_WAIT(1); } else { CP_WAIT(0); }
        __syncthreads();

        hf* As = Asm + buf * APB;
        hf* Ws = Wsm + buf * WPB;
#pragma unroll
        for (int kk = 0; kk < 64; kk += 16) {
            wmma::fragment<wmma::matrix_b, 16, 16, 16, half, wmma::col_major> bf_[4];
#pragma unroll
            for (int j = 0; j < 4; j++)
                wmma::load_matrix_sync(bf_[j], &Ws[(wn * 64 + j * 16) * 72 + kk], 72);
            if constexpr (MODE == 1) {
                wmma::fragment<wmma::matrix_a, 16, 16, 16, half, wmma::col_major> af[2];
                wmma::load_matrix_sync(af[0], &As[kk * 72 + wm * 32], 72);
                wmma::load_matrix_sync(af[1], &As[kk * 72 + wm * 32 + 16], 72);
#pragma unroll
                for (int i = 0; i < 2; i++)
#pragma unroll
                    for (int j = 0; j < 4; j++)
                        wmma::mma_sync(acc[i][j], af[i], bf_[j], acc[i][j]);
            } else {
                wmma::fragment<wmma::matrix_a, 16, 16, 16, half, wmma::row_major> af[2];
                wmma::load_matrix_sync(af[0], &As[(wm * 32) * 72 + kk], 72);
                wmma::load_matrix_sync(af[1], &As[(wm * 32 + 16) * 72 + kk], 72);
#pragma unroll
                for (int i = 0; i < 2; i++)
#pragma unroll
                    for (int j = 0; j < 4; j++)
                        wmma::mma_sync(acc[i][j], af[i], bf_[j], acc[i][j]);
            }
        }
        __syncthreads();
        buf ^= 1;
    }

    if constexpr (MODE == 2) {
#pragma unroll
        for (int i = 0; i < 2; i++)
#pragma unroll
            for (int j = 0; j < 4; j++) {
                const int mg = m0 + wm * 32 + i * 16;
                const int ng = nb + wn * 64 + j * 16;
                wmma::store_matrix_sync(
                    outp + (size_t)z * 1048576 + (size_t)mg * 256 + ng,
                    acc[i][j], 256, wmma::mem_row_major);
            }
    } else {
        // stage fp32 C in smem (operand buffers dead), convert to fp16
#pragma unroll
        for (int i = 0; i < 2; i++)
#pragma unroll
            for (int j = 0; j < 4; j++)
                wmma::store_matrix_sync(&Cs[(wm * 32 + i * 16) * 132 + wn * 64 + j * 16],
                                        acc[i][j], 132, wmma::mem_row_major);
        __syncthreads();
#pragma unroll
        for (int i = 0; i < 16; i++) {
            const int f = tid + 128 * i;        // 2048 chunks of 4
            const int row = f >> 5;
            const int cq = f & 31;
            const float4 v = *reinterpret_cast<const float4*>(&Cs[row * 132 + cq * 4]);
            __half2 lo, hi;
            lo.x = to_h(v.x); lo.y = to_h(v.y);
            hi.x = to_h(v.z); hi.y = to_h(v.w);
            uint2 pk;
            pk.x = *reinterpret_cast<uint32_t*>(&lo);
            pk.y = *reinterpret_cast<uint32_t*>(&hi);
            const int mg = m0 + row;
            const int ng = nb + cq * 4;
            const int head = ng >> 5;
            hf* dst;
            if (isqk)
                dst = g_qkh[qkbr] + (size_t)(mg >> 6) * 16384 + (size_t)head * 2048
                    + (size_t)(mg & 63) * 32 + (ng & 31);
            else
                dst = g_v + (size_t)z * 1048576 + (size_t)head * 131072
                    + (size_t)mg * 32 + (ng & 31);
            *reinterpret_cast<uint2*>(dst) = pk;
        }
    }
}

// ---------------------------------------------------------------------------
// Kernel 4: fused axial mixing, fp16. Block = (hgroup of 16, bh), 512 threads.
// tb staging uses ldm=20 (80B, 16B-multiple per the wmma ldm contract).
// ---------------------------------------------------------------------------
__global__ void __launch_bounds__(512) axial_fused_kernel()
{
    __shared__ hf R[16 * 2048];              // 64KB
    __shared__ float tb[16][320];            // per-warp 16x(ld=20) staging
    const int bh = blockIdx.y;
    const int hg = blockIdx.x;
    const int wid = threadIdx.x >> 5;
    const int lane = threadIdx.x & 31;

    const hf* Ah = g_attn[0] + (size_t)bh * 4096 + (size_t)(hg * 16) * 64;
    const hf* Vg = g_v + (size_t)bh * 131072;

    // ---- stage 1: R[16][2048] = attn_h(16 rows) @ V
    {
        const int n0 = wid * 128;
        wmma::fragment<wmma::accumulator, 16, 16, 16, float> acc[8];
#pragma unroll
        for (int j = 0; j < 8; j++) wmma::fill_fragment(acc[j], 0.f);
#pragma unroll
        for (int k0 = 0; k0 < 64; k0 += 16) {
            wmma::fragment<wmma::matrix_a, 16, 16, 16, half, wmma::row_major> af;
            wmma::load_matrix_sync(af, Ah + k0, 64);
            wmma::fragment<wmma::matrix_b, 16, 16, 16, half, wmma::row_major> bf_[8];
#pragma unroll
            for (int j = 0; j < 8; j++)
                wmma::load_matrix_sync(bf_[j], Vg + (size_t)k0 * 2048 + n0 + j * 16, 2048);
#pragma unroll
            for (int j = 0; j < 8; j++)
                wmma::mma_sync(acc[j], af, bf_[j], acc[j]);
        }
#pragma unroll
        for (int j = 0; j < 8; j++) {
            wmma::store_matrix_sync(&tb[wid][0], acc[j], 20, wmma::mem_row_major);
            __syncwarp();
            const int r = lane >> 1;
            const int c0 = (lane & 1) * 8;
            __half2 p[4];
#pragma unroll
            for (int t = 0; t < 4; t++) {
                p[t].x = to_h(tb[wid][r * 20 + c0 + t * 2]);
                p[t].y = to_h(tb[wid][r * 20 + c0 + t * 2 + 1]);
            }
            *reinterpret_cast<uint4*>(&R[r * 2048 + n0 + j * 16 + c0]) =
                *reinterpret_cast<uint4*>(p);
            __syncwarp();
        }
    }
    __syncthreads();

    // ---- stage 2: warp wid handles h = hg*16+wid; r2 = (R[h] as [dv][w]) @ attn_w
    {
        const hf* Ar = &R[wid * 2048];       // col-major [dv][w], ld 32
        const hf* Bg = g_attn[1] + (size_t)bh * 4096;
        const int h = hg * 16 + wid;
        hf* dstb = g_r2 + (size_t)(bh >> 3) * 1048576
                 + (size_t)h * 64 * 256 + (bh & 7) * 32;

        wmma::fragment<wmma::accumulator, 16, 16, 16, float> acc[2][4];
#pragma unroll
        for (int i = 0; i < 2; i++)
#pragma unroll
            for (int j = 0; j < 4; j++) wmma::fill_fragment(acc[i][j], 0.f);

#pragma unroll
        for (int k0 = 0; k0 < 64; k0 += 16) {
            wmma::fragment<wmma::matrix_a, 16, 16, 16, half, wmma::col_major> af[2];
            wmma::load_matrix_sync(af[0], Ar + k0 * 32, 32);
            wmma::load_matrix_sync(af[1], Ar + k0 * 32 + 16, 32);
            wmma::fragment<wmma::matrix_b, 16, 16, 16, half, wmma::row_major> bf_[4];
#pragma unroll
            for (int j = 0; j < 4; j++)
                wmma::load_matrix_sync(bf_[j], Bg + (size_t)k0 * 64 + j * 16, 64);
#pragma unroll
            for (int i = 0; i < 2; i++)
#pragma unroll
                for (int j = 0; j < 4; j++)
                    wmma::mma_sync(acc[i][j], af[i], bf_[j], acc[i][j]);
        }
#pragma unroll
        for (int i = 0; i < 2; i++)
#pragma unroll
            for (int j = 0; j < 4; j++) {
                wmma::store_matrix_sync(&tb[wid][0], acc[i][j], 20, wmma::mem_row_major);
                __syncwarp();
                const int c = lane >> 1;           // w' within tile
                const int r0 = (lane & 1) * 8;     // dv start
                __half2 p[4];
#pragma unroll
                for (int t = 0; t < 4; t++) {
                    p[t].x = to_h(tb[wid][(r0 + t * 2) * 20 + c]);
                    p[t].y = to_h(tb[wid][(r0 + t * 2 + 1) * 20 + c]);
                }
                *reinterpret_cast<uint4*>(dstb + (size_t)(j * 16 + c) * 256 + i * 16 + r0) =
                    *reinterpret_cast<uint4*>(p);
                __syncwarp();
            }
    }
}

// ---------------------------------------------------------------------------
// Launch
// ---------------------------------------------------------------------------
extern "C" void kernel_launch(void* const* d_in, const int* in_sizes, int n_in,
                              void* d_out, int out_size)
{
    const float* x       = (const float*)d_in[0];
    const float* dw_qh_w = (const float*)d_in[1];
    const float* dw_qh_b = (const float*)d_in[2];
    const float* fc_qh_w = (const float*)d_in[3];
    const float* fc_qh_b = (const float*)d_in[4];
    const float* dw_kh_w = (const float*)d_in[5];
    const float* dw_kh_b = (const float*)d_in[6];
    const float* fc_kh_w = (const float*)d_in[7];
    const float* fc_kh_b = (const float*)d_in[8];
    const float* Bh      = (const float*)d_in[9];
    const float* dw_v_w  = (const float*)d_in[10];
    const float* dw_v_b  = (const float*)d_in[11];
    const float* fc_v_w  = (const float*)d_in[12];
    const float* fc_v_b  = (const float*)d_in[13];
    const float* dw_qw_w = (const float*)d_in[14];
    const float* dw_qw_b = (const float*)d_in[15];
    const float* fc_qw_w = (const float*)d_in[16];
    const float* fc_qw_b = (const float*)d_in[17];
    const float* dw_kw_w = (const float*)d_in[18];
    const float* dw_kw_b = (const float*)d_in[19];
    const float* fc_kw_w = (const float*)d_in[20];
    const float* fc_kw_b = (const float*)d_in[21];
    const float* Bw      = (const float*)d_in[22];
    const float* fc_o_w  = (const float*)d_in[23];
    const float* fc_o_b  = (const float*)d_in[24];
    float* out = (float*)d_out;

    // conv + pooled branches + weight rounding in one launch
    conv_fused_kernel<<<dim3(Cc, Bb + 1), 256>>>(
        x, dw_v_w, dw_v_b,
        dw_qh_w, dw_qh_b, dw_kh_w, dw_kh_b,
        dw_qw_w, dw_qw_b, dw_kw_w, dw_kw_b,
        fc_qh_w, fc_kh_w, fc_qw_w, fc_kw_w, fc_v_w, fc_o_w);

    // combined V GEMM (z<16) + q/k GEMMs (z==16)
    wmma_gemm_kernel<1><<<dim3(64, 2, Bb + 1), 128>>>(
        fc_qh_b, fc_kh_b, fc_qw_b, fc_kw_b, fc_v_b, nullptr);

    attn_kernel<<<dim3(Bb * Hh, 2), 256>>>(Bh, Bw);

    axial_fused_kernel<<<dim3(4, Bb * Hh), 512>>>();

    wmma_gemm_kernel<2><<<dim3(64, 2, Bb), 128>>>(
        fc_o_b, fc_o_b, fc_o_b, fc_o_b, fc_o_b, out);
}

// round 12
// speedup vs baseline: 4.6380x; 1.2215x over previous
#include <cuda_runtime.h>
#include <cuda_fp16.h>
#include <mma.h>
#include <cstdint>

using namespace nvcuda;

#define Bb 16
#define Cc 256
#define Ss 64
#define Hh 8
#define Dd 32

typedef __half hf;

// ---------------------------------------------------------------------------
// Scratch (all intermediates fp16, rounded at producers; fp32 accum in MMA)
// ---------------------------------------------------------------------------
__device__ hf g_pool[4][Cc * Bb * Ss];               // [c][b*64+s]  (A^T)
__device__ hf g_qkh[4][Bb * Hh * Ss * Dd];           // [b][head][s][d]
__device__ hf g_attn[2][Bb * Hh * Ss * Ss];
__device__ hf g_vconv[(size_t)Bb * Cc * 4096];       // [b][c][hw] (A^T)
__device__ hf g_v[(size_t)Bb * Hh * 4096 * 32];      // [b][head][hw][dv]
__device__ hf g_r[(size_t)Bb * Hh * Ss * Ss * Dd];   // [b][head][h][w*32+dv]
__device__ hf g_r2[(size_t)Bb * 4096 * Cc];          // [b][m=hw][k]
__device__ hf g_wh[6][Cc * Cc];                      // pre-rounded weights

__device__ __forceinline__ hf to_h(float x) { return __float2half_rn(x); }

__device__ __forceinline__ void cp_async16(void* smem, const void* gmem) {
    uint32_t s = (uint32_t)__cvta_generic_to_shared(smem);
    asm volatile("cp.async.cg.shared.global [%0], [%1], 16;" :: "r"(s), "l"(gmem));
}
#define CP_COMMIT() asm volatile("cp.async.commit_group;" ::: "memory")
#define CP_WAIT(n)  asm volatile("cp.async.wait_group %0;" :: "n"(n) : "memory")

// ---------------------------------------------------------------------------
// Kernel 1: fused V dwconv + analytic pooled q/k branches + weight rounding.
// Grid (256, 17): y<16 = conv blocks (c, b); y==16 = weight-rounding blocks.
// ---------------------------------------------------------------------------
__global__ void __launch_bounds__(256) conv_fused_kernel(
    const float* __restrict__ x,
    const float* __restrict__ wv,  const float* __restrict__ bv,
    const float* __restrict__ wqh, const float* __restrict__ bqh,
    const float* __restrict__ wkh, const float* __restrict__ bkh,
    const float* __restrict__ wqw, const float* __restrict__ bqw,
    const float* __restrict__ wkw, const float* __restrict__ bkw,
    const float* __restrict__ fqh, const float* __restrict__ fkh,
    const float* __restrict__ fqw, const float* __restrict__ fkw,
    const float* __restrict__ fv,  const float* __restrict__ fo)
{
    const int tid = threadIdx.x;

    if (blockIdx.y == Bb) {
        const int i = blockIdx.x * 256 + tid;
        g_wh[0][i] = to_h(fqh[i]);
        g_wh[1][i] = to_h(fkh[i]);
        g_wh[2][i] = to_h(fqw[i]);
        g_wh[3][i] = to_h(fkw[i]);
        g_wh[4][i] = to_h(fv[i]);
        g_wh[5][i] = to_h(fo[i]);
        return;
    }

    const int c = blockIdx.x;
    const int b = blockIdx.y;

    __shared__ float xs[66][66];
    __shared__ float rowp[2][64], colp[4][64];
    __shared__ float T[64];
    __shared__ float wsm[4][9];
    __shared__ float bsm[4];

    for (int i = tid; i < 66 * 66; i += 256) (&xs[0][0])[i] = 0.f;
    __syncthreads();

    const float* xp = x + ((size_t)b * Cc + c) * 4096;
    for (int i = tid; i < 4096; i += 256) xs[(i >> 6) + 1][(i & 63) + 1] = xp[i];

    if (tid < 9)        wsm[0][tid]      = wqh[c * 9 + tid];
    else if (tid < 18)  wsm[1][tid - 9]  = wkh[c * 9 + tid - 9];
    else if (tid < 27)  wsm[2][tid - 18] = wqw[c * 9 + tid - 18];
    else if (tid < 36)  wsm[3][tid - 27] = wkw[c * 9 + tid - 27];
    if (tid == 36) bsm[0] = bqh[c];
    if (tid == 37) bsm[1] = bkh[c];
    if (tid == 38) bsm[2] = bqw[c];
    if (tid == 39) bsm[3] = bkw[c];

    float w[9];
#pragma unroll
    for (int i = 0; i < 9; i++) w[i] = wv[c * 9 + i];
    const float bias = bv[c];
    __syncthreads();

    const int wcol = tid & 63;
    const int hgrp = tid >> 6;
    hf* op = g_vconv + ((size_t)b * Cc + c) * 4096;

    float colacc = 0.f;
    for (int k = 0; k < 16; k++) {
        const int h = hgrp * 16 + k;
        float s = bias;
#pragma unroll
        for (int dy = 0; dy < 3; dy++)
#pragma unroll
            for (int dx = 0; dx < 3; dx++)
                s += w[dy * 3 + dx] * xs[h + dy][wcol + dx];
        op[h * 64 + wcol] = to_h(s);
        const float v = xs[h + 1][wcol + 1];
        colacc += v;
        float rsum = v;
#pragma unroll
        for (int off = 16; off; off >>= 1)
            rsum += __shfl_down_sync(0xffffffffu, rsum, off);
        if ((tid & 31) == 0) rowp[(tid >> 5) & 1][h] = rsum;
    }
    colp[hgrp][wcol] = colacc;
    __syncthreads();
    if (tid < 64) T[tid] = colp[0][tid] + colp[1][tid] + colp[2][tid] + colp[3][tid];
    __syncthreads();

    if (tid < 64) {
        const int s = tid;
        float o0 = 0.f, o1 = 0.f, o2 = 0.f, o3 = 0.f;
#pragma unroll
        for (int d = 0; d < 3; d++) {
            const int r = s + d - 1;
            if (r >= 0 && r < 64) {
                const float Sv = rowp[0][r] + rowp[1][r];
                const float eL = xs[r + 1][1], eR = xs[r + 1][64];
                o0 += (wsm[0][d*3] + wsm[0][d*3+1] + wsm[0][d*3+2]) * Sv
                    - wsm[0][d*3] * eR - wsm[0][d*3+2] * eL;
                o1 += (wsm[1][d*3] + wsm[1][d*3+1] + wsm[1][d*3+2]) * Sv
                    - wsm[1][d*3] * eR - wsm[1][d*3+2] * eL;
                const float Tv = T[r];
                const float eT = xs[1][r + 1], eB = xs[64][r + 1];
                o2 += (wsm[2][d] + wsm[2][3+d] + wsm[2][6+d]) * Tv
                    - wsm[2][d] * eB - wsm[2][6+d] * eT;
                o3 += (wsm[3][d] + wsm[3][3+d] + wsm[3][6+d]) * Tv
                    - wsm[3][d] * eB - wsm[3][6+d] * eT;
            }
        }
        const float inv = 1.f / 64.f;
        const int mi = b * 64 + s;
        g_pool[0][c * 1024 + mi] = to_h(o0 * inv + bsm[0]);
        g_pool[1][c * 1024 + mi] = to_h(o1 * inv + bsm[1]);
        g_pool[2][c * 1024 + mi] = to_h(o2 * inv + bsm[2]);
        g_pool[3][c * 1024 + mi] = to_h(o3 * inv + bsm[3]);
    }
}

// ---------------------------------------------------------------------------
// Kernel 2: attention. Scores via fp16 wmma, low-register softmax.
// ---------------------------------------------------------------------------
__global__ void __launch_bounds__(256) attn_kernel(
    const float* __restrict__ Bh, const float* __restrict__ Bw)
{
    const int bh = blockIdx.x;
    const int head = bh & 7;
    const int axis = blockIdx.y;
    const float scale = 0.17677669529663687f;

    const hf* q = g_qkh[axis == 0 ? 0 : 2] + (size_t)bh * 2048;
    const hf* k = g_qkh[axis == 0 ? 1 : 3] + (size_t)bh * 2048;
    const float* Bm = ((axis == 0) ? Bh : Bw) + head * 4096;
    hf* o = g_attn[axis] + (size_t)bh * 4096;

    __shared__ float sc[64 * 68];

    {
        const int wid = threadIdx.x >> 5;
        const int wm = wid >> 1;
        const int wn = wid & 1;
        wmma::fragment<wmma::accumulator, 16, 16, 16, float> acc[2];
        wmma::fill_fragment(acc[0], 0.f);
        wmma::fill_fragment(acc[1], 0.f);
#pragma unroll
        for (int d0 = 0; d0 < 32; d0 += 16) {
            wmma::fragment<wmma::matrix_a, 16, 16, 16, half, wmma::row_major> af;
            wmma::load_matrix_sync(af, q + (size_t)(wm * 16) * 32 + d0, 32);
            wmma::fragment<wmma::matrix_b, 16, 16, 16, half, wmma::col_major> bf_[2];
            wmma::load_matrix_sync(bf_[0], k + (size_t)(wn * 32) * 32 + d0, 32);
            wmma::load_matrix_sync(bf_[1], k + (size_t)(wn * 32 + 16) * 32 + d0, 32);
            wmma::mma_sync(acc[0], af, bf_[0], acc[0]);
            wmma::mma_sync(acc[1], af, bf_[1], acc[1]);
        }
        wmma::store_matrix_sync(&sc[wm * 16 * 68 + wn * 32], acc[0], 68,
                                wmma::mem_row_major);
        wmma::store_matrix_sync(&sc[wm * 16 * 68 + wn * 32 + 16], acc[1], 68,
                                wmma::mem_row_major);
    }
    __syncthreads();

    {
        const int i = threadIdx.x >> 2;
        const int qq = threadIdx.x & 3;
        float s[16];
        float mx = -1e30f;
#pragma unroll
        for (int jj = 0; jj < 16; jj += 4) {
            const int j = qq * 16 + jj;
            const float4 c4 = *reinterpret_cast<const float4*>(&sc[i * 68 + j]);
            const float4 b4 = *reinterpret_cast<const float4*>(&Bm[i * 64 + j]);
            s[jj + 0] = c4.x * scale + b4.x;
            s[jj + 1] = c4.y * scale + b4.y;
            s[jj + 2] = c4.z * scale + b4.z;
            s[jj + 3] = c4.w * scale + b4.w;
            mx = fmaxf(mx, fmaxf(fmaxf(s[jj], s[jj + 1]), fmaxf(s[jj + 2], s[jj + 3])));
        }
        mx = fmaxf(mx, __shfl_xor_sync(0xffffffffu, mx, 1));
        mx = fmaxf(mx, __shfl_xor_sync(0xffffffffu, mx, 2));
        float sum = 0.f;
#pragma unroll
        for (int jj = 0; jj < 16; jj++) { s[jj] = __expf(s[jj] - mx); sum += s[jj]; }
        sum += __shfl_xor_sync(0xffffffffu, sum, 1);
        sum += __shfl_xor_sync(0xffffffffu, sum, 2);
        const float r = 1.f / sum;
#pragma unroll
        for (int jj = 0; jj < 16; jj += 4) {
            const int j = qq * 16 + jj;
            __half2 lo, hi;
            lo.x = to_h(s[jj + 0] * r); lo.y = to_h(s[jj + 1] * r);
            hi.x = to_h(s[jj + 2] * r); hi.y = to_h(s[jj + 3] * r);
            uint2 pk;
            pk.x = *reinterpret_cast<uint32_t*>(&lo);
            pk.y = *reinterpret_cast<uint32_t*>(&hi);
            *reinterpret_cast<uint2*>(&o[i * 64 + j]) = pk;
        }
    }
}

// ---------------------------------------------------------------------------
// Unified fp16 wmma GEMM, cp.async double buffered, BK=64 (4 iterations).
// ---------------------------------------------------------------------------
#define APB 4608            // A elems per buffer (64 x 72)
#define WPB 9216            // W elems per buffer (128 x 72)

template <int MODE>
__global__ void __launch_bounds__(128, 3) wmma_gemm_kernel(
    const float* __restrict__ b0, const float* __restrict__ b1,
    const float* __restrict__ b2, const float* __restrict__ b3,
    const float* __restrict__ bv, float* __restrict__ outp)
{
    __shared__ __align__(16) unsigned char smem_raw[2 * APB * 2 + 2 * WPB * 2 + 16 * 132 * 4];
    hf* Asm = reinterpret_cast<hf*>(smem_raw);
    hf* Wsm = reinterpret_cast<hf*>(smem_raw + 2 * APB * 2);
    float* sbias = reinterpret_cast<float*>(smem_raw + 2 * APB * 2 + 2 * WPB * 2);
    float* Cs = reinterpret_cast<float*>(smem_raw);

    const int tid = threadIdx.x;
    const int wid = tid >> 5;
    const int wm = wid >> 1;
    const int wn = wid & 1;
    const int nb = blockIdx.y * 128;
    const int z = blockIdx.z;

    const hf* A;
    const hf* W;
    const float* bias;
    int ldA, m0;
    bool isqk = false;
    int qkbr = 0;
    if constexpr (MODE == 1) {
        if (z < 16) {
            A = g_vconv + (size_t)z * 1048576; ldA = 4096;
            W = g_wh[4]; bias = bv; m0 = blockIdx.x * 64;
        } else {
            isqk = true;
            qkbr = blockIdx.x >> 4;
            A = g_pool[qkbr]; ldA = 1024;
            W = g_wh[qkbr];
            bias = (qkbr == 0) ? b0 : (qkbr == 1) ? b1 : (qkbr == 2) ? b2 : b3;
            m0 = (blockIdx.x & 15) * 64;
        }
    } else {
        A = g_r2 + (size_t)z * 1048576; ldA = 256;
        W = g_wh[5]; bias = b0; m0 = blockIdx.x * 64;
    }

    auto load_tiles = [&](int k0, int buf) {
        hf* As = Asm + buf * APB;
        hf* Ws = Wsm + buf * WPB;
#pragma unroll
        for (int i = 0; i < 4; i++) {
            const int f = tid + 128 * i;
            if constexpr (MODE == 1) {
                const int k = f >> 3, mq = f & 7;
                cp_async16(As + k * 72 + mq * 8,
                           A + (size_t)(k0 + k) * ldA + m0 + mq * 8);
            } else {
                const int m = f >> 3, kq = f & 7;
                cp_async16(As + m * 72 + kq * 8,
                           A + (size_t)(m0 + m) * 256 + k0 + kq * 8);
            }
        }
#pragma unroll
        for (int i = 0; i < 8; i++) {
            const int f = tid + 128 * i;
            const int n = f >> 3, kq = f & 7;
            cp_async16(Ws + n * 72 + kq * 8,
                       W + (size_t)(nb + n) * 256 + k0 + kq * 8);
        }
        CP_COMMIT();
    };

    for (int i = tid; i < 16 * 128; i += 128)
        sbias[(i >> 7) * 132 + (i & 127)] = bias[nb + (i & 127)];

    load_tiles(0, 0);
    __syncthreads();

    wmma::fragment<wmma::accumulator, 16, 16, 16, float> acc[2][4];
#pragma unroll
    for (int i = 0; i < 2; i++)
#pragma unroll
        for (int j = 0; j < 4; j++)
            wmma::load_matrix_sync(acc[i][j], &sbias[wn * 64 + j * 16], 132,
                                   wmma::mem_row_major);
    __syncthreads();

    int buf = 0;
    for (int it = 0; it < 4; it++) {
        if (it < 3) load_tiles((it + 1) * 64, buf ^ 1);
        if (it < 3) { CP_WAIT(1); } else { CP_WAIT(0); }
        __syncthreads();

        hf* As = Asm + buf * APB;
        hf* Ws = Wsm + buf * WPB;
#pragma unroll
        for (int kk = 0; kk < 64; kk += 16) {
            wmma::fragment<wmma::matrix_b, 16, 16, 16, half, wmma::col_major> bf_[4];
#pragma unroll
            for (int j = 0; j < 4; j++)
                wmma::load_matrix_sync(bf_[j], &Ws[(wn * 64 + j * 16) * 72 + kk], 72);
            if constexpr (MODE == 1) {
                wmma::fragment<wmma::matrix_a, 16, 16, 16, half, wmma::col_major> af[2];
                wmma::load_matrix_sync(af[0], &As[kk * 72 + wm * 32], 72);
                wmma::load_matrix_sync(af[1], &As[kk * 72 + wm * 32 + 16], 72);
#pragma unroll
                for (int i = 0; i < 2; i++)
#pragma unroll
                    for (int j = 0; j < 4; j++)
                        wmma::mma_sync(acc[i][j], af[i], bf_[j], acc[i][j]);
            } else {
                wmma::fragment<wmma::matrix_a, 16, 16, 16, half, wmma::row_major> af[2];
                wmma::load_matrix_sync(af[0], &As[(wm * 32) * 72 + kk], 72);
                wmma::load_matrix_sync(af[1], &As[(wm * 32 + 16) * 72 + kk], 72);
#pragma unroll
                for (int i = 0; i < 2; i++)
#pragma unroll
                    for (int j = 0; j < 4; j++)
                        wmma::mma_sync(acc[i][j], af[i], bf_[j], acc[i][j]);
            }
        }
        __syncthreads();
        buf ^= 1;
    }

    if constexpr (MODE == 2) {
#pragma unroll
        for (int i = 0; i < 2; i++)
#pragma unroll
            for (int j = 0; j < 4; j++) {
                const int mg = m0 + wm * 32 + i * 16;
                const int ng = nb + wn * 64 + j * 16;
                wmma::store_matrix_sync(
                    outp + (size_t)z * 1048576 + (size_t)mg * 256 + ng,
                    acc[i][j], 256, wmma::mem_row_major);
            }
    } else {
#pragma unroll
        for (int i = 0; i < 2; i++)
#pragma unroll
            for (int j = 0; j < 4; j++)
                wmma::store_matrix_sync(&Cs[(wm * 32 + i * 16) * 132 + wn * 64 + j * 16],
                                        acc[i][j], 132, wmma::mem_row_major);
        __syncthreads();
#pragma unroll
        for (int i = 0; i < 16; i++) {
            const int f = tid + 128 * i;
            const int row = f >> 5;
            const int cq = f & 31;
            const float4 v = *reinterpret_cast<const float4*>(&Cs[row * 132 + cq * 4]);
            __half2 lo, hi;
            lo.x = to_h(v.x); lo.y = to_h(v.y);
            hi.x = to_h(v.z); hi.y = to_h(v.w);
            uint2 pk;
            pk.x = *reinterpret_cast<uint32_t*>(&lo);
            pk.y = *reinterpret_cast<uint32_t*>(&hi);
            const int mg = m0 + row;
            const int ng = nb + cq * 4;
            const int head = ng >> 5;
            hf* dst;
            if (isqk)
                dst = g_qkh[qkbr] + (size_t)(mg >> 6) * 16384 + (size_t)head * 2048
                    + (size_t)(mg & 63) * 32 + (ng & 31);
            else
                dst = g_v + (size_t)z * 1048576 + (size_t)head * 131072
                    + (size_t)mg * 32 + (ng & 31);
            *reinterpret_cast<uint2*>(dst) = pk;
        }
    }
}

// ---------------------------------------------------------------------------
// Kernel 4: axh — R[64][2048] = attn_h @ V per bh, smem-tiled.
// Grid (4 n-chunks, 128 bh), 512 threads = 16 warps (2m x 8n), tile 32x64.
// ---------------------------------------------------------------------------
__global__ void __launch_bounds__(512) axh_kernel()
{
    __shared__ hf Ah_s[64 * 72];         // 9.2 KB
    __shared__ hf Vs[64 * 520];          // 66.6 KB (also fp32 staging [64][260])
    const int bh = blockIdx.y;
    const int n0 = blockIdx.x * 512;
    const int tid = threadIdx.x;
    const int wid = tid >> 5;
    const int wm = wid >> 3;             // 0..1
    const int wn = wid & 7;              // 0..7

    // stage Ah (64x64) and V chunk (64x512), coalesced
    {
        const hf* Ag = g_attn[0] + (size_t)bh * 4096;
        const int row = tid >> 3, c8 = (tid & 7) * 8;
        *reinterpret_cast<uint4*>(&Ah_s[row * 72 + c8]) =
            *reinterpret_cast<const uint4*>(Ag + row * 64 + c8);
        const hf* Vg = g_v + (size_t)bh * 131072 + n0;
#pragma unroll
        for (int i = 0; i < 8; i++) {
            const int f = tid + 512 * i;
            const int r = f >> 6, cc = (f & 63) * 8;
            *reinterpret_cast<uint4*>(&Vs[r * 520 + cc]) =
                *reinterpret_cast<const uint4*>(Vg + (size_t)r * 2048 + cc);
        }
    }
    __syncthreads();

    wmma::fragment<wmma::accumulator, 16, 16, 16, float> acc[2][4];
#pragma unroll
    for (int i = 0; i < 2; i++)
#pragma unroll
        for (int j = 0; j < 4; j++) wmma::fill_fragment(acc[i][j], 0.f);

#pragma unroll
    for (int kk = 0; kk < 64; kk += 16) {
        wmma::fragment<wmma::matrix_a, 16, 16, 16, half, wmma::row_major> af[2];
        wmma::load_matrix_sync(af[0], &Ah_s[(wm * 32) * 72 + kk], 72);
        wmma::load_matrix_sync(af[1], &Ah_s[(wm * 32 + 16) * 72 + kk], 72);
        wmma::fragment<wmma::matrix_b, 16, 16, 16, half, wmma::row_major> bf_[4];
#pragma unroll
        for (int j = 0; j < 4; j++)
            wmma::load_matrix_sync(bf_[j], &Vs[kk * 520 + wn * 64 + j * 16], 520);
#pragma unroll
        for (int i = 0; i < 2; i++)
#pragma unroll
            for (int j = 0; j < 4; j++)
                wmma::mma_sync(acc[i][j], af[i], bf_[j], acc[i][j]);
    }
    __syncthreads();    // Vs dead -> staging

    // epilogue: 2 passes of 256 n-columns through fp32 staging in Vs
    float* St = reinterpret_cast<float*>(Vs);     // [64][260]
    hf* Rg = g_r + (size_t)bh * 131072;
#pragma unroll
    for (int p = 0; p < 2; p++) {
        if ((wn >> 2) == p) {
#pragma unroll
            for (int i = 0; i < 2; i++)
#pragma unroll
                for (int j = 0; j < 4; j++)
                    wmma::store_matrix_sync(
                        &St[(wm * 32 + i * 16) * 260 + (wn & 3) * 64 + j * 16],
                        acc[i][j], 260, wmma::mem_row_major);
        }
        __syncthreads();
#pragma unroll
        for (int i = 0; i < 4; i++) {
            const int f = tid + 512 * i;          // 2048 chunks of 8
            const int row = f >> 5, c8 = (f & 31) * 8;
            const float4 v0 = *reinterpret_cast<const float4*>(&St[row * 260 + c8]);
            const float4 v1 = *reinterpret_cast<const float4*>(&St[row * 260 + c8 + 4]);
            __half2 pk_[4];
            pk_[0].x = to_h(v0.x); pk_[0].y = to_h(v0.y);
            pk_[1].x = to_h(v0.z); pk_[1].y = to_h(v0.w);
            pk_[2].x = to_h(v1.x); pk_[2].y = to_h(v1.y);
            pk_[3].x = to_h(v1.z); pk_[3].y = to_h(v1.w);
            *reinterpret_cast<uint4*>(Rg + (size_t)row * 2048 + n0 + p * 256 + c8) =
                *reinterpret_cast<uint4*>(pk_);
        }
        __syncthreads();
    }
}

// ---------------------------------------------------------------------------
// Kernel 5: axw — per (bh, h): [32 dv][64 w'] = R[h]^T @ attn_w, smem-tiled.
// Grid (4 h-chunks, 128 bh), 512 threads = 16 warps, warp = one h.
// ---------------------------------------------------------------------------
__global__ void __launch_bounds__(512) axw_kernel()
{
    __shared__ hf Aw_s[64 * 72];         // 9.2 KB
    __shared__ hf Rs[16 * 2056];         // 64.25 KB (also fp32 staging)
    const int bh = blockIdx.y;
    const int hc = blockIdx.x;           // h chunk (16 h)
    const int tid = threadIdx.x;
    const int wid = tid >> 5;

    // stage Aw (64x64) and R chunk (16 rows of 2048), coalesced
    {
        const hf* Ag = g_attn[1] + (size_t)bh * 4096;
        const int row = tid >> 3, c8 = (tid & 7) * 8;
        *reinterpret_cast<uint4*>(&Aw_s[row * 72 + c8]) =
            *reinterpret_cast<const uint4*>(Ag + row * 64 + c8);
        const hf* Rg = g_r + (size_t)bh * 131072 + (size_t)(hc * 16) * 2048;
#pragma unroll
        for (int i = 0; i < 8; i++) {
            const int f = tid + 512 * i;          // 4096 chunks of 8
            const int hl = f >> 8, cc = (f & 255) * 8;
            *reinterpret_cast<uint4*>(&Rs[hl * 2056 + cc]) =
                *reinterpret_cast<const uint4*>(Rg + (size_t)hl * 2048 + cc);
        }
    }
    __syncthreads();

    // warp wid: A = Rs[wid] viewed col-major [dv=32][w=64] (ld 32)
    wmma::fragment<wmma::accumulator, 16, 16, 16, float> acc[2][4];
#pragma unroll
    for (int i = 0; i < 2; i++)
#pragma unroll
        for (int j = 0; j < 4; j++) wmma::fill_fragment(acc[i][j], 0.f);

    const hf* Ar = &Rs[wid * 2056];
#pragma unroll
    for (int kk = 0; kk < 64; kk += 16) {
        wmma::fragment<wmma::matrix_a, 16, 16, 16, half, wmma::col_major> af[2];
        wmma::load_matrix_sync(af[0], Ar + kk * 32, 32);
        wmma::load_matrix_sync(af[1], Ar + kk * 32 + 16, 32);
        wmma::fragment<wmma::matrix_b, 16, 16, 16, half, wmma::row_major> bf_[4];
#pragma unroll
        for (int j = 0; j < 4; j++)
            wmma::load_matrix_sync(bf_[j], &Aw_s[kk * 72 + j * 16], 72);
#pragma unroll
        for (int i = 0; i < 2; i++)
#pragma unroll
            for (int j = 0; j < 4; j++)
                wmma::mma_sync(acc[i][j], af[i], bf_[j], acc[i][j]);
    }
    __syncthreads();    // Rs dead -> staging

    // epilogue: 2 passes of 8 warps; stage col-major [w'][dv] (ld 32),
    // then coalesced convert+write (each output row = 32 contiguous dv).
    float* St = reinterpret_cast<float*>(Rs);     // 8 slices of [64][32] fp32
    hf* outb = g_r2 + (size_t)(bh >> 3) * 1048576 + (bh & 7) * 32;
#pragma unroll
    for (int p = 0; p < 2; p++) {
        if ((wid >> 3) == p) {
            float* sl = St + (wid & 7) * 2048;
#pragma unroll
            for (int i = 0; i < 2; i++)
#pragma unroll
                for (int j = 0; j < 4; j++)
                    wmma::store_matrix_sync(sl + (j * 16) * 32 + i * 16,
                                            acc[i][j], 32, wmma::mem_col_major);
        }
        __syncthreads();
#pragma unroll
        for (int i = 0; i < 4; i++) {
            const int f = tid + 512 * i;          // 2048 chunks of 8
            const int hl = f >> 8;                // 0..7 within pass
            const int rem = f & 255;
            const int wp = rem >> 2, d8 = (rem & 3) * 8;
            const float* src = St + hl * 2048 + wp * 32 + d8;
            const float4 v0 = *reinterpret_cast<const float4*>(src);
            const float4 v1 = *reinterpret_cast<const float4*>(src + 4);
            __half2 pk_[4];
            pk_[0].x = to_h(v0.x); pk_[0].y = to_h(v0.y);
            pk_[1].x = to_h(v0.z); pk_[1].y = to_h(v0.w);
            pk_[2].x = to_h(v1.x); pk_[2].y = to_h(v1.y);
            pk_[3].x = to_h(v1.z); pk_[3].y = to_h(v1.w);
            const int h = hc * 16 + p * 8 + hl;
            *reinterpret_cast<uint4*>(
                outb + (size_t)(h * 64 + wp) * 256 + d8) =
                *reinterpret_cast<uint4*>(pk_);
        }
        __syncthreads();
    }
}

// ---------------------------------------------------------------------------
// Launch
// ---------------------------------------------------------------------------
extern "C" void kernel_launch(void* const* d_in, const int* in_sizes, int n_in,
                              void* d_out, int out_size)
{
    const float* x       = (const float*)d_in[0];
    const float* dw_qh_w = (const float*)d_in[1];
    const float* dw_qh_b = (const float*)d_in[2];
    const float* fc_qh_w = (const float*)d_in[3];
    const float* fc_qh_b = (const float*)d_in[4];
    const float* dw_kh_w = (const float*)d_in[5];
    const float* dw_kh_b = (const float*)d_in[6];
    const float* fc_kh_w = (const float*)d_in[7];
    const float* fc_kh_b = (const float*)d_in[8];
    const float* Bh      = (const float*)d_in[9];
    const float* dw_v_w  = (const float*)d_in[10];
    const float* dw_v_b  = (const float*)d_in[11];
    const float* fc_v_w  = (const float*)d_in[12];
    const float* fc_v_b  = (const float*)d_in[13];
    const float* dw_qw_w = (const float*)d_in[14];
    const float* dw_qw_b = (const float*)d_in[15];
    const float* fc_qw_w = (const float*)d_in[16];
    const float* fc_qw_b = (const float*)d_in[17];
    const float* dw_kw_w = (const float*)d_in[18];
    const float* dw_kw_b = (const float*)d_in[19];
    const float* fc_kw_w = (const float*)d_in[20];
    const float* fc_kw_b = (const float*)d_in[21];
    const float* Bw      = (const float*)d_in[22];
    const float* fc_o_w  = (const float*)d_in[23];
    const float* fc_o_b  = (const float*)d_in[24];
    float* out = (float*)d_out;

    conv_fused_kernel<<<dim3(Cc, Bb + 1), 256>>>(
        x, dw_v_w, dw_v_b,
        dw_qh_w, dw_qh_b, dw_kh_w, dw_kh_b,
        dw_qw_w, dw_qw_b, dw_kw_w, dw_kw_b,
        fc_qh_w, fc_kh_w, fc_qw_w, fc_kw_w, fc_v_w, fc_o_w);

    wmma_gemm_kernel<1><<<dim3(64, 2, Bb + 1), 128>>>(
        fc_qh_b, fc_kh_b, fc_qw_b, fc_kw_b, fc_v_b, nullptr);

    attn_kernel<<<dim3(Bb * Hh, 2), 256>>>(Bh, Bw);

    axh_kernel<<<dim3(4, Bb * Hh), 512>>>();
    axw_kernel<<<dim3(4, Bb * Hh), 512>>>();

    wmma_gemm_kernel<2><<<dim3(64, 2, Bb), 128>>>(
        fc_o_b, fc_o_b, fc_o_b, fc_o_b, fc_o_b, out);
}

// round 13
// speedup vs baseline: 4.8196x; 1.0392x over previous
#include <cuda_runtime.h>
#include <cuda_fp16.h>
#include <mma.h>
#include <cstdint>

using namespace nvcuda;

#define Bb 16
#define Cc 256
#define Ss 64
#define Hh 8
#define Dd 32

typedef __half hf;

// ---------------------------------------------------------------------------
// Scratch (all intermediates fp16, rounded at producers; fp32 accum in MMA)
// ---------------------------------------------------------------------------
__device__ hf g_pool[4][Cc * Bb * Ss];               // [c][b*64+s]  (A^T)
__device__ hf g_qkh[4][Bb * Hh * Ss * Dd];           // [b][head][s][d]
__device__ hf g_attn[2][Bb * Hh * Ss * Ss];
__device__ hf g_vconv[(size_t)Bb * Cc * 4096];       // [b][c][hw] (A^T)
__device__ hf g_v[(size_t)Bb * Hh * 4096 * 32];      // [b][head][hw][dv]
__device__ hf g_r2[(size_t)Bb * 4096 * Cc];          // [b][m=hw][k]
__device__ hf g_wh[6][Cc * Cc];                      // pre-rounded weights

__device__ __forceinline__ hf to_h(float x) { return __float2half_rn(x); }

__device__ __forceinline__ void cp_async16(void* smem, const void* gmem) {
    uint32_t s = (uint32_t)__cvta_generic_to_shared(smem);
    asm volatile("cp.async.cg.shared.global [%0], [%1], 16;" :: "r"(s), "l"(gmem));
}
#define CP_COMMIT() asm volatile("cp.async.commit_group;" ::: "memory")
#define CP_WAIT(n)  asm volatile("cp.async.wait_group %0;" :: "n"(n) : "memory")

// ---------------------------------------------------------------------------
// Kernel 1: fused V dwconv + analytic pooled q/k branches + weight rounding.
// Grid (256, 17): y<16 = conv blocks (c, b); y==16 = weight-rounding blocks.
// ---------------------------------------------------------------------------
__global__ void __launch_bounds__(256) conv_fused_kernel(
    const float* __restrict__ x,
    const float* __restrict__ wv,  const float* __restrict__ bv,
    const float* __restrict__ wqh, const float* __restrict__ bqh,
    const float* __restrict__ wkh, const float* __restrict__ bkh,
    const float* __restrict__ wqw, const float* __restrict__ bqw,
    const float* __restrict__ wkw, const float* __restrict__ bkw,
    const float* __restrict__ fqh, const float* __restrict__ fkh,
    const float* __restrict__ fqw, const float* __restrict__ fkw,
    const float* __restrict__ fv,  const float* __restrict__ fo)
{
    const int tid = threadIdx.x;

    if (blockIdx.y == Bb) {
        const int i = blockIdx.x * 256 + tid;
        g_wh[0][i] = to_h(fqh[i]);
        g_wh[1][i] = to_h(fkh[i]);
        g_wh[2][i] = to_h(fqw[i]);
        g_wh[3][i] = to_h(fkw[i]);
        g_wh[4][i] = to_h(fv[i]);
        g_wh[5][i] = to_h(fo[i]);
        return;
    }

    const int c = blockIdx.x;
    const int b = blockIdx.y;

    __shared__ float xs[66][66];
    __shared__ float rowp[2][64], colp[4][64];
    __shared__ float T[64];
    __shared__ float wsm[4][9];
    __shared__ float bsm[4];

    for (int i = tid; i < 66 * 66; i += 256) (&xs[0][0])[i] = 0.f;
    __syncthreads();

    // vectorized x load: 1024 float4 = 4096 floats
    const float4* xp4 = reinterpret_cast<const float4*>(x + ((size_t)b * Cc + c) * 4096);
    for (int i = tid; i < 1024; i += 256) {
        const float4 v = xp4[i];
        const int e = i * 4;
        float* d = &xs[(e >> 6) + 1][(e & 63) + 1];
        d[0] = v.x; d[1] = v.y; d[2] = v.z; d[3] = v.w;
    }

    if (tid < 9)        wsm[0][tid]      = wqh[c * 9 + tid];
    else if (tid < 18)  wsm[1][tid - 9]  = wkh[c * 9 + tid - 9];
    else if (tid < 27)  wsm[2][tid - 18] = wqw[c * 9 + tid - 18];
    else if (tid < 36)  wsm[3][tid - 27] = wkw[c * 9 + tid - 27];
    if (tid == 36) bsm[0] = bqh[c];
    if (tid == 37) bsm[1] = bkh[c];
    if (tid == 38) bsm[2] = bqw[c];
    if (tid == 39) bsm[3] = bkw[c];

    float w[9];
#pragma unroll
    for (int i = 0; i < 9; i++) w[i] = wv[c * 9 + i];
    const float bias = bv[c];
    __syncthreads();

    const int wcol = tid & 63;
    const int hgrp = tid >> 6;
    hf* op = g_vconv + ((size_t)b * Cc + c) * 4096;

    float colacc = 0.f;
    for (int k = 0; k < 16; k++) {
        const int h = hgrp * 16 + k;
        float s = bias;
#pragma unroll
        for (int dy = 0; dy < 3; dy++)
#pragma unroll
            for (int dx = 0; dx < 3; dx++)
                s += w[dy * 3 + dx] * xs[h + dy][wcol + dx];
        op[h * 64 + wcol] = to_h(s);
        const float v = xs[h + 1][wcol + 1];
        colacc += v;
        float rsum = v;
#pragma unroll
        for (int off = 16; off; off >>= 1)
            rsum += __shfl_down_sync(0xffffffffu, rsum, off);
        if ((tid & 31) == 0) rowp[(tid >> 5) & 1][h] = rsum;
    }
    colp[hgrp][wcol] = colacc;
    __syncthreads();
    if (tid < 64) T[tid] = colp[0][tid] + colp[1][tid] + colp[2][tid] + colp[3][tid];
    __syncthreads();

    if (tid < 64) {
        const int s = tid;
        float o0 = 0.f, o1 = 0.f, o2 = 0.f, o3 = 0.f;
#pragma unroll
        for (int d = 0; d < 3; d++) {
            const int r = s + d - 1;
            if (r >= 0 && r < 64) {
                const float Sv = rowp[0][r] + rowp[1][r];
                const float eL = xs[r + 1][1], eR = xs[r + 1][64];
                o0 += (wsm[0][d*3] + wsm[0][d*3+1] + wsm[0][d*3+2]) * Sv
                    - wsm[0][d*3] * eR - wsm[0][d*3+2] * eL;
                o1 += (wsm[1][d*3] + wsm[1][d*3+1] + wsm[1][d*3+2]) * Sv
                    - wsm[1][d*3] * eR - wsm[1][d*3+2] * eL;
                const float Tv = T[r];
                const float eT = xs[1][r + 1], eB = xs[64][r + 1];
                o2 += (wsm[2][d] + wsm[2][3+d] + wsm[2][6+d]) * Tv
                    - wsm[2][d] * eB - wsm[2][6+d] * eT;
                o3 += (wsm[3][d] + wsm[3][3+d] + wsm[3][6+d]) * Tv
                    - wsm[3][d] * eB - wsm[3][6+d] * eT;
            }
        }
        const float inv = 1.f / 64.f;
        const int mi = b * 64 + s;
        g_pool[0][c * 1024 + mi] = to_h(o0 * inv + bsm[0]);
        g_pool[1][c * 1024 + mi] = to_h(o1 * inv + bsm[1]);
        g_pool[2][c * 1024 + mi] = to_h(o2 * inv + bsm[2]);
        g_pool[3][c * 1024 + mi] = to_h(o3 * inv + bsm[3]);
    }
}

// ---------------------------------------------------------------------------
// Kernel 2: attention. Scores via fp16 wmma, low-register softmax.
// ---------------------------------------------------------------------------
__global__ void __launch_bounds__(256) attn_kernel(
    const float* __restrict__ Bh, const float* __restrict__ Bw)
{
    const int bh = blockIdx.x;
    const int head = bh & 7;
    const int axis = blockIdx.y;
    const float scale = 0.17677669529663687f;

    const hf* q = g_qkh[axis == 0 ? 0 : 2] + (size_t)bh * 2048;
    const hf* k = g_qkh[axis == 0 ? 1 : 3] + (size_t)bh * 2048;
    const float* Bm = ((axis == 0) ? Bh : Bw) + head * 4096;
    hf* o = g_attn[axis] + (size_t)bh * 4096;

    __shared__ float sc[64 * 68];

    {
        const int wid = threadIdx.x >> 5;
        const int wm = wid >> 1;
        const int wn = wid & 1;
        wmma::fragment<wmma::accumulator, 16, 16, 16, float> acc[2];
        wmma::fill_fragment(acc[0], 0.f);
        wmma::fill_fragment(acc[1], 0.f);
#pragma unroll
        for (int d0 = 0; d0 < 32; d0 += 16) {
            wmma::fragment<wmma::matrix_a, 16, 16, 16, half, wmma::row_major> af;
            wmma::load_matrix_sync(af, q + (size_t)(wm * 16) * 32 + d0, 32);
            wmma::fragment<wmma::matrix_b, 16, 16, 16, half, wmma::col_major> bf_[2];
            wmma::load_matrix_sync(bf_[0], k + (size_t)(wn * 32) * 32 + d0, 32);
            wmma::load_matrix_sync(bf_[1], k + (size_t)(wn * 32 + 16) * 32 + d0, 32);
            wmma::mma_sync(acc[0], af, bf_[0], acc[0]);
            wmma::mma_sync(acc[1], af, bf_[1], acc[1]);
        }
        wmma::store_matrix_sync(&sc[wm * 16 * 68 + wn * 32], acc[0], 68,
                                wmma::mem_row_major);
        wmma::store_matrix_sync(&sc[wm * 16 * 68 + wn * 32 + 16], acc[1], 68,
                                wmma::mem_row_major);
    }
    __syncthreads();

    {
        const int i = threadIdx.x >> 2;
        const int qq = threadIdx.x & 3;
        float s[16];
        float mx = -1e30f;
#pragma unroll
        for (int jj = 0; jj < 16; jj += 4) {
            const int j = qq * 16 + jj;
            const float4 c4 = *reinterpret_cast<const float4*>(&sc[i * 68 + j]);
            const float4 b4 = *reinterpret_cast<const float4*>(&Bm[i * 64 + j]);
            s[jj + 0] = c4.x * scale + b4.x;
            s[jj + 1] = c4.y * scale + b4.y;
            s[jj + 2] = c4.z * scale + b4.z;
            s[jj + 3] = c4.w * scale + b4.w;
            mx = fmaxf(mx, fmaxf(fmaxf(s[jj], s[jj + 1]), fmaxf(s[jj + 2], s[jj + 3])));
        }
        mx = fmaxf(mx, __shfl_xor_sync(0xffffffffu, mx, 1));
        mx = fmaxf(mx, __shfl_xor_sync(0xffffffffu, mx, 2));
        float sum = 0.f;
#pragma unroll
        for (int jj = 0; jj < 16; jj++) { s[jj] = __expf(s[jj] - mx); sum += s[jj]; }
        sum += __shfl_xor_sync(0xffffffffu, sum, 1);
        sum += __shfl_xor_sync(0xffffffffu, sum, 2);
        const float r = 1.f / sum;
#pragma unroll
        for (int jj = 0; jj < 16; jj += 4) {
            const int j = qq * 16 + jj;
            __half2 lo, hi;
            lo.x = to_h(s[jj + 0] * r); lo.y = to_h(s[jj + 1] * r);
            hi.x = to_h(s[jj + 2] * r); hi.y = to_h(s[jj + 3] * r);
            uint2 pk;
            pk.x = *reinterpret_cast<uint32_t*>(&lo);
            pk.y = *reinterpret_cast<uint32_t*>(&hi);
            *reinterpret_cast<uint2*>(&o[i * 64 + j]) = pk;
        }
    }
}

// ---------------------------------------------------------------------------
// Unified fp16 wmma GEMM, cp.async double buffered, BK=64 (4 iterations).
// ---------------------------------------------------------------------------
#define APB 4608            // A elems per buffer (64 x 72)
#define WPB 9216            // W elems per buffer (128 x 72)

template <int MODE>
__global__ void __launch_bounds__(128, 3) wmma_gemm_kernel(
    const float* __restrict__ b0, const float* __restrict__ b1,
    const float* __restrict__ b2, const float* __restrict__ b3,
    const float* __restrict__ bv, float* __restrict__ outp)
{
    __shared__ __align__(16) unsigned char smem_raw[2 * APB * 2 + 2 * WPB * 2 + 16 * 132 * 4];
    hf* Asm = reinterpret_cast<hf*>(smem_raw);
    hf* Wsm = reinterpret_cast<hf*>(smem_raw + 2 * APB * 2);
    float* sbias = reinterpret_cast<float*>(smem_raw + 2 * APB * 2 + 2 * WPB * 2);
    float* Cs = reinterpret_cast<float*>(smem_raw);

    const int tid = threadIdx.x;
    const int wid = tid >> 5;
    const int wm = wid >> 1;
    const int wn = wid & 1;
    const int nb = blockIdx.y * 128;
    const int z = blockIdx.z;

    const hf* A;
    const hf* W;
    const float* bias;
    int ldA, m0;
    bool isqk = false;
    int qkbr = 0;
    if constexpr (MODE == 1) {
        if (z < 16) {
            A = g_vconv + (size_t)z * 1048576; ldA = 4096;
            W = g_wh[4]; bias = bv; m0 = blockIdx.x * 64;
        } else {
            isqk = true;
            qkbr = blockIdx.x >> 4;
            A = g_pool[qkbr]; ldA = 1024;
            W = g_wh[qkbr];
            bias = (qkbr == 0) ? b0 : (qkbr == 1) ? b1 : (qkbr == 2) ? b2 : b3;
            m0 = (blockIdx.x & 15) * 64;
        }
    } else {
        A = g_r2 + (size_t)z * 1048576; ldA = 256;
        W = g_wh[5]; bias = b0; m0 = blockIdx.x * 64;
    }

    auto load_tiles = [&](int k0, int buf) {
        hf* As = Asm + buf * APB;
        hf* Ws = Wsm + buf * WPB;
#pragma unroll
        for (int i = 0; i < 4; i++) {
            const int f = tid + 128 * i;
            if constexpr (MODE == 1) {
                const int k = f >> 3, mq = f & 7;
                cp_async16(As + k * 72 + mq * 8,
                           A + (size_t)(k0 + k) * ldA + m0 + mq * 8);
            } else {
                const int m = f >> 3, kq = f & 7;
                cp_async16(As + m * 72 + kq * 8,
                           A + (size_t)(m0 + m) * 256 + k0 + kq * 8);
            }
        }
#pragma unroll
        for (int i = 0; i < 8; i++) {
            const int f = tid + 128 * i;
            const int n = f >> 3, kq = f & 7;
            cp_async16(Ws + n * 72 + kq * 8,
                       W + (size_t)(nb + n) * 256 + k0 + kq * 8);
        }
        CP_COMMIT();
    };

    for (int i = tid; i < 16 * 128; i += 128)
        sbias[(i >> 7) * 132 + (i & 127)] = bias[nb + (i & 127)];

    load_tiles(0, 0);
    __syncthreads();

    wmma::fragment<wmma::accumulator, 16, 16, 16, float> acc[2][4];
#pragma unroll
    for (int i = 0; i < 2; i++)
#pragma unroll
        for (int j = 0; j < 4; j++)
            wmma::load_matrix_sync(acc[i][j], &sbias[wn * 64 + j * 16], 132,
                                   wmma::mem_row_major);
    __syncthreads();

    int buf = 0;
    for (int it = 0; it < 4; it++) {
        if (it < 3) load_tiles((it + 1) * 64, buf ^ 1);
        if (it < 3) { CP_WAIT(1); } else { CP_WAIT(0); }
        __syncthreads();

        hf* As = Asm + buf * APB;
        hf* Ws = Wsm + buf * WPB;
#pragma unroll
        for (int kk = 0; kk < 64; kk += 16) {
            wmma::fragment<wmma::matrix_b, 16, 16, 16, half, wmma::col_major> bf_[4];
#pragma unroll
            for (int j = 0; j < 4; j++)
                wmma::load_matrix_sync(bf_[j], &Ws[(wn * 64 + j * 16) * 72 + kk], 72);
            if constexpr (MODE == 1) {
                wmma::fragment<wmma::matrix_a, 16, 16, 16, half, wmma::col_major> af[2];
                wmma::load_matrix_sync(af[0], &As[kk * 72 + wm * 32], 72);
                wmma::load_matrix_sync(af[1], &As[kk * 72 + wm * 32 + 16], 72);
#pragma unroll
                for (int i = 0; i < 2; i++)
#pragma unroll
                    for (int j = 0; j < 4; j++)
                        wmma::mma_sync(acc[i][j], af[i], bf_[j], acc[i][j]);
            } else {
                wmma::fragment<wmma::matrix_a, 16, 16, 16, half, wmma::row_major> af[2];
                wmma::load_matrix_sync(af[0], &As[(wm * 32) * 72 + kk], 72);
                wmma::load_matrix_sync(af[1], &As[(wm * 32 + 16) * 72 + kk], 72);
#pragma unroll
                for (int i = 0; i < 2; i++)
#pragma unroll
                    for (int j = 0; j < 4; j++)
                        wmma::mma_sync(acc[i][j], af[i], bf_[j], acc[i][j]);
            }
        }
        __syncthreads();
        buf ^= 1;
    }

    if constexpr (MODE == 2) {
#pragma unroll
        for (int i = 0; i < 2; i++)
#pragma unroll
            for (int j = 0; j < 4; j++) {
                const int mg = m0 + wm * 32 + i * 16;
                const int ng = nb + wn * 64 + j * 16;
                wmma::store_matrix_sync(
                    outp + (size_t)z * 1048576 + (size_t)mg * 256 + ng,
                    acc[i][j], 256, wmma::mem_row_major);
            }
    } else {
#pragma unroll
        for (int i = 0; i < 2; i++)
#pragma unroll
            for (int j = 0; j < 4; j++)
                wmma::store_matrix_sync(&Cs[(wm * 32 + i * 16) * 132 + wn * 64 + j * 16],
                                        acc[i][j], 132, wmma::mem_row_major);
        __syncthreads();
#pragma unroll
        for (int i = 0; i < 16; i++) {
            const int f = tid + 128 * i;
            const int row = f >> 5;
            const int cq = f & 31;
            const float4 v = *reinterpret_cast<const float4*>(&Cs[row * 132 + cq * 4]);
            __half2 lo, hi;
            lo.x = to_h(v.x); lo.y = to_h(v.y);
            hi.x = to_h(v.z); hi.y = to_h(v.w);
            uint2 pk;
            pk.x = *reinterpret_cast<uint32_t*>(&lo);
            pk.y = *reinterpret_cast<uint32_t*>(&hi);
            const int mg = m0 + row;
            const int ng = nb + cq * 4;
            const int head = ng >> 5;
            hf* dst;
            if (isqk)
                dst = g_qkh[qkbr] + (size_t)(mg >> 6) * 16384 + (size_t)head * 2048
                    + (size_t)(mg & 63) * 32 + (ng & 31);
            else
                dst = g_v + (size_t)z * 1048576 + (size_t)head * 131072
                    + (size_t)mg * 32 + (ng & 31);
            *reinterpret_cast<uint2*>(dst) = pk;
        }
    }
}

// ---------------------------------------------------------------------------
// Kernel 4: fused axial mixing with smem discipline.
// Block = (hc: 16-h chunk, bh), 512 threads = 16 warps.
// Stage 1: R16[16][2048] = attn_h[16 rows] @ V, streaming V in 8 smem chunks
//          of [64][256]; fp32 accum, fp16 R16 in smem. (g_r eliminated.)
// Stage 2: warp = one h: [32dv][64w'] = R16[h]^T @ attn_w -> g_r2.
// ---------------------------------------------------------------------------
__global__ void __launch_bounds__(512) axial2_kernel()
{
    __shared__ hf Ah_s[16 * 72];          // 2.3 KB  (attn_h slice)
    __shared__ hf Aw_s[64 * 72];          // 9.2 KB
    __shared__ hf R16[16 * 2056];         // 65.8 KB
    __shared__ hf Vs[64 * 264];           // 33.8 KB (stage-2 fp32 staging too)
    __shared__ float St[16 * 320];        // 20.5 KB (stage-1 per-warp staging)

    const int bh = blockIdx.y;
    const int hc = blockIdx.x;
    const int tid = threadIdx.x;
    const int wid = tid >> 5;
    const int lane = tid & 31;

    // stage attn_h slice (16x64) + attn_w (64x64)
    {
        const hf* Ahg = g_attn[0] + (size_t)bh * 4096 + (size_t)(hc * 16) * 64;
        if (tid < 128) {
            const int row = tid >> 3, c8 = (tid & 7) * 8;
            *reinterpret_cast<uint4*>(&Ah_s[row * 72 + c8]) =
                *reinterpret_cast<const uint4*>(Ahg + row * 64 + c8);
        }
        const hf* Awg = g_attn[1] + (size_t)bh * 4096;
        const int row = tid >> 3, c8 = (tid & 7) * 8;
        *reinterpret_cast<uint4*>(&Aw_s[row * 72 + c8]) =
            *reinterpret_cast<const uint4*>(Awg + row * 64 + c8);
    }
    __syncthreads();

    // ---- stage 1: 8 chunks of 256 n-cols; warp wid owns cols wid*16..+16
    const hf* Vg = g_v + (size_t)bh * 131072;
    for (int ch = 0; ch < 8; ch++) {
        const int n0 = ch * 256;
        // load V chunk [64][256] coalesced
#pragma unroll
        for (int i = 0; i < 4; i++) {
            const int f = tid + 512 * i;          // 2048 chunks of 8
            const int r = f >> 5, c8 = (f & 31) * 8;
            *reinterpret_cast<uint4*>(&Vs[r * 264 + c8]) =
                *reinterpret_cast<const uint4*>(Vg + (size_t)r * 2048 + n0 + c8);
        }
        __syncthreads();

        wmma::fragment<wmma::accumulator, 16, 16, 16, float> acc;
        wmma::fill_fragment(acc, 0.f);
#pragma unroll
        for (int kk = 0; kk < 64; kk += 16) {
            wmma::fragment<wmma::matrix_a, 16, 16, 16, half, wmma::row_major> af;
            wmma::load_matrix_sync(af, &Ah_s[kk], 72);
            wmma::fragment<wmma::matrix_b, 16, 16, 16, half, wmma::row_major> bf_;
            wmma::load_matrix_sync(bf_, &Vs[kk * 264 + wid * 16], 264);
            wmma::mma_sync(acc, af, bf_, acc);
        }
        // convert into R16 via per-warp staging
        wmma::store_matrix_sync(&St[wid * 320], acc, 20, wmma::mem_row_major);
        __syncwarp();
        {
            const int r = lane >> 1;
            const int c0 = (lane & 1) * 8;
            __half2 p[4];
#pragma unroll
            for (int t = 0; t < 4; t++) {
                p[t].x = to_h(St[wid * 320 + r * 20 + c0 + t * 2]);
                p[t].y = to_h(St[wid * 320 + r * 20 + c0 + t * 2 + 1]);
            }
            *reinterpret_cast<uint4*>(&R16[r * 2056 + n0 + wid * 16 + c0]) =
                *reinterpret_cast<uint4*>(p);
        }
        __syncthreads();   // Vs reuse next chunk; R16 chunk visible
    }

    // ---- stage 2: warp wid = h-local; A = R16[wid] col-major [dv=32][w=64]
    wmma::fragment<wmma::accumulator, 16, 16, 16, float> acc2[2][4];
#pragma unroll
    for (int i = 0; i < 2; i++)
#pragma unroll
        for (int j = 0; j < 4; j++) wmma::fill_fragment(acc2[i][j], 0.f);

    const hf* Ar = &R16[wid * 2056];
#pragma unroll
    for (int kk = 0; kk < 64; kk += 16) {
        wmma::fragment<wmma::matrix_a, 16, 16, 16, half, wmma::col_major> af[2];
        wmma::load_matrix_sync(af[0], Ar + kk * 32, 32);
        wmma::load_matrix_sync(af[1], Ar + kk * 32 + 16, 32);
        wmma::fragment<wmma::matrix_b, 16, 16, 16, half, wmma::row_major> bf_[4];
#pragma unroll
        for (int j = 0; j < 4; j++)
            wmma::load_matrix_sync(bf_[j], &Aw_s[kk * 72 + j * 16], 72);
#pragma unroll
        for (int i = 0; i < 2; i++)
#pragma unroll
            for (int j = 0; j < 4; j++)
                wmma::mma_sync(acc2[i][j], af[i], bf_[j], acc2[i][j]);
    }
    __syncthreads();    // Vs dead -> stage-2 staging

    // epilogue: 4 passes of 4 warps; stage col-major [w'][dv] (ld 32)
    float* St2 = reinterpret_cast<float*>(Vs);      // 4 slices of [64][32] fp32
    hf* outb = g_r2 + (size_t)(bh >> 3) * 1048576 + (bh & 7) * 32;
#pragma unroll
    for (int p = 0; p < 4; p++) {
        if ((wid >> 2) == p) {
            float* sl = St2 + (wid & 3) * 2048;
#pragma unroll
            for (int i = 0; i < 2; i++)
#pragma unroll
                for (int j = 0; j < 4; j++)
                    wmma::store_matrix_sync(sl + (j * 16) * 32 + i * 16,
                                            acc2[i][j], 32, wmma::mem_col_major);
        }
        __syncthreads();
#pragma unroll
        for (int i = 0; i < 2; i++) {
            const int f = tid + 512 * i;          // 1024 chunks of 8
            const int hl = f >> 8;                // 0..3 within pass
            const int rem = f & 255;
            const int wp = rem >> 2, d8 = (rem & 3) * 8;
            const float* src = St2 + hl * 2048 + wp * 32 + d8;
            const float4 v0 = *reinterpret_cast<const float4*>(src);
            const float4 v1 = *reinterpret_cast<const float4*>(src + 4);
            __half2 pk_[4];
            pk_[0].x = to_h(v0.x); pk_[0].y = to_h(v0.y);
            pk_[1].x = to_h(v0.z); pk_[1].y = to_h(v0.w);
            pk_[2].x = to_h(v1.x); pk_[2].y = to_h(v1.y);
            pk_[3].x = to_h(v1.z); pk_[3].y = to_h(v1.w);
            const int h = hc * 16 + p * 4 + hl;
            *reinterpret_cast<uint4*>(
                outb + (size_t)(h * 64 + wp) * 256 + d8) =
                *reinterpret_cast<uint4*>(pk_);
        }
        __syncthreads();
    }
}

// ---------------------------------------------------------------------------
// Launch
// ---------------------------------------------------------------------------
extern "C" void kernel_launch(void* const* d_in, const int* in_sizes, int n_in,
                              void* d_out, int out_size)
{
    const float* x       = (const float*)d_in[0];
    const float* dw_qh_w = (const float*)d_in[1];
    const float* dw_qh_b = (const float*)d_in[2];
    const float* fc_qh_w = (const float*)d_in[3];
    const float* fc_qh_b = (const float*)d_in[4];
    const float* dw_kh_w = (const float*)d_in[5];
    const float* dw_kh_b = (const float*)d_in[6];
    const float* fc_kh_w = (const float*)d_in[7];
    const float* fc_kh_b = (const float*)d_in[8];
    const float* Bh      = (const float*)d_in[9];
    const float* dw_v_w  = (const float*)d_in[10];
    const float* dw_v_b  = (const float*)d_in[11];
    const float* fc_v_w  = (const float*)d_in[12];
    const float* fc_v_b  = (const float*)d_in[13];
    const float* dw_qw_w = (const float*)d_in[14];
    const float* dw_qw_b = (const float*)d_in[15];
    const float* fc_qw_w = (const float*)d_in[16];
    const float* fc_qw_b = (const float*)d_in[17];
    const float* dw_kw_w = (const float*)d_in[18];
    const float* dw_kw_b = (const float*)d_in[19];
    const float* fc_kw_w = (const float*)d_in[20];
    const float* fc_kw_b = (const float*)d_in[21];
    const float* Bw      = (const float*)d_in[22];
    const float* fc_o_w  = (const float*)d_in[23];
    const float* fc_o_b  = (const float*)d_in[24];
    float* out = (float*)d_out;

    conv_fused_kernel<<<dim3(Cc, Bb + 1), 256>>>(
        x, dw_v_w, dw_v_b,
        dw_qh_w, dw_qh_b, dw_kh_w, dw_kh_b,
        dw_qw_w, dw_qw_b, dw_kw_w, dw_kw_b,
        fc_qh_w, fc_kh_w, fc_qw_w, fc_kw_w, fc_v_w, fc_o_w);

    wmma_gemm_kernel<1><<<dim3(64, 2, Bb + 1), 128>>>(
        fc_qh_b, fc_kh_b, fc_qw_b, fc_kw_b, fc_v_b, nullptr);

    attn_kernel<<<dim3(Bb * Hh, 2), 256>>>(Bh, Bw);

    axial2_kernel<<<dim3(4, Bb * Hh), 512>>>();

    wmma_gemm_kernel<2><<<dim3(64, 2, Bb), 128>>>(
        fc_o_b, fc_o_b, fc_o_b, fc_o_b, fc_o_b, out);
}

// round 14
// speedup vs baseline: 5.1504x; 1.0686x over previous
#include <cuda_runtime.h>
#include <cuda_fp16.h>
#include <mma.h>
#include <cstdint>

using namespace nvcuda;

#define Bb 16
#define Cc 256
#define Ss 64
#define Hh 8
#define Dd 32

typedef __half hf;

// ---------------------------------------------------------------------------
// Scratch (all intermediates fp16, rounded at producers; fp32 accum in MMA)
// ---------------------------------------------------------------------------
__device__ hf g_pool[4][Cc * Bb * Ss];               // [c][b*64+s]  (A^T)
__device__ hf g_qkh[4][Bb * Hh * Ss * Dd];           // [b][head][s][d]
__device__ hf g_attn[2][Bb * Hh * Ss * Ss];
__device__ hf g_vconv[(size_t)Bb * Cc * 4096];       // [b][c][hw] (A^T)
__device__ hf g_v[(size_t)Bb * Hh * 4096 * 32];      // [b][head][hw][dv]
__device__ hf g_r[(size_t)Bb * Hh * Ss * Ss * Dd];   // [b][head][h][w*32+dv]
__device__ hf g_r2[(size_t)Bb * 4096 * Cc];          // [b][m=hw][k]
__device__ hf g_wh[6][Cc * Cc];                      // pre-rounded weights

__device__ __forceinline__ hf to_h(float x) { return __float2half_rn(x); }

__device__ __forceinline__ void cp_async16(void* smem, const void* gmem) {
    uint32_t s = (uint32_t)__cvta_generic_to_shared(smem);
    asm volatile("cp.async.cg.shared.global [%0], [%1], 16;" :: "r"(s), "l"(gmem));
}
#define CP_COMMIT() asm volatile("cp.async.commit_group;" ::: "memory")
#define CP_WAIT(n)  asm volatile("cp.async.wait_group %0;" :: "n"(n) : "memory")

// ---------------------------------------------------------------------------
// Kernel 1: fused V dwconv + analytic pooled q/k branches + weight rounding.
// Grid (256, 17): y<16 = conv blocks (c, b); y==16 = weight-rounding blocks.
// ---------------------------------------------------------------------------
__global__ void __launch_bounds__(256) conv_fused_kernel(
    const float* __restrict__ x,
    const float* __restrict__ wv,  const float* __restrict__ bv,
    const float* __restrict__ wqh, const float* __restrict__ bqh,
    const float* __restrict__ wkh, const float* __restrict__ bkh,
    const float* __restrict__ wqw, const float* __restrict__ bqw,
    const float* __restrict__ wkw, const float* __restrict__ bkw,
    const float* __restrict__ fqh, const float* __restrict__ fkh,
    const float* __restrict__ fqw, const float* __restrict__ fkw,
    const float* __restrict__ fv,  const float* __restrict__ fo)
{
    const int tid = threadIdx.x;

    if (blockIdx.y == Bb) {
        const int i = blockIdx.x * 256 + tid;
        g_wh[0][i] = to_h(fqh[i]);
        g_wh[1][i] = to_h(fkh[i]);
        g_wh[2][i] = to_h(fqw[i]);
        g_wh[3][i] = to_h(fkw[i]);
        g_wh[4][i] = to_h(fv[i]);
        g_wh[5][i] = to_h(fo[i]);
        return;
    }

    const int c = blockIdx.x;
    const int b = blockIdx.y;

    __shared__ float xs[66][66];
    __shared__ float rowp[2][64], colp[4][64];
    __shared__ float T[64];
    __shared__ float wsm[4][9];
    __shared__ float bsm[4];

    for (int i = tid; i < 66 * 66; i += 256) (&xs[0][0])[i] = 0.f;
    __syncthreads();

    const float4* xp4 = reinterpret_cast<const float4*>(x + ((size_t)b * Cc + c) * 4096);
    for (int i = tid; i < 1024; i += 256) {
        const float4 v = xp4[i];
        const int e = i * 4;
        float* d = &xs[(e >> 6) + 1][(e & 63) + 1];
        d[0] = v.x; d[1] = v.y; d[2] = v.z; d[3] = v.w;
    }

    if (tid < 9)        wsm[0][tid]      = wqh[c * 9 + tid];
    else if (tid < 18)  wsm[1][tid - 9]  = wkh[c * 9 + tid - 9];
    else if (tid < 27)  wsm[2][tid - 18] = wqw[c * 9 + tid - 18];
    else if (tid < 36)  wsm[3][tid - 27] = wkw[c * 9 + tid - 27];
    if (tid == 36) bsm[0] = bqh[c];
    if (tid == 37) bsm[1] = bkh[c];
    if (tid == 38) bsm[2] = bqw[c];
    if (tid == 39) bsm[3] = bkw[c];

    float w[9];
#pragma unroll
    for (int i = 0; i < 9; i++) w[i] = wv[c * 9 + i];
    const float bias = bv[c];
    __syncthreads();

    const int wcol = tid & 63;
    const int hgrp = tid >> 6;
    hf* op = g_vconv + ((size_t)b * Cc + c) * 4096;

    float colacc = 0.f;
    for (int k = 0; k < 16; k++) {
        const int h = hgrp * 16 + k;
        float s = bias;
#pragma unroll
        for (int dy = 0; dy < 3; dy++)
#pragma unroll
            for (int dx = 0; dx < 3; dx++)
                s += w[dy * 3 + dx] * xs[h + dy][wcol + dx];
        op[h * 64 + wcol] = to_h(s);
        const float v = xs[h + 1][wcol + 1];
        colacc += v;
        float rsum = v;
#pragma unroll
        for (int off = 16; off; off >>= 1)
            rsum += __shfl_down_sync(0xffffffffu, rsum, off);
        if ((tid & 31) == 0) rowp[(tid >> 5) & 1][h] = rsum;
    }
    colp[hgrp][wcol] = colacc;
    __syncthreads();
    if (tid < 64) T[tid] = colp[0][tid] + colp[1][tid] + colp[2][tid] + colp[3][tid];
    __syncthreads();

    if (tid < 64) {
        const int s = tid;
        float o0 = 0.f, o1 = 0.f, o2 = 0.f, o3 = 0.f;
#pragma unroll
        for (int d = 0; d < 3; d++) {
            const int r = s + d - 1;
            if (r >= 0 && r < 64) {
                const float Sv = rowp[0][r] + rowp[1][r];
                const float eL = xs[r + 1][1], eR = xs[r + 1][64];
                o0 += (wsm[0][d*3] + wsm[0][d*3+1] + wsm[0][d*3+2]) * Sv
                    - wsm[0][d*3] * eR - wsm[0][d*3+2] * eL;
                o1 += (wsm[1][d*3] + wsm[1][d*3+1] + wsm[1][d*3+2]) * Sv
                    - wsm[1][d*3] * eR - wsm[1][d*3+2] * eL;
                const float Tv = T[r];
                const float eT = xs[1][r + 1], eB = xs[64][r + 1];
                o2 += (wsm[2][d] + wsm[2][3+d] + wsm[2][6+d]) * Tv
                    - wsm[2][d] * eB - wsm[2][6+d] * eT;
                o3 += (wsm[3][d] + wsm[3][3+d] + wsm[3][6+d]) * Tv
                    - wsm[3][d] * eB - wsm[3][6+d] * eT;
            }
        }
        const float inv = 1.f / 64.f;
        const int mi = b * 64 + s;
        g_pool[0][c * 1024 + mi] = to_h(o0 * inv + bsm[0]);
        g_pool[1][c * 1024 + mi] = to_h(o1 * inv + bsm[1]);
        g_pool[2][c * 1024 + mi] = to_h(o2 * inv + bsm[2]);
        g_pool[3][c * 1024 + mi] = to_h(o3 * inv + bsm[3]);
    }
}

// ---------------------------------------------------------------------------
// Kernel 2: attention. Scores via fp16 wmma, low-register softmax.
// ---------------------------------------------------------------------------
__global__ void __launch_bounds__(256) attn_kernel(
    const float* __restrict__ Bh, const float* __restrict__ Bw)
{
    const int bh = blockIdx.x;
    const int head = bh & 7;
    const int axis = blockIdx.y;
    const float scale = 0.17677669529663687f;

    const hf* q = g_qkh[axis == 0 ? 0 : 2] + (size_t)bh * 2048;
    const hf* k = g_qkh[axis == 0 ? 1 : 3] + (size_t)bh * 2048;
    const float* Bm = ((axis == 0) ? Bh : Bw) + head * 4096;
    hf* o = g_attn[axis] + (size_t)bh * 4096;

    __shared__ float sc[64 * 68];

    {
        const int wid = threadIdx.x >> 5;
        const int wm = wid >> 1;
        const int wn = wid & 1;
        wmma::fragment<wmma::accumulator, 16, 16, 16, float> acc[2];
        wmma::fill_fragment(acc[0], 0.f);
        wmma::fill_fragment(acc[1], 0.f);
#pragma unroll
        for (int d0 = 0; d0 < 32; d0 += 16) {
            wmma::fragment<wmma::matrix_a, 16, 16, 16, half, wmma::row_major> af;
            wmma::load_matrix_sync(af, q + (size_t)(wm * 16) * 32 + d0, 32);
            wmma::fragment<wmma::matrix_b, 16, 16, 16, half, wmma::col_major> bf_[2];
            wmma::load_matrix_sync(bf_[0], k + (size_t)(wn * 32) * 32 + d0, 32);
            wmma::load_matrix_sync(bf_[1], k + (size_t)(wn * 32 + 16) * 32 + d0, 32);
            wmma::mma_sync(acc[0], af, bf_[0], acc[0]);
            wmma::mma_sync(acc[1], af, bf_[1], acc[1]);
        }
        wmma::store_matrix_sync(&sc[wm * 16 * 68 + wn * 32], acc[0], 68,
                                wmma::mem_row_major);
        wmma::store_matrix_sync(&sc[wm * 16 * 68 + wn * 32 + 16], acc[1], 68,
                                wmma::mem_row_major);
    }
    __syncthreads();

    {
        const int i = threadIdx.x >> 2;
        const int qq = threadIdx.x & 3;
        float s[16];
        float mx = -1e30f;
#pragma unroll
        for (int jj = 0; jj < 16; jj += 4) {
            const int j = qq * 16 + jj;
            const float4 c4 = *reinterpret_cast<const float4*>(&sc[i * 68 + j]);
            const float4 b4 = *reinterpret_cast<const float4*>(&Bm[i * 64 + j]);
            s[jj + 0] = c4.x * scale + b4.x;
            s[jj + 1] = c4.y * scale + b4.y;
            s[jj + 2] = c4.z * scale + b4.z;
            s[jj + 3] = c4.w * scale + b4.w;
            mx = fmaxf(mx, fmaxf(fmaxf(s[jj], s[jj + 1]), fmaxf(s[jj + 2], s[jj + 3])));
        }
        mx = fmaxf(mx, __shfl_xor_sync(0xffffffffu, mx, 1));
        mx = fmaxf(mx, __shfl_xor_sync(0xffffffffu, mx, 2));
        float sum = 0.f;
#pragma unroll
        for (int jj = 0; jj < 16; jj++) { s[jj] = __expf(s[jj] - mx); sum += s[jj]; }
        sum += __shfl_xor_sync(0xffffffffu, sum, 1);
        sum += __shfl_xor_sync(0xffffffffu, sum, 2);
        const float r = 1.f / sum;
#pragma unroll
        for (int jj = 0; jj < 16; jj += 4) {
            const int j = qq * 16 + jj;
            __half2 lo, hi;
            lo.x = to_h(s[jj + 0] * r); lo.y = to_h(s[jj + 1] * r);
            hi.x = to_h(s[jj + 2] * r); hi.y = to_h(s[jj + 3] * r);
            uint2 pk;
            pk.x = *reinterpret_cast<uint32_t*>(&lo);
            pk.y = *reinterpret_cast<uint32_t*>(&hi);
            *reinterpret_cast<uint2*>(&o[i * 64 + j]) = pk;
        }
    }
}

// ---------------------------------------------------------------------------
// Unified fp16 wmma GEMM, cp.async double buffered, BK=64 (4 iterations).
// ---------------------------------------------------------------------------
#define APB 4608            // A elems per buffer (64 x 72)
#define WPB 9216            // W elems per buffer (128 x 72)

template <int MODE>
__global__ void __launch_bounds__(128, 3) wmma_gemm_kernel(
    const float* __restrict__ b0, const float* __restrict__ b1,
    const float* __restrict__ b2, const float* __restrict__ b3,
    const float* __restrict__ bv, float* __restrict__ outp)
{
    __shared__ __align__(16) unsigned char smem_raw[2 * APB * 2 + 2 * WPB * 2 + 16 * 132 * 4];
    hf* Asm = reinterpret_cast<hf*>(smem_raw);
    hf* Wsm = reinterpret_cast<hf*>(smem_raw + 2 * APB * 2);
    float* sbias = reinterpret_cast<float*>(smem_raw + 2 * APB * 2 + 2 * WPB * 2);
    float* Cs = reinterpret_cast<float*>(smem_raw);

    const int tid = threadIdx.x;
    const int wid = tid >> 5;
    const int wm = wid >> 1;
    const int wn = wid & 1;
    const int nb = blockIdx.y * 128;
    const int z = blockIdx.z;

    const hf* A;
    const hf* W;
    const float* bias;
    int ldA, m0;
    bool isqk = false;
    int qkbr = 0;
    if constexpr (MODE == 1) {
        if (z < 16) {
            A = g_vconv + (size_t)z * 1048576; ldA = 4096;
            W = g_wh[4]; bias = bv; m0 = blockIdx.x * 64;
        } else {
            isqk = true;
            qkbr = blockIdx.x >> 4;
            A = g_pool[qkbr]; ldA = 1024;
            W = g_wh[qkbr];
            bias = (qkbr == 0) ? b0 : (qkbr == 1) ? b1 : (qkbr == 2) ? b2 : b3;
            m0 = (blockIdx.x & 15) * 64;
        }
    } else {
        A = g_r2 + (size_t)z * 1048576; ldA = 256;
        W = g_wh[5]; bias = b0; m0 = blockIdx.x * 64;
    }

    auto load_tiles = [&](int k0, int buf) {
        hf* As = Asm + buf * APB;
        hf* Ws = Wsm + buf * WPB;
#pragma unroll
        for (int i = 0; i < 4; i++) {
            const int f = tid + 128 * i;
            if constexpr (MODE == 1) {
                const int k = f >> 3, mq = f & 7;
                cp_async16(As + k * 72 + mq * 8,
                           A + (size_t)(k0 + k) * ldA + m0 + mq * 8);
            } else {
                const int m = f >> 3, kq = f & 7;
                cp_async16(As + m * 72 + kq * 8,
                           A + (size_t)(m0 + m) * 256 + k0 + kq * 8);
            }
        }
#pragma unroll
        for (int i = 0; i < 8; i++) {
            const int f = tid + 128 * i;
            const int n = f >> 3, kq = f & 7;
            cp_async16(Ws + n * 72 + kq * 8,
                       W + (size_t)(nb + n) * 256 + k0 + kq * 8);
        }
        CP_COMMIT();
    };

    for (int i = tid; i < 16 * 128; i += 128)
        sbias[(i >> 7) * 132 + (i & 127)] = bias[nb + (i & 127)];

    load_tiles(0, 0);
    __syncthreads();

    wmma::fragment<wmma::accumulator, 16, 16, 16, float> acc[2][4];
#pragma unroll
    for (int i = 0; i < 2; i++)
#pragma unroll
        for (int j = 0; j < 4; j++)
            wmma::load_matrix_sync(acc[i][j], &sbias[wn * 64 + j * 16], 132,
                                   wmma::mem_row_major);
    __syncthreads();

    int buf = 0;
    for (int it = 0; it < 4; it++) {
        if (it < 3) load_tiles((it + 1) * 64, buf ^ 1);
        if (it < 3) { CP_WAIT(1); } else { CP_WAIT(0); }
        __syncthreads();

        hf* As = Asm + buf * APB;
        hf* Ws = Wsm + buf * WPB;
#pragma unroll
        for (int kk = 0; kk < 64; kk += 16) {
            wmma::fragment<wmma::matrix_b, 16, 16, 16, half, wmma::col_major> bf_[4];
#pragma unroll
            for (int j = 0; j < 4; j++)
                wmma::load_matrix_sync(bf_[j], &Ws[(wn * 64 + j * 16) * 72 + kk], 72);
            if constexpr (MODE == 1) {
                wmma::fragment<wmma::matrix_a, 16, 16, 16, half, wmma::col_major> af[2];
                wmma::load_matrix_sync(af[0], &As[kk * 72 + wm * 32], 72);
                wmma::load_matrix_sync(af[1], &As[kk * 72 + wm * 32 + 16], 72);
#pragma unroll
                for (int i = 0; i < 2; i++)
#pragma unroll
                    for (int j = 0; j < 4; j++)
                        wmma::mma_sync(acc[i][j], af[i], bf_[j], acc[i][j]);
            } else {
                wmma::fragment<wmma::matrix_a, 16, 16, 16, half, wmma::row_major> af[2];
                wmma::load_matrix_sync(af[0], &As[(wm * 32) * 72 + kk], 72);
                wmma::load_matrix_sync(af[1], &As[(wm * 32 + 16) * 72 + kk], 72);
#pragma unroll
                for (int i = 0; i < 2; i++)
#pragma unroll
                    for (int j = 0; j < 4; j++)
                        wmma::mma_sync(acc[i][j], af[i], bf_[j], acc[i][j]);
            }
        }
        __syncthreads();
        buf ^= 1;
    }

    if constexpr (MODE == 2) {
#pragma unroll
        for (int i = 0; i < 2; i++)
#pragma unroll
            for (int j = 0; j < 4; j++) {
                const int mg = m0 + wm * 32 + i * 16;
                const int ng = nb + wn * 64 + j * 16;
                wmma::store_matrix_sync(
                    outp + (size_t)z * 1048576 + (size_t)mg * 256 + ng,
                    acc[i][j], 256, wmma::mem_row_major);
            }
    } else {
#pragma unroll
        for (int i = 0; i < 2; i++)
#pragma unroll
            for (int j = 0; j < 4; j++)
                wmma::store_matrix_sync(&Cs[(wm * 32 + i * 16) * 132 + wn * 64 + j * 16],
                                        acc[i][j], 132, wmma::mem_row_major);
        __syncthreads();
#pragma unroll
        for (int i = 0; i < 16; i++) {
            const int f = tid + 128 * i;
            const int row = f >> 5;
            const int cq = f & 31;
            const float4 v = *reinterpret_cast<const float4*>(&Cs[row * 132 + cq * 4]);
            __half2 lo, hi;
            lo.x = to_h(v.x); lo.y = to_h(v.y);
            hi.x = to_h(v.z); hi.y = to_h(v.w);
            uint2 pk;
            pk.x = *reinterpret_cast<uint32_t*>(&lo);
            pk.y = *reinterpret_cast<uint32_t*>(&hi);
            const int mg = m0 + row;
            const int ng = nb + cq * 4;
            const int head = ng >> 5;
            hf* dst;
            if (isqk)
                dst = g_qkh[qkbr] + (size_t)(mg >> 6) * 16384 + (size_t)head * 2048
                    + (size_t)(mg & 63) * 32 + (ng & 31);
            else
                dst = g_v + (size_t)z * 1048576 + (size_t)head * 131072
                    + (size_t)mg * 32 + (ng & 31);
            *reinterpret_cast<uint2*>(dst) = pk;
        }
    }
}

// ---------------------------------------------------------------------------
// Kernel 4: axh — R[64][2048] = attn_h @ V per bh, smem-tiled.
// Grid (4 n-chunks, 128 bh), 512 threads = 16 warps (2m x 8n), tile 32x64.
// ---------------------------------------------------------------------------
__global__ void __launch_bounds__(512) axh_kernel()
{
    __shared__ hf Ah_s[64 * 72];         // 9.2 KB
    __shared__ hf Vs[64 * 520];          // 66.6 KB (also fp32 staging [64][260])
    const int bh = blockIdx.y;
    const int n0 = blockIdx.x * 512;
    const int tid = threadIdx.x;
    const int wid = tid >> 5;
    const int wm = wid >> 3;             // 0..1
    const int wn = wid & 7;              // 0..7

    {
        const hf* Ag = g_attn[0] + (size_t)bh * 4096;
        const int row = tid >> 3, c8 = (tid & 7) * 8;
        *reinterpret_cast<uint4*>(&Ah_s[row * 72 + c8]) =
            *reinterpret_cast<const uint4*>(Ag + row * 64 + c8);
        const hf* Vg = g_v + (size_t)bh * 131072 + n0;
#pragma unroll
        for (int i = 0; i < 8; i++) {
            const int f = tid + 512 * i;
            const int r = f >> 6, cc = (f & 63) * 8;
            *reinterpret_cast<uint4*>(&Vs[r * 520 + cc]) =
                *reinterpret_cast<const uint4*>(Vg + (size_t)r * 2048 + cc);
        }
    }
    __syncthreads();

    wmma::fragment<wmma::accumulator, 16, 16, 16, float> acc[2][4];
#pragma unroll
    for (int i = 0; i < 2; i++)
#pragma unroll
        for (int j = 0; j < 4; j++) wmma::fill_fragment(acc[i][j], 0.f);

#pragma unroll
    for (int kk = 0; kk < 64; kk += 16) {
        wmma::fragment<wmma::matrix_a, 16, 16, 16, half, wmma::row_major> af[2];
        wmma::load_matrix_sync(af[0], &Ah_s[(wm * 32) * 72 + kk], 72);
        wmma::load_matrix_sync(af[1], &Ah_s[(wm * 32 + 16) * 72 + kk], 72);
        wmma::fragment<wmma::matrix_b, 16, 16, 16, half, wmma::row_major> bf_[4];
#pragma unroll
        for (int j = 0; j < 4; j++)
            wmma::load_matrix_sync(bf_[j], &Vs[kk * 520 + wn * 64 + j * 16], 520);
#pragma unroll
        for (int i = 0; i < 2; i++)
#pragma unroll
            for (int j = 0; j < 4; j++)
                wmma::mma_sync(acc[i][j], af[i], bf_[j], acc[i][j]);
    }
    __syncthreads();    // Vs dead -> staging

    float* St = reinterpret_cast<float*>(Vs);     // [64][260]
    hf* Rg = g_r + (size_t)bh * 131072;
#pragma unroll
    for (int p = 0; p < 2; p++) {
        if ((wn >> 2) == p) {
#pragma unroll
            for (int i = 0; i < 2; i++)
#pragma unroll
                for (int j = 0; j < 4; j++)
                    wmma::store_matrix_sync(
                        &St[(wm * 32 + i * 16) * 260 + (wn & 3) * 64 + j * 16],
                        acc[i][j], 260, wmma::mem_row_major);
        }
        __syncthreads();
#pragma unroll
        for (int i = 0; i < 4; i++) {
            const int f = tid + 512 * i;          // 2048 chunks of 8
            const int row = f >> 5, c8 = (f & 31) * 8;
            const float4 v0 = *reinterpret_cast<const float4*>(&St[row * 260 + c8]);
            const float4 v1 = *reinterpret_cast<const float4*>(&St[row * 260 + c8 + 4]);
            __half2 pk_[4];
            pk_[0].x = to_h(v0.x); pk_[0].y = to_h(v0.y);
            pk_[1].x = to_h(v0.z); pk_[1].y = to_h(v0.w);
            pk_[2].x = to_h(v1.x); pk_[2].y = to_h(v1.y);
            pk_[3].x = to_h(v1.z); pk_[3].y = to_h(v1.w);
            *reinterpret_cast<uint4*>(Rg + (size_t)row * 2048 + n0 + p * 256 + c8) =
                *reinterpret_cast<uint4*>(pk_);
        }
        __syncthreads();
    }
}

// ---------------------------------------------------------------------------
// Kernel 5: axw — per (bh, h): [32 dv][64 w'] = R[h]^T @ attn_w, smem-tiled.
// Grid (4 h-chunks, 128 bh), 512 threads = 16 warps, warp = one h.
// ---------------------------------------------------------------------------
__global__ void __launch_bounds__(512) axw_kernel()
{
    __shared__ hf Aw_s[64 * 72];         // 9.2 KB
    __shared__ hf Rs[16 * 2056];         // 64.25 KB (also fp32 staging)
    const int bh = blockIdx.y;
    const int hc = blockIdx.x;           // h chunk (16 h)
    const int tid = threadIdx.x;
    const int wid = tid >> 5;

    {
        const hf* Ag = g_attn[1] + (size_t)bh * 4096;
        const int row = tid >> 3, c8 = (tid & 7) * 8;
        *reinterpret_cast<uint4*>(&Aw_s[row * 72 + c8]) =
            *reinterpret_cast<const uint4*>(Ag + row * 64 + c8);
        const hf* Rg = g_r + (size_t)bh * 131072 + (size_t)(hc * 16) * 2048;
#pragma unroll
        for (int i = 0; i < 8; i++) {
            const int f = tid + 512 * i;          // 4096 chunks of 8
            const int hl = f >> 8, cc = (f & 255) * 8;
            *reinterpret_cast<uint4*>(&Rs[hl * 2056 + cc]) =
                *reinterpret_cast<const uint4*>(Rg + (size_t)hl * 2048 + cc);
        }
    }
    __syncthreads();

    wmma::fragment<wmma::accumulator, 16, 16, 16, float> acc[2][4];
#pragma unroll
    for (int i = 0; i < 2; i++)
#pragma unroll
        for (int j = 0; j < 4; j++) wmma::fill_fragment(acc[i][j], 0.f);

    const hf* Ar = &Rs[wid * 2056];
#pragma unroll
    for (int kk = 0; kk < 64; kk += 16) {
        wmma::fragment<wmma::matrix_a, 16, 16, 16, half, wmma::col_major> af[2];
        wmma::load_matrix_sync(af[0], Ar + kk * 32, 32);
        wmma::load_matrix_sync(af[1], Ar + kk * 32 + 16, 32);
        wmma::fragment<wmma::matrix_b, 16, 16, 16, half, wmma::row_major> bf_[4];
#pragma unroll
        for (int j = 0; j < 4; j++)
            wmma::load_matrix_sync(bf_[j], &Aw_s[kk * 72 + j * 16], 72);
#pragma unroll
        for (int i = 0; i < 2; i++)
#pragma unroll
            for (int j = 0; j < 4; j++)
                wmma::mma_sync(acc[i][j], af[i], bf_[j], acc[i][j]);
    }
    __syncthreads();    // Rs dead -> staging

    float* St = reinterpret_cast<float*>(Rs);     // 8 slices of [64][32] fp32
    hf* outb = g_r2 + (size_t)(bh >> 3) * 1048576 + (bh & 7) * 32;
#pragma unroll
    for (int p = 0; p < 2; p++) {
        if ((wid >> 3) == p) {
            float* sl = St + (wid & 7) * 2048;
#pragma unroll
            for (int i = 0; i < 2; i++)
#pragma unroll
                for (int j = 0; j < 4; j++)
                    wmma::store_matrix_sync(sl + (j * 16) * 32 + i * 16,
                                            acc[i][j], 32, wmma::mem_col_major);
        }
        __syncthreads();
#pragma unroll
        for (int i = 0; i < 4; i++) {
            const int f = tid + 512 * i;          // 2048 chunks of 8
            const int hl = f >> 8;                // 0..7 within pass
            const int rem = f & 255;
            const int wp = rem >> 2, d8 = (rem & 3) * 8;
            const float* src = St + hl * 2048 + wp * 32 + d8;
            const float4 v0 = *reinterpret_cast<const float4*>(src);
            const float4 v1 = *reinterpret_cast<const float4*>(src + 4);
            __half2 pk_[4];
            pk_[0].x = to_h(v0.x); pk_[0].y = to_h(v0.y);
            pk_[1].x = to_h(v0.z); pk_[1].y = to_h(v0.w);
            pk_[2].x = to_h(v1.x); pk_[2].y = to_h(v1.y);
            pk_[3].x = to_h(v1.z); pk_[3].y = to_h(v1.w);
            const int h = hc * 16 + p * 8 + hl;
            *reinterpret_cast<uint4*>(
                outb + (size_t)(h * 64 + wp) * 256 + d8) =
                *reinterpret_cast<uint4*>(pk_);
        }
        __syncthreads();
    }
}

// ---------------------------------------------------------------------------
// Launch
// ---------------------------------------------------------------------------
extern "C" void kernel_launch(void* const* d_in, const int* in_sizes, int n_in,
                              void* d_out, int out_size)
{
    const float* x       = (const float*)d_in[0];
    const float* dw_qh_w = (const float*)d_in[1];
    const float* dw_qh_b = (const float*)d_in[2];
    const float* fc_qh_w = (const float*)d_in[3];
    const float* fc_qh_b = (const float*)d_in[4];
    const float* dw_kh_w = (const float*)d_in[5];
    const float* dw_kh_b = (const float*)d_in[6];
    const float* fc_kh_w = (const float*)d_in[7];
    const float* fc_kh_b = (const float*)d_in[8];
    const float* Bh      = (const float*)d_in[9];
    const float* dw_v_w  = (const float*)d_in[10];
    const float* dw_v_b  = (const float*)d_in[11];
    const float* fc_v_w  = (const float*)d_in[12];
    const float* fc_v_b  = (const float*)d_in[13];
    const float* dw_qw_w = (const float*)d_in[14];
    const float* dw_qw_b = (const float*)d_in[15];
    const float* fc_qw_w = (const float*)d_in[16];
    const float* fc_qw_b = (const float*)d_in[17];
    const float* dw_kw_w = (const float*)d_in[18];
    const float* dw_kw_b = (const float*)d_in[19];
    const float* fc_kw_w = (const float*)d_in[20];
    const float* fc_kw_b = (const float*)d_in[21];
    const float* Bw      = (const float*)d_in[22];
    const float* fc_o_w  = (const float*)d_in[23];
    const float* fc_o_b  = (const float*)d_in[24];
    float* out = (float*)d_out;

    conv_fused_kernel<<<dim3(Cc, Bb + 1), 256>>>(
        x, dw_v_w, dw_v_b,
        dw_qh_w, dw_qh_b, dw_kh_w, dw_kh_b,
        dw_qw_w, dw_qw_b, dw_kw_w, dw_kw_b,
        fc_qh_w, fc_kh_w, fc_qw_w, fc_kw_w, fc_v_w, fc_o_w);

    wmma_gemm_kernel<1><<<dim3(64, 2, Bb + 1), 128>>>(
        fc_qh_b, fc_kh_b, fc_qw_b, fc_kw_b, fc_v_b, nullptr);

    attn_kernel<<<dim3(Bb * Hh, 2), 256>>>(Bh, Bw);

    axh_kernel<<<dim3(4, Bb * Hh), 512>>>();
    axw_kernel<<<dim3(4, Bb * Hh), 512>>>();

    wmma_gemm_kernel<2><<<dim3(64, 2, Bb), 128>>>(
        fc_o_b, fc_o_b, fc_o_b, fc_o_b, fc_o_b, out);
}

// round 15
// speedup vs baseline: 5.3450x; 1.0378x over previous
#include <cuda_runtime.h>
#include <cuda_fp16.h>
#include <mma.h>
#include <cstdint>

using namespace nvcuda;

#define Bb 16
#define Cc 256
#define Ss 64
#define Hh 8
#define Dd 32

typedef __half hf;

// ---------------------------------------------------------------------------
// Scratch (all intermediates fp16, rounded at producers; fp32 accum in MMA)
// ---------------------------------------------------------------------------
__device__ hf g_pool[4][Cc * Bb * Ss];               // [c][b*64+s]  (A^T)
__device__ hf g_qkh[4][Bb * Hh * Ss * Dd];           // [b][head][s][d]
__device__ hf g_attn[2][Bb * Hh * Ss * Ss];
__device__ hf g_vconv[(size_t)Bb * Cc * 4096];       // [b][c][hw] (A^T)
__device__ hf g_v[(size_t)Bb * Hh * 4096 * 32];      // [b][head][hw][dv]
__device__ hf g_r[(size_t)Bb * Hh * Ss * Ss * Dd];   // [b][head][h][w*32+dv]
__device__ hf g_r2[(size_t)Bb * 4096 * Cc];          // [b][m=hw][k]
__device__ hf g_wh[6][Cc * Cc];                      // pre-rounded weights

__device__ __forceinline__ hf to_h(float x) { return __float2half_rn(x); }

__device__ __forceinline__ void cp_async16(void* smem, const void* gmem) {
    uint32_t s = (uint32_t)__cvta_generic_to_shared(smem);
    asm volatile("cp.async.cg.shared.global [%0], [%1], 16;" :: "r"(s), "l"(gmem));
}
#define CP_COMMIT() asm volatile("cp.async.commit_group;" ::: "memory")
#define CP_WAIT(n)  asm volatile("cp.async.wait_group %0;" :: "n"(n) : "memory")

// ---------------------------------------------------------------------------
// Kernel 1: fused V dwconv + analytic pooled q/k branches + weight rounding.
// ---------------------------------------------------------------------------
__global__ void __launch_bounds__(256) conv_fused_kernel(
    const float* __restrict__ x,
    const float* __restrict__ wv,  const float* __restrict__ bv,
    const float* __restrict__ wqh, const float* __restrict__ bqh,
    const float* __restrict__ wkh, const float* __restrict__ bkh,
    const float* __restrict__ wqw, const float* __restrict__ bqw,
    const float* __restrict__ wkw, const float* __restrict__ bkw,
    const float* __restrict__ fqh, const float* __restrict__ fkh,
    const float* __restrict__ fqw, const float* __restrict__ fkw,
    const float* __restrict__ fv,  const float* __restrict__ fo)
{
    const int tid = threadIdx.x;

    if (blockIdx.y == Bb) {
        const int i = blockIdx.x * 256 + tid;
        g_wh[0][i] = to_h(fqh[i]);
        g_wh[1][i] = to_h(fkh[i]);
        g_wh[2][i] = to_h(fqw[i]);
        g_wh[3][i] = to_h(fkw[i]);
        g_wh[4][i] = to_h(fv[i]);
        g_wh[5][i] = to_h(fo[i]);
        return;
    }

    const int c = blockIdx.x;
    const int b = blockIdx.y;

    __shared__ float xs[66][66];
    __shared__ float rowp[2][64], colp[4][64];
    __shared__ float T[64];
    __shared__ float wsm[4][9];
    __shared__ float bsm[4];

    for (int i = tid; i < 66 * 66; i += 256) (&xs[0][0])[i] = 0.f;
    __syncthreads();

    const float4* xp4 = reinterpret_cast<const float4*>(x + ((size_t)b * Cc + c) * 4096);
    for (int i = tid; i < 1024; i += 256) {
        const float4 v = xp4[i];
        const int e = i * 4;
        float* d = &xs[(e >> 6) + 1][(e & 63) + 1];
        d[0] = v.x; d[1] = v.y; d[2] = v.z; d[3] = v.w;
    }

    if (tid < 9)        wsm[0][tid]      = wqh[c * 9 + tid];
    else if (tid < 18)  wsm[1][tid - 9]  = wkh[c * 9 + tid - 9];
    else if (tid < 27)  wsm[2][tid - 18] = wqw[c * 9 + tid - 18];
    else if (tid < 36)  wsm[3][tid - 27] = wkw[c * 9 + tid - 27];
    if (tid == 36) bsm[0] = bqh[c];
    if (tid == 37) bsm[1] = bkh[c];
    if (tid == 38) bsm[2] = bqw[c];
    if (tid == 39) bsm[3] = bkw[c];

    float w[9];
#pragma unroll
    for (int i = 0; i < 9; i++) w[i] = wv[c * 9 + i];
    const float bias = bv[c];
    __syncthreads();

    const int wcol = tid & 63;
    const int hgrp = tid >> 6;
    hf* op = g_vconv + ((size_t)b * Cc + c) * 4096;

    float colacc = 0.f;
    for (int k = 0; k < 16; k++) {
        const int h = hgrp * 16 + k;
        float s = bias;
#pragma unroll
        for (int dy = 0; dy < 3; dy++)
#pragma unroll
            for (int dx = 0; dx < 3; dx++)
                s += w[dy * 3 + dx] * xs[h + dy][wcol + dx];
        op[h * 64 + wcol] = to_h(s);
        const float v = xs[h + 1][wcol + 1];
        colacc += v;
        float rsum = v;
#pragma unroll
        for (int off = 16; off; off >>= 1)
            rsum += __shfl_down_sync(0xffffffffu, rsum, off);
        if ((tid & 31) == 0) rowp[(tid >> 5) & 1][h] = rsum;
    }
    colp[hgrp][wcol] = colacc;
    __syncthreads();
    if (tid < 64) T[tid] = colp[0][tid] + colp[1][tid] + colp[2][tid] + colp[3][tid];
    __syncthreads();

    if (tid < 64) {
        const int s = tid;
        float o0 = 0.f, o1 = 0.f, o2 = 0.f, o3 = 0.f;
#pragma unroll
        for (int d = 0; d < 3; d++) {
            const int r = s + d - 1;
            if (r >= 0 && r < 64) {
                const float Sv = rowp[0][r] + rowp[1][r];
                const float eL = xs[r + 1][1], eR = xs[r + 1][64];
                o0 += (wsm[0][d*3] + wsm[0][d*3+1] + wsm[0][d*3+2]) * Sv
                    - wsm[0][d*3] * eR - wsm[0][d*3+2] * eL;
                o1 += (wsm[1][d*3] + wsm[1][d*3+1] + wsm[1][d*3+2]) * Sv
                    - wsm[1][d*3] * eR - wsm[1][d*3+2] * eL;
                const float Tv = T[r];
                const float eT = xs[1][r + 1], eB = xs[64][r + 1];
                o2 += (wsm[2][d] + wsm[2][3+d] + wsm[2][6+d]) * Tv
                    - wsm[2][d] * eB - wsm[2][6+d] * eT;
                o3 += (wsm[3][d] + wsm[3][3+d] + wsm[3][6+d]) * Tv
                    - wsm[3][d] * eB - wsm[3][6+d] * eT;
            }
        }
        const float inv = 1.f / 64.f;
        const int mi = b * 64 + s;
        g_pool[0][c * 1024 + mi] = to_h(o0 * inv + bsm[0]);
        g_pool[1][c * 1024 + mi] = to_h(o1 * inv + bsm[1]);
        g_pool[2][c * 1024 + mi] = to_h(o2 * inv + bsm[2]);
        g_pool[3][c * 1024 + mi] = to_h(o3 * inv + bsm[3]);
    }
}

// ---------------------------------------------------------------------------
// Kernel 2: attention. Scores via fp16 wmma, low-register softmax.
// ---------------------------------------------------------------------------
__global__ void __launch_bounds__(256) attn_kernel(
    const float* __restrict__ Bh, const float* __restrict__ Bw)
{
    const int bh = blockIdx.x;
    const int head = bh & 7;
    const int axis = blockIdx.y;
    const float scale = 0.17677669529663687f;

    const hf* q = g_qkh[axis == 0 ? 0 : 2] + (size_t)bh * 2048;
    const hf* k = g_qkh[axis == 0 ? 1 : 3] + (size_t)bh * 2048;
    const float* Bm = ((axis == 0) ? Bh : Bw) + head * 4096;
    hf* o = g_attn[axis] + (size_t)bh * 4096;

    __shared__ float sc[64 * 68];

    {
        const int wid = threadIdx.x >> 5;
        const int wm = wid >> 1;
        const int wn = wid & 1;
        wmma::fragment<wmma::accumulator, 16, 16, 16, float> acc[2];
        wmma::fill_fragment(acc[0], 0.f);
        wmma::fill_fragment(acc[1], 0.f);
#pragma unroll
        for (int d0 = 0; d0 < 32; d0 += 16) {
            wmma::fragment<wmma::matrix_a, 16, 16, 16, half, wmma::row_major> af;
            wmma::load_matrix_sync(af, q + (size_t)(wm * 16) * 32 + d0, 32);
            wmma::fragment<wmma::matrix_b, 16, 16, 16, half, wmma::col_major> bf_[2];
            wmma::load_matrix_sync(bf_[0], k + (size_t)(wn * 32) * 32 + d0, 32);
            wmma::load_matrix_sync(bf_[1], k + (size_t)(wn * 32 + 16) * 32 + d0, 32);
            wmma::mma_sync(acc[0], af, bf_[0], acc[0]);
            wmma::mma_sync(acc[1], af, bf_[1], acc[1]);
        }
        wmma::store_matrix_sync(&sc[wm * 16 * 68 + wn * 32], acc[0], 68,
                                wmma::mem_row_major);
        wmma::store_matrix_sync(&sc[wm * 16 * 68 + wn * 32 + 16], acc[1], 68,
                                wmma::mem_row_major);
    }
    __syncthreads();

    {
        const int i = threadIdx.x >> 2;
        const int qq = threadIdx.x & 3;
        float s[16];
        float mx = -1e30f;
#pragma unroll
        for (int jj = 0; jj < 16; jj += 4) {
            const int j = qq * 16 + jj;
            const float4 c4 = *reinterpret_cast<const float4*>(&sc[i * 68 + j]);
            const float4 b4 = *reinterpret_cast<const float4*>(&Bm[i * 64 + j]);
            s[jj + 0] = c4.x * scale + b4.x;
            s[jj + 1] = c4.y * scale + b4.y;
            s[jj + 2] = c4.z * scale + b4.z;
            s[jj + 3] = c4.w * scale + b4.w;
            mx = fmaxf(mx, fmaxf(fmaxf(s[jj], s[jj + 1]), fmaxf(s[jj + 2], s[jj + 3])));
        }
        mx = fmaxf(mx, __shfl_xor_sync(0xffffffffu, mx, 1));
        mx = fmaxf(mx, __shfl_xor_sync(0xffffffffu, mx, 2));
        float sum = 0.f;
#pragma unroll
        for (int jj = 0; jj < 16; jj++) { s[jj] = __expf(s[jj] - mx); sum += s[jj]; }
        sum += __shfl_xor_sync(0xffffffffu, sum, 1);
        sum += __shfl_xor_sync(0xffffffffu, sum, 2);
        const float r = 1.f / sum;
#pragma unroll
        for (int jj = 0; jj < 16; jj += 4) {
            const int j = qq * 16 + jj;
            __half2 lo, hi;
            lo.x = to_h(s[jj + 0] * r); lo.y = to_h(s[jj + 1] * r);
            hi.x = to_h(s[jj + 2] * r); hi.y = to_h(s[jj + 3] * r);
            uint2 pk;
            pk.x = *reinterpret_cast<uint32_t*>(&lo);
            pk.y = *reinterpret_cast<uint32_t*>(&hi);
            *reinterpret_cast<uint2*>(&o[i * 64 + j]) = pk;
        }
    }
}

// ---------------------------------------------------------------------------
// Unified fp16 wmma GEMM, cp.async double buffered, BK=64 (4 iterations).
// ---------------------------------------------------------------------------
#define APB 4608            // A elems per buffer (64 x 72)
#define WPB 9216            // W elems per buffer (128 x 72)

template <int MODE>
__global__ void __launch_bounds__(128, 3) wmma_gemm_kernel(
    const float* __restrict__ b0, const float* __restrict__ b1,
    const float* __restrict__ b2, const float* __restrict__ b3,
    const float* __restrict__ bv, float* __restrict__ outp)
{
    __shared__ __align__(16) unsigned char smem_raw[2 * APB * 2 + 2 * WPB * 2 + 16 * 132 * 4];
    hf* Asm = reinterpret_cast<hf*>(smem_raw);
    hf* Wsm = reinterpret_cast<hf*>(smem_raw + 2 * APB * 2);
    float* sbias = reinterpret_cast<float*>(smem_raw + 2 * APB * 2 + 2 * WPB * 2);
    float* Cs = reinterpret_cast<float*>(smem_raw);

    const int tid = threadIdx.x;
    const int wid = tid >> 5;
    const int wm = wid >> 1;
    const int wn = wid & 1;
    const int nb = blockIdx.y * 128;
    const int z = blockIdx.z;

    const hf* A;
    const hf* W;
    const float* bias;
    int ldA, m0;
    bool isqk = false;
    int qkbr = 0;
    if constexpr (MODE == 1) {
        if (z < 16) {
            A = g_vconv + (size_t)z * 1048576; ldA = 4096;
            W = g_wh[4]; bias = bv; m0 = blockIdx.x * 64;
        } else {
            isqk = true;
            qkbr = blockIdx.x >> 4;
            A = g_pool[qkbr]; ldA = 1024;
            W = g_wh[qkbr];
            bias = (qkbr == 0) ? b0 : (qkbr == 1) ? b1 : (qkbr == 2) ? b2 : b3;
            m0 = (blockIdx.x & 15) * 64;
        }
    } else {
        A = g_r2 + (size_t)z * 1048576; ldA = 256;
        W = g_wh[5]; bias = b0; m0 = blockIdx.x * 64;
    }

    auto load_tiles = [&](int k0, int buf) {
        hf* As = Asm + buf * APB;
        hf* Ws = Wsm + buf * WPB;
#pragma unroll
        for (int i = 0; i < 4; i++) {
            const int f = tid + 128 * i;
            if constexpr (MODE == 1) {
                const int k = f >> 3, mq = f & 7;
                cp_async16(As + k * 72 + mq * 8,
                           A + (size_t)(k0 + k) * ldA + m0 + mq * 8);
            } else {
                const int m = f >> 3, kq = f & 7;
                cp_async16(As + m * 72 + kq * 8,
                           A + (size_t)(m0 + m) * 256 + k0 + kq * 8);
            }
        }
#pragma unroll
        for (int i = 0; i < 8; i++) {
            const int f = tid + 128 * i;
            const int n = f >> 3, kq = f & 7;
            cp_async16(Ws + n * 72 + kq * 8,
                       W + (size_t)(nb + n) * 256 + k0 + kq * 8);
        }
        CP_COMMIT();
    };

    for (int i = tid; i < 16 * 128; i += 128)
        sbias[(i >> 7) * 132 + (i & 127)] = bias[nb + (i & 127)];

    load_tiles(0, 0);
    __syncthreads();

    wmma::fragment<wmma::accumulator, 16, 16, 16, float> acc[2][4];
#pragma unroll
    for (int i = 0; i < 2; i++)
#pragma unroll
        for (int j = 0; j < 4; j++)
            wmma::load_matrix_sync(acc[i][j], &sbias[wn * 64 + j * 16], 132,
                                   wmma::mem_row_major);
    __syncthreads();

    int buf = 0;
    for (int it = 0; it < 4; it++) {
        if (it < 3) load_tiles((it + 1) * 64, buf ^ 1);
        if (it < 3) { CP_WAIT(1); } else { CP_WAIT(0); }
        __syncthreads();

        hf* As = Asm + buf * APB;
        hf* Ws = Wsm + buf * WPB;
#pragma unroll
        for (int kk = 0; kk < 64; kk += 16) {
            wmma::fragment<wmma::matrix_b, 16, 16, 16, half, wmma::col_major> bf_[4];
#pragma unroll
            for (int j = 0; j < 4; j++)
                wmma::load_matrix_sync(bf_[j], &Ws[(wn * 64 + j * 16) * 72 + kk], 72);
            if constexpr (MODE == 1) {
                wmma::fragment<wmma::matrix_a, 16, 16, 16, half, wmma::col_major> af[2];
                wmma::load_matrix_sync(af[0], &As[kk * 72 + wm * 32], 72);
                wmma::load_matrix_sync(af[1], &As[kk * 72 + wm * 32 + 16], 72);
#pragma unroll
                for (int i = 0; i < 2; i++)
#pragma unroll
                    for (int j = 0; j < 4; j++)
                        wmma::mma_sync(acc[i][j], af[i], bf_[j], acc[i][j]);
            } else {
                wmma::fragment<wmma::matrix_a, 16, 16, 16, half, wmma::row_major> af[2];
                wmma::load_matrix_sync(af[0], &As[(wm * 32) * 72 + kk], 72);
                wmma::load_matrix_sync(af[1], &As[(wm * 32 + 16) * 72 + kk], 72);
#pragma unroll
                for (int i = 0; i < 2; i++)
#pragma unroll
                    for (int j = 0; j < 4; j++)
                        wmma::mma_sync(acc[i][j], af[i], bf_[j], acc[i][j]);
            }
        }
        __syncthreads();
        buf ^= 1;
    }

    if constexpr (MODE == 2) {
#pragma unroll
        for (int i = 0; i < 2; i++)
#pragma unroll
            for (int j = 0; j < 4; j++) {
                const int mg = m0 + wm * 32 + i * 16;
                const int ng = nb + wn * 64 + j * 16;
                wmma::store_matrix_sync(
                    outp + (size_t)z * 1048576 + (size_t)mg * 256 + ng,
                    acc[i][j], 256, wmma::mem_row_major);
            }
    } else {
#pragma unroll
        for (int i = 0; i < 2; i++)
#pragma unroll
            for (int j = 0; j < 4; j++)
                wmma::store_matrix_sync(&Cs[(wm * 32 + i * 16) * 132 + wn * 64 + j * 16],
                                        acc[i][j], 132, wmma::mem_row_major);
        __syncthreads();
#pragma unroll
        for (int i = 0; i < 16; i++) {
            const int f = tid + 128 * i;
            const int row = f >> 5;
            const int cq = f & 31;
            const float4 v = *reinterpret_cast<const float4*>(&Cs[row * 132 + cq * 4]);
            __half2 lo, hi;
            lo.x = to_h(v.x); lo.y = to_h(v.y);
            hi.x = to_h(v.z); hi.y = to_h(v.w);
            uint2 pk;
            pk.x = *reinterpret_cast<uint32_t*>(&lo);
            pk.y = *reinterpret_cast<uint32_t*>(&hi);
            const int mg = m0 + row;
            const int ng = nb + cq * 4;
            const int head = ng >> 5;
            hf* dst;
            if (isqk)
                dst = g_qkh[qkbr] + (size_t)(mg >> 6) * 16384 + (size_t)head * 2048
                    + (size_t)(mg & 63) * 32 + (ng & 31);
            else
                dst = g_v + (size_t)z * 1048576 + (size_t)head * 131072
                    + (size_t)mg * 32 + (ng & 31);
            *reinterpret_cast<uint2*>(dst) = pk;
        }
    }
}

// ---------------------------------------------------------------------------
// Kernel 4: axh — R[64][256-chunk] = attn_h @ V per bh, smem-tiled.
// Grid (8 n-chunks, 128 bh), 256 threads = 8 warps (2m x 4n), tile 32x64.
// 2 CTAs/SM (regs ~102 x 256 = 26K).
// ---------------------------------------------------------------------------
__global__ void __launch_bounds__(256) axh_kernel()
{
    __shared__ hf Ah_s[64 * 72];         // 9.2 KB
    __shared__ hf Vs[64 * 264];          // 33.8 KB (aliased fp32 staging [64][132])
    const int bh = blockIdx.y;
    const int n0 = blockIdx.x * 256;
    const int tid = threadIdx.x;
    const int wid = tid >> 5;
    const int wm = wid >> 2;             // 0..1
    const int wn = wid & 3;              // 0..3

    {
        const hf* Ag = g_attn[0] + (size_t)bh * 4096;
#pragma unroll
        for (int i = 0; i < 2; i++) {
            const int f = tid + 256 * i;          // 512 chunks of 8
            const int row = f >> 3, c8 = (f & 7) * 8;
            *reinterpret_cast<uint4*>(&Ah_s[row * 72 + c8]) =
                *reinterpret_cast<const uint4*>(Ag + row * 64 + c8);
        }
        const hf* Vg = g_v + (size_t)bh * 131072 + n0;
#pragma unroll
        for (int i = 0; i < 8; i++) {
            const int f = tid + 256 * i;          // 2048 chunks of 8
            const int r = f >> 5, cc = (f & 31) * 8;
            *reinterpret_cast<uint4*>(&Vs[r * 264 + cc]) =
                *reinterpret_cast<const uint4*>(Vg + (size_t)r * 2048 + cc);
        }
    }
    __syncthreads();

    wmma::fragment<wmma::accumulator, 16, 16, 16, float> acc[2][4];
#pragma unroll
    for (int i = 0; i < 2; i++)
#pragma unroll
        for (int j = 0; j < 4; j++) wmma::fill_fragment(acc[i][j], 0.f);

#pragma unroll
    for (int kk = 0; kk < 64; kk += 16) {
        wmma::fragment<wmma::matrix_a, 16, 16, 16, half, wmma::row_major> af[2];
        wmma::load_matrix_sync(af[0], &Ah_s[(wm * 32) * 72 + kk], 72);
        wmma::load_matrix_sync(af[1], &Ah_s[(wm * 32 + 16) * 72 + kk], 72);
        wmma::fragment<wmma::matrix_b, 16, 16, 16, half, wmma::row_major> bf_[4];
#pragma unroll
        for (int j = 0; j < 4; j++)
            wmma::load_matrix_sync(bf_[j], &Vs[kk * 264 + wn * 64 + j * 16], 264);
#pragma unroll
        for (int i = 0; i < 2; i++)
#pragma unroll
            for (int j = 0; j < 4; j++)
                wmma::mma_sync(acc[i][j], af[i], bf_[j], acc[i][j]);
    }
    __syncthreads();    // Vs dead -> staging

    // epilogue: 2 passes of 128 n-cols through fp32 staging [64][132] in Vs
    float* St = reinterpret_cast<float*>(Vs);
    hf* Rg = g_r + (size_t)bh * 131072;
#pragma unroll
    for (int p = 0; p < 2; p++) {
        if ((wn >> 1) == p) {
#pragma unroll
            for (int i = 0; i < 2; i++)
#pragma unroll
                for (int j = 0; j < 4; j++)
                    wmma::store_matrix_sync(
                        &St[(wm * 32 + i * 16) * 132 + (wn & 1) * 64 + j * 16],
                        acc[i][j], 132, wmma::mem_row_major);
        }
        __syncthreads();
#pragma unroll
        for (int i = 0; i < 4; i++) {
            const int f = tid + 256 * i;          // 1024 chunks of 8
            const int row = f >> 4, c8 = (f & 15) * 8;
            const float4 v0 = *reinterpret_cast<const float4*>(&St[row * 132 + c8]);
            const float4 v1 = *reinterpret_cast<const float4*>(&St[row * 132 + c8 + 4]);
            __half2 pk_[4];
            pk_[0].x = to_h(v0.x); pk_[0].y = to_h(v0.y);
            pk_[1].x = to_h(v0.z); pk_[1].y = to_h(v0.w);
            pk_[2].x = to_h(v1.x); pk_[2].y = to_h(v1.y);
            pk_[3].x = to_h(v1.z); pk_[3].y = to_h(v1.w);
            *reinterpret_cast<uint4*>(Rg + (size_t)row * 2048 + n0 + p * 128 + c8) =
                *reinterpret_cast<uint4*>(pk_);
        }
        __syncthreads();
    }
}

// ---------------------------------------------------------------------------
// Kernel 5: axw — per (bh, h): [32 dv][64 w'] = R[h]^T @ attn_w, smem-tiled.
// Grid (8 h-chunks, 128 bh), 256 threads = 8 warps, warp = one h. 2 CTAs/SM.
// ---------------------------------------------------------------------------
__global__ void __launch_bounds__(256) axw_kernel()
{
    __shared__ hf Aw_s[64 * 72];         // 9.2 KB
    __shared__ hf Rs[8 * 2056];          // 32.1 KB (aliased fp32 staging)
    const int bh = blockIdx.y;
    const int hc = blockIdx.x;           // h chunk (8 h)
    const int tid = threadIdx.x;
    const int wid = tid >> 5;

    {
        const hf* Ag = g_attn[1] + (size_t)bh * 4096;
#pragma unroll
        for (int i = 0; i < 2; i++) {
            const int f = tid + 256 * i;
            const int row = f >> 3, c8 = (f & 7) * 8;
            *reinterpret_cast<uint4*>(&Aw_s[row * 72 + c8]) =
                *reinterpret_cast<const uint4*>(Ag + row * 64 + c8);
        }
        const hf* Rg = g_r + (size_t)bh * 131072 + (size_t)(hc * 8) * 2048;
#pragma unroll
        for (int i = 0; i < 8; i++) {
            const int f = tid + 256 * i;          // 2048 chunks of 8
            const int hl = f >> 8, cc = (f & 255) * 8;
            *reinterpret_cast<uint4*>(&Rs[hl * 2056 + cc]) =
                *reinterpret_cast<const uint4*>(Rg + (size_t)hl * 2048 + cc);
        }
    }
    __syncthreads();

    wmma::fragment<wmma::accumulator, 16, 16, 16, float> acc[2][4];
#pragma unroll
    for (int i = 0; i < 2; i++)
#pragma unroll
        for (int j = 0; j < 4; j++) wmma::fill_fragment(acc[i][j], 0.f);

    const hf* Ar = &Rs[wid * 2056];
#pragma unroll
    for (int kk = 0; kk < 64; kk += 16) {
        wmma::fragment<wmma::matrix_a, 16, 16, 16, half, wmma::col_major> af[2];
        wmma::load_matrix_sync(af[0], Ar + kk * 32, 32);
        wmma::load_matrix_sync(af[1], Ar + kk * 32 + 16, 32);
        wmma::fragment<wmma::matrix_b, 16, 16, 16, half, wmma::row_major> bf_[4];
#pragma unroll
        for (int j = 0; j < 4; j++)
            wmma::load_matrix_sync(bf_[j], &Aw_s[kk * 72 + j * 16], 72);
#pragma unroll
        for (int i = 0; i < 2; i++)
#pragma unroll
            for (int j = 0; j < 4; j++)
                wmma::mma_sync(acc[i][j], af[i], bf_[j], acc[i][j]);
    }
    __syncthreads();    // Rs dead -> staging

    // epilogue: 2 passes of 4 warps; stage col-major [w'][dv] (ld 32)
    float* St = reinterpret_cast<float*>(Rs);     // 4 slices of [64][32] fp32
    hf* outb = g_r2 + (size_t)(bh >> 3) * 1048576 + (bh & 7) * 32;
#pragma unroll
    for (int p = 0; p < 2; p++) {
        if ((wid >> 2) == p) {
            float* sl = St + (wid & 3) * 2048;
#pragma unroll
            for (int i = 0; i < 2; i++)
#pragma unroll
                for (int j = 0; j < 4; j++)
                    wmma::store_matrix_sync(sl + (j * 16) * 32 + i * 16,
                                            acc[i][j], 32, wmma::mem_col_major);
        }
        __syncthreads();
#pragma unroll
        for (int i = 0; i < 4; i++) {
            const int f = tid + 256 * i;          // 1024 chunks of 8
            const int hl = f >> 8;                // 0..3 within pass
            const int rem = f & 255;
            const int wp = rem >> 2, d8 = (rem & 3) * 8;
            const float* src = St + hl * 2048 + wp * 32 + d8;
            const float4 v0 = *reinterpret_cast<const float4*>(src);
            const float4 v1 = *reinterpret_cast<const float4*>(src + 4);
            __half2 pk_[4];
            pk_[0].x = to_h(v0.x); pk_[0].y = to_h(v0.y);
            pk_[1].x = to_h(v0.z); pk_[1].y = to_h(v0.w);
            pk_[2].x = to_h(v1.x); pk_[2].y = to_h(v1.y);
            pk_[3].x = to_h(v1.z); pk_[3].y = to_h(v1.w);
            const int h = hc * 8 + p * 4 + hl;
            *reinterpret_cast<uint4*>(
                outb + (size_t)(h * 64 + wp) * 256 + d8) =
                *reinterpret_cast<uint4*>(pk_);
        }
        __syncthreads();
    }
}

// ---------------------------------------------------------------------------
// Launch
// ---------------------------------------------------------------------------
extern "C" void kernel_launch(void* const* d_in, const int* in_sizes, int n_in,
                              void* d_out, int out_size)
{
    const float* x       = (const float*)d_in[0];
    const float* dw_qh_w = (const float*)d_in[1];
    const float* dw_qh_b = (const float*)d_in[2];
    const float* fc_qh_w = (const float*)d_in[3];
    const float* fc_qh_b = (const float*)d_in[4];
    const float* dw_kh_w = (const float*)d_in[5];
    const float* dw_kh_b = (const float*)d_in[6];
    const float* fc_kh_w = (const float*)d_in[7];
    const float* fc_kh_b = (const float*)d_in[8];
    const float* Bh      = (const float*)d_in[9];
    const float* dw_v_w  = (const float*)d_in[10];
    const float* dw_v_b  = (const float*)d_in[11];
    const float* fc_v_w  = (const float*)d_in[12];
    const float* fc_v_b  = (const float*)d_in[13];
    const float* dw_qw_w = (const float*)d_in[14];
    const float* dw_qw_b = (const float*)d_in[15];
    const float* fc_qw_w = (const float*)d_in[16];
    const float* fc_qw_b = (const float*)d_in[17];
    const float* dw_kw_w = (const float*)d_in[18];
    const float* dw_kw_b = (const float*)d_in[19];
    const float* fc_kw_w = (const float*)d_in[20];
    const float* fc_kw_b = (const float*)d_in[21];
    const float* Bw      = (const float*)d_in[22];
    const float* fc_o_w  = (const float*)d_in[23];
    const float* fc_o_b  = (const float*)d_in[24];
    float* out = (float*)d_out;

    conv_fused_kernel<<<dim3(Cc, Bb + 1), 256>>>(
        x, dw_v_w, dw_v_b,
        dw_qh_w, dw_qh_b, dw_kh_w, dw_kh_b,
        dw_qw_w, dw_qw_b, dw_kw_w, dw_kw_b,
        fc_qh_w, fc_kh_w, fc_qw_w, fc_kw_w, fc_v_w, fc_o_w);

    wmma_gemm_kernel<1><<<dim3(64, 2, Bb + 1), 128>>>(
        fc_qh_b, fc_kh_b, fc_qw_b, fc_kw_b, fc_v_b, nullptr);

    attn_kernel<<<dim3(Bb * Hh, 2), 256>>>(Bh, Bw);

    axh_kernel<<<dim3(8, Bb * Hh), 256>>>();
    axw_kernel<<<dim3(8, Bb * Hh), 256>>>();

    wmma_gemm_kernel<2><<<dim3(64, 2, Bb), 128>>>(
        fc_o_b, fc_o_b, fc_o_b, fc_o_b, fc_o_b, out);
}

// round 16
// speedup vs baseline: 5.6015x; 1.0480x over previous
#include <cuda_runtime.h>
#include <cuda_fp16.h>
#include <mma.h>
#include <cstdint>

using namespace nvcuda;

#define Bb 16
#define Cc 256
#define Ss 64
#define Hh 8
#define Dd 32

typedef __half hf;

// ---------------------------------------------------------------------------
// Scratch (all intermediates fp16, rounded at producers; fp32 accum in MMA)
// ---------------------------------------------------------------------------
__device__ hf g_pool[4][Cc * Bb * Ss];               // [c][b*64+s]  (A^T)
__device__ hf g_qkh[4][Bb * Hh * Ss * Dd];           // [b][head][s][d]
__device__ hf g_attn[2][Bb * Hh * Ss * Ss];
__device__ hf g_vconv[(size_t)Bb * Cc * 4096];       // [b][c][hw] (A^T)
__device__ hf g_v[(size_t)Bb * Hh * 4096 * 32];      // [b][head][hw][dv]
__device__ hf g_r[(size_t)Bb * Hh * Ss * Ss * Dd];   // [b][head][h][w*32+dv]
__device__ hf g_r2[(size_t)Bb * 4096 * Cc];          // [b][m=hw][k]
__device__ hf g_wh[6][Cc * Cc];                      // pre-rounded weights

__device__ __forceinline__ hf to_h(float x) { return __float2half_rn(x); }

__device__ __forceinline__ void cp_async16(void* smem, const void* gmem) {
    uint32_t s = (uint32_t)__cvta_generic_to_shared(smem);
    asm volatile("cp.async.cg.shared.global [%0], [%1], 16;" :: "r"(s), "l"(gmem));
}
#define CP_COMMIT() asm volatile("cp.async.commit_group;" ::: "memory")
#define CP_WAIT(n)  asm volatile("cp.async.wait_group %0;" :: "n"(n) : "memory")

// ---------------------------------------------------------------------------
// Kernel 1: fused V dwconv + analytic pooled q/k branches + weight rounding.
// ---------------------------------------------------------------------------
__global__ void __launch_bounds__(256) conv_fused_kernel(
    const float* __restrict__ x,
    const float* __restrict__ wv,  const float* __restrict__ bv,
    const float* __restrict__ wqh, const float* __restrict__ bqh,
    const float* __restrict__ wkh, const float* __restrict__ bkh,
    const float* __restrict__ wqw, const float* __restrict__ bqw,
    const float* __restrict__ wkw, const float* __restrict__ bkw,
    const float* __restrict__ fqh, const float* __restrict__ fkh,
    const float* __restrict__ fqw, const float* __restrict__ fkw,
    const float* __restrict__ fv,  const float* __restrict__ fo)
{
    const int tid = threadIdx.x;

    if (blockIdx.y == Bb) {
        const int i = blockIdx.x * 256 + tid;
        g_wh[0][i] = to_h(fqh[i]);
        g_wh[1][i] = to_h(fkh[i]);
        g_wh[2][i] = to_h(fqw[i]);
        g_wh[3][i] = to_h(fkw[i]);
        g_wh[4][i] = to_h(fv[i]);
        g_wh[5][i] = to_h(fo[i]);
        return;
    }

    const int c = blockIdx.x;
    const int b = blockIdx.y;

    __shared__ float xs[66][66];
    __shared__ float rowp[2][64], colp[4][64];
    __shared__ float T[64];
    __shared__ float wsm[4][9];
    __shared__ float bsm[4];

    for (int i = tid; i < 66 * 66; i += 256) (&xs[0][0])[i] = 0.f;
    __syncthreads();

    const float4* xp4 = reinterpret_cast<const float4*>(x + ((size_t)b * Cc + c) * 4096);
    for (int i = tid; i < 1024; i += 256) {
        const float4 v = xp4[i];
        const int e = i * 4;
        float* d = &xs[(e >> 6) + 1][(e & 63) + 1];
        d[0] = v.x; d[1] = v.y; d[2] = v.z; d[3] = v.w;
    }

    if (tid < 9)        wsm[0][tid]      = wqh[c * 9 + tid];
    else if (tid < 18)  wsm[1][tid - 9]  = wkh[c * 9 + tid - 9];
    else if (tid < 27)  wsm[2][tid - 18] = wqw[c * 9 + tid - 18];
    else if (tid < 36)  wsm[3][tid - 27] = wkw[c * 9 + tid - 27];
    if (tid == 36) bsm[0] = bqh[c];
    if (tid == 37) bsm[1] = bkh[c];
    if (tid == 38) bsm[2] = bqw[c];
    if (tid == 39) bsm[3] = bkw[c];

    float w[9];
#pragma unroll
    for (int i = 0; i < 9; i++) w[i] = wv[c * 9 + i];
    const float bias = bv[c];
    __syncthreads();

    const int wcol = tid & 63;
    const int hgrp = tid >> 6;
    hf* op = g_vconv + ((size_t)b * Cc + c) * 4096;

    float colacc = 0.f;
    for (int k = 0; k < 16; k++) {
        const int h = hgrp * 16 + k;
        float s = bias;
#pragma unroll
        for (int dy = 0; dy < 3; dy++)
#pragma unroll
            for (int dx = 0; dx < 3; dx++)
                s += w[dy * 3 + dx] * xs[h + dy][wcol + dx];
        op[h * 64 + wcol] = to_h(s);
        const float v = xs[h + 1][wcol + 1];
        colacc += v;
        float rsum = v;
#pragma unroll
        for (int off = 16; off; off >>= 1)
            rsum += __shfl_down_sync(0xffffffffu, rsum, off);
        if ((tid & 31) == 0) rowp[(tid >> 5) & 1][h] = rsum;
    }
    colp[hgrp][wcol] = colacc;
    __syncthreads();
    if (tid < 64) T[tid] = colp[0][tid] + colp[1][tid] + colp[2][tid] + colp[3][tid];
    __syncthreads();

    if (tid < 64) {
        const int s = tid;
        float o0 = 0.f, o1 = 0.f, o2 = 0.f, o3 = 0.f;
#pragma unroll
        for (int d = 0; d < 3; d++) {
            const int r = s + d - 1;
            if (r >= 0 && r < 64) {
                const float Sv = rowp[0][r] + rowp[1][r];
                const float eL = xs[r + 1][1], eR = xs[r + 1][64];
                o0 += (wsm[0][d*3] + wsm[0][d*3+1] + wsm[0][d*3+2]) * Sv
                    - wsm[0][d*3] * eR - wsm[0][d*3+2] * eL;
                o1 += (wsm[1][d*3] + wsm[1][d*3+1] + wsm[1][d*3+2]) * Sv
                    - wsm[1][d*3] * eR - wsm[1][d*3+2] * eL;
                const float Tv = T[r];
                const float eT = xs[1][r + 1], eB = xs[64][r + 1];
                o2 += (wsm[2][d] + wsm[2][3+d] + wsm[2][6+d]) * Tv
                    - wsm[2][d] * eB - wsm[2][6+d] * eT;
                o3 += (wsm[3][d] + wsm[3][3+d] + wsm[3][6+d]) * Tv
                    - wsm[3][d] * eB - wsm[3][6+d] * eT;
            }
        }
        const float inv = 1.f / 64.f;
        const int mi = b * 64 + s;
        g_pool[0][c * 1024 + mi] = to_h(o0 * inv + bsm[0]);
        g_pool[1][c * 1024 + mi] = to_h(o1 * inv + bsm[1]);
        g_pool[2][c * 1024 + mi] = to_h(o2 * inv + bsm[2]);
        g_pool[3][c * 1024 + mi] = to_h(o3 * inv + bsm[3]);
    }
}

// ---------------------------------------------------------------------------
// Kernel 2: attention. Scores via fp16 wmma, low-register softmax.
// ---------------------------------------------------------------------------
__global__ void __launch_bounds__(256) attn_kernel(
    const float* __restrict__ Bh, const float* __restrict__ Bw)
{
    const int bh = blockIdx.x;
    const int head = bh & 7;
    const int axis = blockIdx.y;
    const float scale = 0.17677669529663687f;

    const hf* q = g_qkh[axis == 0 ? 0 : 2] + (size_t)bh * 2048;
    const hf* k = g_qkh[axis == 0 ? 1 : 3] + (size_t)bh * 2048;
    const float* Bm = ((axis == 0) ? Bh : Bw) + head * 4096;
    hf* o = g_attn[axis] + (size_t)bh * 4096;

    __shared__ float sc[64 * 68];

    {
        const int wid = threadIdx.x >> 5;
        const int wm = wid >> 1;
        const int wn = wid & 1;
        wmma::fragment<wmma::accumulator, 16, 16, 16, float> acc[2];
        wmma::fill_fragment(acc[0], 0.f);
        wmma::fill_fragment(acc[1], 0.f);
#pragma unroll
        for (int d0 = 0; d0 < 32; d0 += 16) {
            wmma::fragment<wmma::matrix_a, 16, 16, 16, half, wmma::row_major> af;
            wmma::load_matrix_sync(af, q + (size_t)(wm * 16) * 32 + d0, 32);
            wmma::fragment<wmma::matrix_b, 16, 16, 16, half, wmma::col_major> bf_[2];
            wmma::load_matrix_sync(bf_[0], k + (size_t)(wn * 32) * 32 + d0, 32);
            wmma::load_matrix_sync(bf_[1], k + (size_t)(wn * 32 + 16) * 32 + d0, 32);
            wmma::mma_sync(acc[0], af, bf_[0], acc[0]);
            wmma::mma_sync(acc[1], af, bf_[1], acc[1]);
        }
        wmma::store_matrix_sync(&sc[wm * 16 * 68 + wn * 32], acc[0], 68,
                                wmma::mem_row_major);
        wmma::store_matrix_sync(&sc[wm * 16 * 68 + wn * 32 + 16], acc[1], 68,
                                wmma::mem_row_major);
    }
    __syncthreads();

    {
        const int i = threadIdx.x >> 2;
        const int qq = threadIdx.x & 3;
        float s[16];
        float mx = -1e30f;
#pragma unroll
        for (int jj = 0; jj < 16; jj += 4) {
            const int j = qq * 16 + jj;
            const float4 c4 = *reinterpret_cast<const float4*>(&sc[i * 68 + j]);
            const float4 b4 = *reinterpret_cast<const float4*>(&Bm[i * 64 + j]);
            s[jj + 0] = c4.x * scale + b4.x;
            s[jj + 1] = c4.y * scale + b4.y;
            s[jj + 2] = c4.z * scale + b4.z;
            s[jj + 3] = c4.w * scale + b4.w;
            mx = fmaxf(mx, fmaxf(fmaxf(s[jj], s[jj + 1]), fmaxf(s[jj + 2], s[jj + 3])));
        }
        mx = fmaxf(mx, __shfl_xor_sync(0xffffffffu, mx, 1));
        mx = fmaxf(mx, __shfl_xor_sync(0xffffffffu, mx, 2));
        float sum = 0.f;
#pragma unroll
        for (int jj = 0; jj < 16; jj++) { s[jj] = __expf(s[jj] - mx); sum += s[jj]; }
        sum += __shfl_xor_sync(0xffffffffu, sum, 1);
        sum += __shfl_xor_sync(0xffffffffu, sum, 2);
        const float r = 1.f / sum;
#pragma unroll
        for (int jj = 0; jj < 16; jj += 4) {
            const int j = qq * 16 + jj;
            __half2 lo, hi;
            lo.x = to_h(s[jj + 0] * r); lo.y = to_h(s[jj + 1] * r);
            hi.x = to_h(s[jj + 2] * r); hi.y = to_h(s[jj + 3] * r);
            uint2 pk;
            pk.x = *reinterpret_cast<uint32_t*>(&lo);
            pk.y = *reinterpret_cast<uint32_t*>(&hi);
            *reinterpret_cast<uint2*>(&o[i * 64 + j]) = pk;
        }
    }
}

// ---------------------------------------------------------------------------
// Unified fp16 wmma GEMM, cp.async double buffered, BK=64 (4 iterations).
// No sbias staging: zero-init acc, bias added in the smem epilogue.
// smem 54KB -> 4 CTAs/SM with __launch_bounds__(128, 4).
// ---------------------------------------------------------------------------
#define APB 4608            // A elems per buffer (64 x 72)
#define WPB 9216            // W elems per buffer (128 x 72)

template <int MODE>
__global__ void __launch_bounds__(128, 4) wmma_gemm_kernel(
    const float* __restrict__ b0, const float* __restrict__ b1,
    const float* __restrict__ b2, const float* __restrict__ b3,
    const float* __restrict__ bv, float* __restrict__ outp)
{
    __shared__ __align__(16) unsigned char smem_raw[2 * APB * 2 + 2 * WPB * 2];
    hf* Asm = reinterpret_cast<hf*>(smem_raw);
    hf* Wsm = reinterpret_cast<hf*>(smem_raw + 2 * APB * 2);
    float* Cs = reinterpret_cast<float*>(smem_raw);   // epilogue staging [64][132]

    const int tid = threadIdx.x;
    const int wid = tid >> 5;
    const int wm = wid >> 1;
    const int wn = wid & 1;
    const int nb = blockIdx.y * 128;
    const int z = blockIdx.z;

    const hf* A;
    const hf* W;
    const float* bias;
    int ldA, m0;
    bool isqk = false;
    int qkbr = 0;
    if constexpr (MODE == 1) {
        if (z < 16) {
            A = g_vconv + (size_t)z * 1048576; ldA = 4096;
            W = g_wh[4]; bias = bv; m0 = blockIdx.x * 64;
        } else {
            isqk = true;
            qkbr = blockIdx.x >> 4;
            A = g_pool[qkbr]; ldA = 1024;
            W = g_wh[qkbr];
            bias = (qkbr == 0) ? b0 : (qkbr == 1) ? b1 : (qkbr == 2) ? b2 : b3;
            m0 = (blockIdx.x & 15) * 64;
        }
    } else {
        A = g_r2 + (size_t)z * 1048576; ldA = 256;
        W = g_wh[5]; bias = b0; m0 = blockIdx.x * 64;
    }

    auto load_tiles = [&](int k0, int buf) {
        hf* As = Asm + buf * APB;
        hf* Ws = Wsm + buf * WPB;
#pragma unroll
        for (int i = 0; i < 4; i++) {
            const int f = tid + 128 * i;
            if constexpr (MODE == 1) {
                const int k = f >> 3, mq = f & 7;
                cp_async16(As + k * 72 + mq * 8,
                           A + (size_t)(k0 + k) * ldA + m0 + mq * 8);
            } else {
                const int m = f >> 3, kq = f & 7;
                cp_async16(As + m * 72 + kq * 8,
                           A + (size_t)(m0 + m) * 256 + k0 + kq * 8);
            }
        }
#pragma unroll
        for (int i = 0; i < 8; i++) {
            const int f = tid + 128 * i;
            const int n = f >> 3, kq = f & 7;
            cp_async16(Ws + n * 72 + kq * 8,
                       W + (size_t)(nb + n) * 256 + k0 + kq * 8);
        }
        CP_COMMIT();
    };

    load_tiles(0, 0);

    wmma::fragment<wmma::accumulator, 16, 16, 16, float> acc[2][4];
#pragma unroll
    for (int i = 0; i < 2; i++)
#pragma unroll
        for (int j = 0; j < 4; j++)
            wmma::fill_fragment(acc[i][j], 0.f);

    int buf = 0;
    for (int it = 0; it < 4; it++) {
        if (it < 3) load_tiles((it + 1) * 64, buf ^ 1);
        if (it < 3) { CP_WAIT(1); } else { CP_WAIT(0); }
        __syncthreads();

        hf* As = Asm + buf * APB;
        hf* Ws = Wsm + buf * WPB;
#pragma unroll
        for (int kk = 0; kk < 64; kk += 16) {
            wmma::fragment<wmma::matrix_b, 16, 16, 16, half, wmma::col_major> bf_[4];
#pragma unroll
            for (int j = 0; j < 4; j++)
                wmma::load_matrix_sync(bf_[j], &Ws[(wn * 64 + j * 16) * 72 + kk], 72);
            if constexpr (MODE == 1) {
                wmma::fragment<wmma::matrix_a, 16, 16, 16, half, wmma::col_major> af[2];
                wmma::load_matrix_sync(af[0], &As[kk * 72 + wm * 32], 72);
                wmma::load_matrix_sync(af[1], &As[kk * 72 + wm * 32 + 16], 72);
#pragma unroll
                for (int i = 0; i < 2; i++)
#pragma unroll
                    for (int j = 0; j < 4; j++)
                        wmma::mma_sync(acc[i][j], af[i], bf_[j], acc[i][j]);
            } else {
                wmma::fragment<wmma::matrix_a, 16, 16, 16, half, wmma::row_major> af[2];
                wmma::load_matrix_sync(af[0], &As[(wm * 32) * 72 + kk], 72);
                wmma::load_matrix_sync(af[1], &As[(wm * 32 + 16) * 72 + kk], 72);
#pragma unroll
                for (int i = 0; i < 2; i++)
#pragma unroll
                    for (int j = 0; j < 4; j++)
                        wmma::mma_sync(acc[i][j], af[i], bf_[j], acc[i][j]);
            }
        }
        __syncthreads();
        buf ^= 1;
    }

    // epilogue: stage fp32 C in smem (operand buffers dead), add bias, emit.
#pragma unroll
    for (int i = 0; i < 2; i++)
#pragma unroll
        for (int j = 0; j < 4; j++)
            wmma::store_matrix_sync(&Cs[(wm * 32 + i * 16) * 132 + wn * 64 + j * 16],
                                    acc[i][j], 132, wmma::mem_row_major);
    __syncthreads();
#pragma unroll
    for (int i = 0; i < 16; i++) {
        const int f = tid + 128 * i;        // 2048 chunks of 4
        const int row = f >> 5;
        const int cq = f & 31;
        const float4 v = *reinterpret_cast<const float4*>(&Cs[row * 132 + cq * 4]);
        const int mg = m0 + row;
        const int ng = nb + cq * 4;
        const float4 b4 = *reinterpret_cast<const float4*>(&bias[ng]);
        float4 o4;
        o4.x = v.x + b4.x; o4.y = v.y + b4.y;
        o4.z = v.z + b4.z; o4.w = v.w + b4.w;
        if constexpr (MODE == 2) {
            *reinterpret_cast<float4*>(
                outp + (size_t)z * 1048576 + (size_t)mg * 256 + ng) = o4;
        } else {
            __half2 lo, hi;
            lo.x = to_h(o4.x); lo.y = to_h(o4.y);
            hi.x = to_h(o4.z); hi.y = to_h(o4.w);
            uint2 pk;
            pk.x = *reinterpret_cast<uint32_t*>(&lo);
            pk.y = *reinterpret_cast<uint32_t*>(&hi);
            const int head = ng >> 5;
            hf* dst;
            if (isqk)
                dst = g_qkh[qkbr] + (size_t)(mg >> 6) * 16384 + (size_t)head * 2048
                    + (size_t)(mg & 63) * 32 + (ng & 31);
            else
                dst = g_v + (size_t)z * 1048576 + (size_t)head * 131072
                    + (size_t)mg * 32 + (ng & 31);
            *reinterpret_cast<uint2*>(dst) = pk;
        }
    }
}

// ---------------------------------------------------------------------------
// Kernel 4: axh — R[64][256-chunk] = attn_h @ V per bh, smem-tiled.
// Grid (8 n-chunks, 128 bh), 256 threads = 8 warps (2m x 4n), tile 32x64.
// ---------------------------------------------------------------------------
__global__ void __launch_bounds__(256) axh_kernel()
{
    __shared__ hf Ah_s[64 * 72];         // 9.2 KB
    __shared__ hf Vs[64 * 264];          // 33.8 KB (aliased fp32 staging [64][132])
    const int bh = blockIdx.y;
    const int n0 = blockIdx.x * 256;
    const int tid = threadIdx.x;
    const int wid = tid >> 5;
    const int wm = wid >> 2;             // 0..1
    const int wn = wid & 3;              // 0..3

    {
        const hf* Ag = g_attn[0] + (size_t)bh * 4096;
#pragma unroll
        for (int i = 0; i < 2; i++) {
            const int f = tid + 256 * i;
            const int row = f >> 3, c8 = (f & 7) * 8;
            *reinterpret_cast<uint4*>(&Ah_s[row * 72 + c8]) =
                *reinterpret_cast<const uint4*>(Ag + row * 64 + c8);
        }
        const hf* Vg = g_v + (size_t)bh * 131072 + n0;
#pragma unroll
        for (int i = 0; i < 8; i++) {
            const int f = tid + 256 * i;
            const int r = f >> 5, cc = (f & 31) * 8;
            *reinterpret_cast<uint4*>(&Vs[r * 264 + cc]) =
                *reinterpret_cast<const uint4*>(Vg + (size_t)r * 2048 + cc);
        }
    }
    __syncthreads();

    wmma::fragment<wmma::accumulator, 16, 16, 16, float> acc[2][4];
#pragma unroll
    for (int i = 0; i < 2; i++)
#pragma unroll
        for (int j = 0; j < 4; j++) wmma::fill_fragment(acc[i][j], 0.f);

#pragma unroll
    for (int kk = 0; kk < 64; kk += 16) {
        wmma::fragment<wmma::matrix_a, 16, 16, 16, half, wmma::row_major> af[2];
        wmma::load_matrix_sync(af[0], &Ah_s[(wm * 32) * 72 + kk], 72);
        wmma::load_matrix_sync(af[1], &Ah_s[(wm * 32 + 16) * 72 + kk], 72);
        wmma::fragment<wmma::matrix_b, 16, 16, 16, half, wmma::row_major> bf_[4];
#pragma unroll
        for (int j = 0; j < 4; j++)
            wmma::load_matrix_sync(bf_[j], &Vs[kk * 264 + wn * 64 + j * 16], 264);
#pragma unroll
        for (int i = 0; i < 2; i++)
#pragma unroll
            for (int j = 0; j < 4; j++)
                wmma::mma_sync(acc[i][j], af[i], bf_[j], acc[i][j]);
    }
    __syncthreads();    // Vs dead -> staging

    float* St = reinterpret_cast<float*>(Vs);
    hf* Rg = g_r + (size_t)bh * 131072;
#pragma unroll
    for (int p = 0; p < 2; p++) {
        if ((wn >> 1) == p) {
#pragma unroll
            for (int i = 0; i < 2; i++)
#pragma unroll
                for (int j = 0; j < 4; j++)
                    wmma::store_matrix_sync(
                        &St[(wm * 32 + i * 16) * 132 + (wn & 1) * 64 + j * 16],
                        acc[i][j], 132, wmma::mem_row_major);
        }
        __syncthreads();
#pragma unroll
        for (int i = 0; i < 4; i++) {
            const int f = tid + 256 * i;
            const int row = f >> 4, c8 = (f & 15) * 8;
            const float4 v0 = *reinterpret_cast<const float4*>(&St[row * 132 + c8]);
            const float4 v1 = *reinterpret_cast<const float4*>(&St[row * 132 + c8 + 4]);
            __half2 pk_[4];
            pk_[0].x = to_h(v0.x); pk_[0].y = to_h(v0.y);
            pk_[1].x = to_h(v0.z); pk_[1].y = to_h(v0.w);
            pk_[2].x = to_h(v1.x); pk_[2].y = to_h(v1.y);
            pk_[3].x = to_h(v1.z); pk_[3].y = to_h(v1.w);
            *reinterpret_cast<uint4*>(Rg + (size_t)row * 2048 + n0 + p * 128 + c8) =
                *reinterpret_cast<uint4*>(pk_);
        }
        __syncthreads();
    }
}

// ---------------------------------------------------------------------------
// Kernel 5: axw — per (bh, h): [32 dv][64 w'] = R[h]^T @ attn_w, smem-tiled.
// Grid (8 h-chunks, 128 bh), 256 threads = 8 warps, warp = one h.
// ---------------------------------------------------------------------------
__global__ void __launch_bounds__(256) axw_kernel()
{
    __shared__ hf Aw_s[64 * 72];         // 9.2 KB
    __shared__ hf Rs[8 * 2056];          // 32.1 KB (aliased fp32 staging)
    const int bh = blockIdx.y;
    const int hc = blockIdx.x;           // h chunk (8 h)
    const int tid = threadIdx.x;
    const int wid = tid >> 5;

    {
        const hf* Ag = g_attn[1] + (size_t)bh * 4096;
#pragma unroll
        for (int i = 0; i < 2; i++) {
            const int f = tid + 256 * i;
            const int row = f >> 3, c8 = (f & 7) * 8;
            *reinterpret_cast<uint4*>(&Aw_s[row * 72 + c8]) =
                *reinterpret_cast<const uint4*>(Ag + row * 64 + c8);
        }
        const hf* Rg = g_r + (size_t)bh * 131072 + (size_t)(hc * 8) * 2048;
#pragma unroll
        for (int i = 0; i < 8; i++) {
            const int f = tid + 256 * i;
            const int hl = f >> 8, cc = (f & 255) * 8;
            *reinterpret_cast<uint4*>(&Rs[hl * 2056 + cc]) =
                *reinterpret_cast<const uint4*>(Rg + (size_t)hl * 2048 + cc);
        }
    }
    __syncthreads();

    wmma::fragment<wmma::accumulator, 16, 16, 16, float> acc[2][4];
#pragma unroll
    for (int i = 0; i < 2; i++)
#pragma unroll
        for (int j = 0; j < 4; j++) wmma::fill_fragment(acc[i][j], 0.f);

    const hf* Ar = &Rs[wid * 2056];
#pragma unroll
    for (int kk = 0; kk < 64; kk += 16) {
        wmma::fragment<wmma::matrix_a, 16, 16, 16, half, wmma::col_major> af[2];
        wmma::load_matrix_sync(af[0], Ar + kk * 32, 32);
        wmma::load_matrix_sync(af[1], Ar + kk * 32 + 16, 32);
        wmma::fragment<wmma::matrix_b, 16, 16, 16, half, wmma::row_major> bf_[4];
#pragma unroll
        for (int j = 0; j < 4; j++)
            wmma::load_matrix_sync(bf_[j], &Aw_s[kk * 72 + j * 16], 72);
#pragma unroll
        for (int i = 0; i < 2; i++)
#pragma unroll
            for (int j = 0; j < 4; j++)
                wmma::mma_sync(acc[i][j], af[i], bf_[j], acc[i][j]);
    }
    __syncthreads();    // Rs dead -> staging

    float* St = reinterpret_cast<float*>(Rs);     // 4 slices of [64][32] fp32
    hf* outb = g_r2 + (size_t)(bh >> 3) * 1048576 + (bh & 7) * 32;
#pragma unroll
    for (int p = 0; p < 2; p++) {
        if ((wid >> 2) == p) {
            float* sl = St + (wid & 3) * 2048;
#pragma unroll
            for (int i = 0; i < 2; i++)
#pragma unroll
                for (int j = 0; j < 4; j++)
                    wmma::store_matrix_sync(sl + (j * 16) * 32 + i * 16,
                                            acc[i][j], 32, wmma::mem_col_major);
        }
        __syncthreads();
#pragma unroll
        for (int i = 0; i < 4; i++) {
            const int f = tid + 256 * i;
            const int hl = f >> 8;                // 0..3 within pass
            const int rem = f & 255;
            const int wp = rem >> 2, d8 = (rem & 3) * 8;
            const float* src = St + hl * 2048 + wp * 32 + d8;
            const float4 v0 = *reinterpret_cast<const float4*>(src);
            const float4 v1 = *reinterpret_cast<const float4*>(src + 4);
            __half2 pk_[4];
            pk_[0].x = to_h(v0.x); pk_[0].y = to_h(v0.y);
            pk_[1].x = to_h(v0.z); pk_[1].y = to_h(v0.w);
            pk_[2].x = to_h(v1.x); pk_[2].y = to_h(v1.y);
            pk_[3].x = to_h(v1.z); pk_[3].y = to_h(v1.w);
            const int h = hc * 8 + p * 4 + hl;
            *reinterpret_cast<uint4*>(
                outb + (size_t)(h * 64 + wp) * 256 + d8) =
                *reinterpret_cast<uint4*>(pk_);
        }
        __syncthreads();
    }
}

// ---------------------------------------------------------------------------
// Launch
// ---------------------------------------------------------------------------
extern "C" void kernel_launch(void* const* d_in, const int* in_sizes, int n_in,
                              void* d_out, int out_size)
{
    const float* x       = (const float*)d_in[0];
    const float* dw_qh_w = (const float*)d_in[1];
    const float* dw_qh_b = (const float*)d_in[2];
    const float* fc_qh_w = (const float*)d_in[3];
    const float* fc_qh_b = (const float*)d_in[4];
    const float* dw_kh_w = (const float*)d_in[5];
    const float* dw_kh_b = (const float*)d_in[6];
    const float* fc_kh_w = (const float*)d_in[7];
    const float* fc_kh_b = (const float*)d_in[8];
    const float* Bh      = (const float*)d_in[9];
    const float* dw_v_w  = (const float*)d_in[10];
    const float* dw_v_b  = (const float*)d_in[11];
    const float* fc_v_w  = (const float*)d_in[12];
    const float* fc_v_b  = (const float*)d_in[13];
    const float* dw_qw_w = (const float*)d_in[14];
    const float* dw_qw_b = (const float*)d_in[15];
    const float* fc_qw_w = (const float*)d_in[16];
    const float* fc_qw_b = (const float*)d_in[17];
    const float* dw_kw_w = (const float*)d_in[18];
    const float* dw_kw_b = (const float*)d_in[19];
    const float* fc_kw_w = (const float*)d_in[20];
    const float* fc_kw_b = (const float*)d_in[21];
    const float* Bw      = (const float*)d_in[22];
    const float* fc_o_w  = (const float*)d_in[23];
    const float* fc_o_b  = (const float*)d_in[24];
    float* out = (float*)d_out;

    conv_fused_kernel<<<dim3(Cc, Bb + 1), 256>>>(
        x, dw_v_w, dw_v_b,
        dw_qh_w, dw_qh_b, dw_kh_w, dw_kh_b,
        dw_qw_w, dw_qw_b, dw_kw_w, dw_kw_b,
        fc_qh_w, fc_kh_w, fc_qw_w, fc_kw_w, fc_v_w, fc_o_w);

    wmma_gemm_kernel<1><<<dim3(64, 2, Bb + 1), 128>>>(
        fc_qh_b, fc_kh_b, fc_qw_b, fc_kw_b, fc_v_b, nullptr);

    attn_kernel<<<dim3(Bb * Hh, 2), 256>>>(Bh, Bw);

    axh_kernel<<<dim3(8, Bb * Hh), 256>>>();
    axw_kernel<<<dim3(8, Bb * Hh), 256>>>();

    wmma_gemm_kernel<2><<<dim3(64, 2, Bb), 128>>>(
        fc_o_b, fc_o_b, fc_o_b, fc_o_b, fc_o_b, out);
}